// round 1
// baseline (speedup 1.0000x reference)
#include <cuda_runtime.h>
#include <math.h>

#define B_ 8
#define N_ 2048
#define H_ 1024
#define E_ 64

// Scratch for projected keys/values (no allocation allowed in kernel_launch).
__device__ float g_keys[B_ * N_ * E_];
__device__ float g_vals[B_ * N_ * E_];

// ---------------------------------------------------------------------------
// Projection: C[16384,128] = input[16384,1024] @ [k | v]   (q is dead code)
// BM=128, BN=128, BK=16, 256 threads, 8x8 per-thread micro-tile.
// ---------------------------------------------------------------------------
__global__ __launch_bounds__(256) void proj_kernel(
    const float* __restrict__ A,
    const float* __restrict__ Wk,
    const float* __restrict__ Wv)
{
    __shared__ float Ash[16][128];   // [k][m]  (A transposed into smem)
    __shared__ float Wsh[16][128];   // [k][n]

    const int tid = threadIdx.x;
    const int ty = tid >> 4;         // 0..15 -> output rows ty*8..ty*8+7
    const int tx = tid & 15;         // 0..15 -> output cols tx*8..tx*8+7
    const int M0 = blockIdx.x * 128;

    float acc[8][8];
#pragma unroll
    for (int i = 0; i < 8; ++i)
#pragma unroll
        for (int j = 0; j < 8; ++j) acc[i][j] = 0.f;

    for (int kt = 0; kt < H_ / 16; ++kt) {
        // Load A tile 128x16 (512 float4, 2 per thread), store transposed.
#pragma unroll
        for (int l = 0; l < 2; ++l) {
            int idx = tid + l * 256;           // 0..511
            int row = idx >> 2;                // 0..127
            int kq  = (idx & 3) << 2;          // 0,4,8,12
            float4 a = *reinterpret_cast<const float4*>(
                A + (size_t)(M0 + row) * H_ + kt * 16 + kq);
            Ash[kq + 0][row] = a.x;
            Ash[kq + 1][row] = a.y;
            Ash[kq + 2][row] = a.z;
            Ash[kq + 3][row] = a.w;
        }
        // Load W tile 16x128: cols 0..63 from k, 64..127 from v.
#pragma unroll
        for (int l = 0; l < 2; ++l) {
            int idx = tid + l * 256;           // 0..511
            int kk = idx >> 5;                 // 0..15
            int c4 = (idx & 31) << 2;          // 0..124
            const float* src = (c4 < 64)
                ? (Wk + (size_t)(kt * 16 + kk) * E_ + c4)
                : (Wv + (size_t)(kt * 16 + kk) * E_ + (c4 - 64));
            *reinterpret_cast<float4*>(&Wsh[kk][c4]) =
                *reinterpret_cast<const float4*>(src);
        }
        __syncthreads();

#pragma unroll
        for (int kk = 0; kk < 16; ++kk) {
            float a[8], w[8];
            *reinterpret_cast<float4*>(&a[0]) = *reinterpret_cast<float4*>(&Ash[kk][ty * 8]);
            *reinterpret_cast<float4*>(&a[4]) = *reinterpret_cast<float4*>(&Ash[kk][ty * 8 + 4]);
            *reinterpret_cast<float4*>(&w[0]) = *reinterpret_cast<float4*>(&Wsh[kk][tx * 8]);
            *reinterpret_cast<float4*>(&w[4]) = *reinterpret_cast<float4*>(&Wsh[kk][tx * 8 + 4]);
#pragma unroll
            for (int i = 0; i < 8; ++i)
#pragma unroll
                for (int j = 0; j < 8; ++j)
                    acc[i][j] = fmaf(a[i], w[j], acc[i][j]);
        }
        __syncthreads();
    }

    // Write: cols < 64 -> keys, cols >= 64 -> values. Each thread's 8 cols
    // are entirely within one matrix (8 | 64).
#pragma unroll
    for (int rr = 0; rr < 8; ++rr) {
        int m = M0 + ty * 8 + rr;
        float* dst = (tx < 8) ? (g_keys + (size_t)m * E_ + tx * 8)
                              : (g_vals + (size_t)m * E_ + (tx - 8) * 8);
        float4 o0 = make_float4(acc[rr][0], acc[rr][1], acc[rr][2], acc[rr][3]);
        float4 o1 = make_float4(acc[rr][4], acc[rr][5], acc[rr][6], acc[rr][7]);
        *reinterpret_cast<float4*>(dst)     = o0;
        *reinterpret_cast<float4*>(dst + 4) = o1;
    }
}

// ---------------------------------------------------------------------------
// Attention: S[i,j] = keys_i . values_j / 8, keep j >= i, softmax over j,
// O = P @ values. Flash-style over 64x64 tiles, starting at the diagonal.
// One block = (batch b, 64-row tile t). 256 threads, 4x4 micro-tiles.
// ---------------------------------------------------------------------------
__global__ __launch_bounds__(256) void attn_kernel(float* __restrict__ out)
{
    __shared__ float Ksh[64][64];   // keys tile, [e][r]
    __shared__ float Ue[64][64];    // values tile [e][c] for S-gemm; reused as P[r][c]
    __shared__ float Vc[64][64];    // values tile [c][e] for O-gemm

    const int tid = threadIdx.x;
    const int ty = tid >> 4;        // 0..15 -> rows ty*4..ty*4+3
    const int tx = tid & 15;        // 0..15 -> cols tx*4..tx*4+3
    const int t = blockIdx.x >> 3;  // row-tile 0..31 (t=0 longest, launched first)
    const int b = blockIdx.x & 7;

    const float* keys = g_keys + (size_t)b * N_ * E_;
    const float* vals = g_vals + (size_t)b * N_ * E_;

    // Load K tile (rows t*64..t*64+63), store e-major.
#pragma unroll
    for (int l = 0; l < 4; ++l) {
        int idx = tid + l * 256;     // float4 index 0..1023
        int row = idx >> 4;          // 0..63
        int e4  = (idx & 15) << 2;   // 0..60
        float4 kk = *reinterpret_cast<const float4*>(
            keys + (size_t)(t * 64 + row) * E_ + e4);
        Ksh[e4 + 0][row] = kk.x;
        Ksh[e4 + 1][row] = kk.y;
        Ksh[e4 + 2][row] = kk.z;
        Ksh[e4 + 3][row] = kk.w;
    }

    float m_i[4], l_i[4], accO[4][4];
#pragma unroll
    for (int r = 0; r < 4; ++r) {
        m_i[r] = -INFINITY;
        l_i[r] = 0.f;
#pragma unroll
        for (int c = 0; c < 4; ++c) accO[r][c] = 0.f;
    }

    for (int jt = t; jt < N_ / 64; ++jt) {
        __syncthreads();  // previous O-gemm done (also orders the K-tile stores)

        // Load V tile in both layouts.
#pragma unroll
        for (int l = 0; l < 4; ++l) {
            int idx = tid + l * 256;
            int row = idx >> 4;
            int e4  = (idx & 15) << 2;
            float4 v = *reinterpret_cast<const float4*>(
                vals + (size_t)(jt * 64 + row) * E_ + e4);
            Ue[e4 + 0][row] = v.x;
            Ue[e4 + 1][row] = v.y;
            Ue[e4 + 2][row] = v.z;
            Ue[e4 + 3][row] = v.w;
            *reinterpret_cast<float4*>(&Vc[row][e4]) = v;
        }
        __syncthreads();

        // S-gemm: S[r][c] = sum_e K[r][e] * V[c][e]
        float S[4][4];
#pragma unroll
        for (int r = 0; r < 4; ++r)
#pragma unroll
            for (int c = 0; c < 4; ++c) S[r][c] = 0.f;

#pragma unroll 8
        for (int e = 0; e < 64; ++e) {
            float4 kv = *reinterpret_cast<float4*>(&Ksh[e][ty * 4]);
            float4 vv = *reinterpret_cast<float4*>(&Ue[e][tx * 4]);
            float ka[4] = {kv.x, kv.y, kv.z, kv.w};
            float va[4] = {vv.x, vv.y, vv.z, vv.w};
#pragma unroll
            for (int r = 0; r < 4; ++r)
#pragma unroll
                for (int c = 0; c < 4; ++c)
                    S[r][c] = fmaf(ka[r], va[c], S[r][c]);
        }
        __syncthreads();  // done reading Ue (about to overwrite with P)

        // Scale + mask (mask only on diagonal tile: keep j >= i).
        const float sc = 0.125f;  // 1/sqrt(64)
        if (jt == t) {
#pragma unroll
            for (int r = 0; r < 4; ++r)
#pragma unroll
                for (int c = 0; c < 4; ++c) {
                    int li = ty * 4 + r;
                    int lj = tx * 4 + c;
                    S[r][c] = (lj >= li) ? S[r][c] * sc : -1e30f;
                }
        } else {
#pragma unroll
            for (int r = 0; r < 4; ++r)
#pragma unroll
                for (int c = 0; c < 4; ++c) S[r][c] *= sc;
        }

        // Online softmax update (row reductions across the 16 tx lanes).
#pragma unroll
        for (int r = 0; r < 4; ++r) {
            float tmax = fmaxf(fmaxf(S[r][0], S[r][1]), fmaxf(S[r][2], S[r][3]));
#pragma unroll
            for (int msk = 1; msk < 16; msk <<= 1)
                tmax = fmaxf(tmax, __shfl_xor_sync(0xffffffffu, tmax, msk));
            float mnew = fmaxf(m_i[r], tmax);
            float alpha = __expf(m_i[r] - mnew);
            float ps = 0.f;
#pragma unroll
            for (int c = 0; c < 4; ++c) {
                float p = __expf(S[r][c] - mnew);
                S[r][c] = p;
                ps += p;
            }
#pragma unroll
            for (int msk = 1; msk < 16; msk <<= 1)
                ps += __shfl_xor_sync(0xffffffffu, ps, msk);
            l_i[r] = l_i[r] * alpha + ps;
            m_i[r] = mnew;
#pragma unroll
            for (int c = 0; c < 4; ++c) accO[r][c] *= alpha;
        }

        // Store P (row-major) into Ue.
#pragma unroll
        for (int r = 0; r < 4; ++r)
            *reinterpret_cast<float4*>(&Ue[ty * 4 + r][tx * 4]) =
                make_float4(S[r][0], S[r][1], S[r][2], S[r][3]);
        __syncthreads();  // P visible

        // O-gemm: accO[r][e] += sum_c P[r][c] * V[c][e]
#pragma unroll 4
        for (int c0 = 0; c0 < 64; c0 += 4) {
            float4 p[4], v[4];
#pragma unroll
            for (int r = 0; r < 4; ++r)
                p[r] = *reinterpret_cast<float4*>(&Ue[ty * 4 + r][c0]);
#pragma unroll
            for (int i = 0; i < 4; ++i)
                v[i] = *reinterpret_cast<float4*>(&Vc[c0 + i][tx * 4]);
#pragma unroll
            for (int r = 0; r < 4; ++r) {
#pragma unroll
                for (int i = 0; i < 4; ++i) {
                    float pv = (i == 0) ? p[r].x : (i == 1) ? p[r].y : (i == 2) ? p[r].z : p[r].w;
                    accO[r][0] = fmaf(pv, v[i].x, accO[r][0]);
                    accO[r][1] = fmaf(pv, v[i].y, accO[r][1]);
                    accO[r][2] = fmaf(pv, v[i].z, accO[r][2]);
                    accO[r][3] = fmaf(pv, v[i].w, accO[r][3]);
                }
            }
        }
    }

    // Final normalize + write.
    const int rowbase = b * N_ + t * 64 + ty * 4;
#pragma unroll
    for (int r = 0; r < 4; ++r) {
        float inv = 1.f / l_i[r];
        float4 o = make_float4(accO[r][0] * inv, accO[r][1] * inv,
                               accO[r][2] * inv, accO[r][3] * inv);
        *reinterpret_cast<float4*>(out + (size_t)(rowbase + r) * E_ + tx * 4) = o;
    }
}

// ---------------------------------------------------------------------------
extern "C" void kernel_launch(void* const* d_in, const int* in_sizes, int n_in,
                              void* d_out, int out_size)
{
    (void)in_sizes; (void)n_in; (void)out_size;
    const float* input = (const float*)d_in[0];
    const float* Wk    = (const float*)d_in[1];
    // d_in[2] is q — dead in the reference, intentionally unused.
    const float* Wv    = (const float*)d_in[3];
    float* out = (float*)d_out;

    proj_kernel<<<128, 256>>>(input, Wk, Wv);   // 16384x128x1024 GEMM
    attn_kernel<<<256, 256>>>(out);             // 8 batches x 32 row-tiles
}

// round 2
// speedup vs baseline: 1.1530x; 1.1530x over previous
#include <cuda_runtime.h>
#include <math.h>

#define B_ 8
#define N_ 2048
#define H_ 1024
#define E_ 64
#define NT 32            // number of 64-row tiles per batch
#define CHUNK 4          // j-tiles (64 cols each) per partial block
#define MAXC 8           // max chunks per row-tile = ceil(32/4)
#define BLK_PER_B 144    // sum_t ceil((32-t)/4)

// Scratch (no allocation allowed in kernel_launch).
__device__ float g_keys[B_ * N_ * E_];
__device__ float g_vals[B_ * N_ * E_];
__device__ float g_pO[B_ * NT * MAXC * 64 * 64];   // unnormalized partial O
__device__ float g_pm[B_ * NT * MAXC * 64];        // partial row max
__device__ float g_pl[B_ * NT * MAXC * 64];        // partial row sum

// ---------------------------------------------------------------------------
// Projection: C[16384,128] = input[16384,1024] @ [k | v]   (q is dead code)
// BM=128, BN=128, BK=16, 256 threads, 8x8 per-thread micro-tile.
// (~80% of fp32 FMA roofline — unchanged this round.)
// ---------------------------------------------------------------------------
__global__ __launch_bounds__(256) void proj_kernel(
    const float* __restrict__ A,
    const float* __restrict__ Wk,
    const float* __restrict__ Wv)
{
    __shared__ float Ash[16][128];
    __shared__ float Wsh[16][128];

    const int tid = threadIdx.x;
    const int ty = tid >> 4;
    const int tx = tid & 15;
    const int M0 = blockIdx.x * 128;

    float acc[8][8];
#pragma unroll
    for (int i = 0; i < 8; ++i)
#pragma unroll
        for (int j = 0; j < 8; ++j) acc[i][j] = 0.f;

    for (int kt = 0; kt < H_ / 16; ++kt) {
#pragma unroll
        for (int l = 0; l < 2; ++l) {
            int idx = tid + l * 256;
            int row = idx >> 2;
            int kq  = (idx & 3) << 2;
            float4 a = *reinterpret_cast<const float4*>(
                A + (size_t)(M0 + row) * H_ + kt * 16 + kq);
            Ash[kq + 0][row] = a.x;
            Ash[kq + 1][row] = a.y;
            Ash[kq + 2][row] = a.z;
            Ash[kq + 3][row] = a.w;
        }
#pragma unroll
        for (int l = 0; l < 2; ++l) {
            int idx = tid + l * 256;
            int kk = idx >> 5;
            int c4 = (idx & 31) << 2;
            const float* src = (c4 < 64)
                ? (Wk + (size_t)(kt * 16 + kk) * E_ + c4)
                : (Wv + (size_t)(kt * 16 + kk) * E_ + (c4 - 64));
            *reinterpret_cast<float4*>(&Wsh[kk][c4]) =
                *reinterpret_cast<const float4*>(src);
        }
        __syncthreads();

#pragma unroll
        for (int kk = 0; kk < 16; ++kk) {
            float a[8], w[8];
            *reinterpret_cast<float4*>(&a[0]) = *reinterpret_cast<float4*>(&Ash[kk][ty * 8]);
            *reinterpret_cast<float4*>(&a[4]) = *reinterpret_cast<float4*>(&Ash[kk][ty * 8 + 4]);
            *reinterpret_cast<float4*>(&w[0]) = *reinterpret_cast<float4*>(&Wsh[kk][tx * 8]);
            *reinterpret_cast<float4*>(&w[4]) = *reinterpret_cast<float4*>(&Wsh[kk][tx * 8 + 4]);
#pragma unroll
            for (int i = 0; i < 8; ++i)
#pragma unroll
                for (int j = 0; j < 8; ++j)
                    acc[i][j] = fmaf(a[i], w[j], acc[i][j]);
        }
        __syncthreads();
    }

#pragma unroll
    for (int rr = 0; rr < 8; ++rr) {
        int m = M0 + ty * 8 + rr;
        float* dst = (tx < 8) ? (g_keys + (size_t)m * E_ + tx * 8)
                              : (g_vals + (size_t)m * E_ + (tx - 8) * 8);
        *reinterpret_cast<float4*>(dst) =
            make_float4(acc[rr][0], acc[rr][1], acc[rr][2], acc[rr][3]);
        *reinterpret_cast<float4*>(dst + 4) =
            make_float4(acc[rr][4], acc[rr][5], acc[rr][6], acc[rr][7]);
    }
}

// ---------------------------------------------------------------------------
// Attention partial pass: one block = (batch, 64-row tile, chunk of <=4
// 64-col j-tiles). 128 threads, 4x8 micro-tiles. Writes unnormalized
// (O, m, l) partials to scratch.
// Dynamic smem layout (floats):
//   Ksh[64][64]  e-major keys:  Ksh[e*64 + r]
//   Ue [64][68]  V e-major (Ue[e*68+c]) during S-gemm, then P (Ue[r*68+c])
//   Vc [64][68]  V c-major: Vc[c*68+e]
// ---------------------------------------------------------------------------
#define SM_KSH 0
#define SM_UE  (64 * 64)
#define SM_VC  (SM_UE + 64 * 68)
#define SM_FLOATS (SM_VC + 64 * 68)
#define ATTN_SMEM_BYTES (SM_FLOATS * 4)

__global__ __launch_bounds__(128) void attn_partial()
{
    extern __shared__ float sm[];
    float* Ksh = sm + SM_KSH;
    float* Ue  = sm + SM_UE;
    float* Vc  = sm + SM_VC;

    const int tid = threadIdx.x;
    const int ty = tid >> 3;   // 0..15 -> rows ty*4..+3
    const int tx = tid & 7;    // 0..7  -> cols tx*8..+7

    // block -> (b, t, chunk)
    const int b = blockIdx.x / BLK_PER_B;
    int ent = blockIdx.x - b * BLK_PER_B;
    int t = 0, acc = 0;
    for (int tt = 0; tt < NT; ++tt) {
        int nc = (NT - tt + CHUNK - 1) / CHUNK;
        if (ent < acc + nc) { t = tt; break; }
        acc += nc;
    }
    const int chunk = ent - acc;
    const int j0 = t + chunk * CHUNK;
    const int j1 = min(NT, j0 + CHUNK);

    const float* keys = g_keys + ((size_t)b * N_ + t * 64) * E_;
    const float* vals = g_vals + (size_t)b * N_ * E_;

    // Load K tile (64 rows x 64 e), store e-major.
#pragma unroll
    for (int l = 0; l < 8; ++l) {
        int idx = tid + l * 128;         // float4 index 0..1023
        int row = idx >> 4;
        int e4  = (idx & 15) << 2;
        float4 kk = *reinterpret_cast<const float4*>(keys + (size_t)row * E_ + e4);
        Ksh[(e4 + 0) * 64 + row] = kk.x;
        Ksh[(e4 + 1) * 64 + row] = kk.y;
        Ksh[(e4 + 2) * 64 + row] = kk.z;
        Ksh[(e4 + 3) * 64 + row] = kk.w;
    }

    float m_i[4], l_i[4], accO[4][8];
#pragma unroll
    for (int r = 0; r < 4; ++r) {
        m_i[r] = -INFINITY;
        l_i[r] = 0.f;
#pragma unroll
        for (int c = 0; c < 8; ++c) accO[r][c] = 0.f;
    }

    for (int jt = j0; jt < j1; ++jt) {
        __syncthreads();   // K stores (1st iter) / previous O-gemm reads done

        // Load V tile in both layouts.
#pragma unroll
        for (int l = 0; l < 8; ++l) {
            int idx = tid + l * 128;
            int row = idx >> 4;
            int e4  = (idx & 15) << 2;
            float4 v = *reinterpret_cast<const float4*>(
                vals + (size_t)(jt * 64 + row) * E_ + e4);
            Ue[(e4 + 0) * 68 + row] = v.x;
            Ue[(e4 + 1) * 68 + row] = v.y;
            Ue[(e4 + 2) * 68 + row] = v.z;
            Ue[(e4 + 3) * 68 + row] = v.w;
            *reinterpret_cast<float4*>(&Vc[row * 68 + e4]) = v;
        }
        __syncthreads();

        // S-gemm: S[r][c] = sum_e K[r][e] * V[c][e]
        float S[4][8];
#pragma unroll
        for (int r = 0; r < 4; ++r)
#pragma unroll
            for (int c = 0; c < 8; ++c) S[r][c] = 0.f;

#pragma unroll 4
        for (int e = 0; e < 64; ++e) {
            float4 kf = *reinterpret_cast<float4*>(&Ksh[e * 64 + ty * 4]);
            float4 v0 = *reinterpret_cast<float4*>(&Ue[e * 68 + tx * 8]);
            float4 v1 = *reinterpret_cast<float4*>(&Ue[e * 68 + tx * 8 + 4]);
            float ka[4] = {kf.x, kf.y, kf.z, kf.w};
            float va[8] = {v0.x, v0.y, v0.z, v0.w, v1.x, v1.y, v1.z, v1.w};
#pragma unroll
            for (int r = 0; r < 4; ++r)
#pragma unroll
                for (int c = 0; c < 8; ++c)
                    S[r][c] = fmaf(ka[r], va[c], S[r][c]);
        }
        __syncthreads();   // done reading Ue as V; about to overwrite with P

        // Scale + mask (diagonal tile only: keep j >= i).
        const float sc = 0.125f;   // 1/sqrt(64)
        if (jt == t) {
#pragma unroll
            for (int r = 0; r < 4; ++r)
#pragma unroll
                for (int c = 0; c < 8; ++c)
                    S[r][c] = (tx * 8 + c >= ty * 4 + r) ? S[r][c] * sc : -1e30f;
        } else {
#pragma unroll
            for (int r = 0; r < 4; ++r)
#pragma unroll
                for (int c = 0; c < 8; ++c) S[r][c] *= sc;
        }

        // Online softmax (row reductions across 8 tx lanes).
#pragma unroll
        for (int r = 0; r < 4; ++r) {
            float tmax = S[r][0];
#pragma unroll
            for (int c = 1; c < 8; ++c) tmax = fmaxf(tmax, S[r][c]);
#pragma unroll
            for (int msk = 1; msk < 8; msk <<= 1)
                tmax = fmaxf(tmax, __shfl_xor_sync(0xffffffffu, tmax, msk));
            float mnew = fmaxf(m_i[r], tmax);
            float alpha = __expf(m_i[r] - mnew);
            float ps = 0.f;
#pragma unroll
            for (int c = 0; c < 8; ++c) {
                float p = __expf(S[r][c] - mnew);
                S[r][c] = p;
                ps += p;
            }
#pragma unroll
            for (int msk = 1; msk < 8; msk <<= 1)
                ps += __shfl_xor_sync(0xffffffffu, ps, msk);
            l_i[r] = l_i[r] * alpha + ps;
            m_i[r] = mnew;
#pragma unroll
            for (int c = 0; c < 8; ++c) accO[r][c] *= alpha;
        }

        // Store P (row-major, padded stride 68).
#pragma unroll
        for (int r = 0; r < 4; ++r) {
            *reinterpret_cast<float4*>(&Ue[(ty * 4 + r) * 68 + tx * 8]) =
                make_float4(S[r][0], S[r][1], S[r][2], S[r][3]);
            *reinterpret_cast<float4*>(&Ue[(ty * 4 + r) * 68 + tx * 8 + 4]) =
                make_float4(S[r][4], S[r][5], S[r][6], S[r][7]);
        }
        __syncthreads();   // P visible

        // O-gemm: accO[r][e] += sum_c P[r][c] * V[c][e], e-cols tx*8..+7
#pragma unroll 4
        for (int c0 = 0; c0 < 64; c0 += 4) {
            float4 p[4];
#pragma unroll
            for (int r = 0; r < 4; ++r)
                p[r] = *reinterpret_cast<float4*>(&Ue[(ty * 4 + r) * 68 + c0]);
            float4 va[4], vb[4];
#pragma unroll
            for (int i = 0; i < 4; ++i) {
                va[i] = *reinterpret_cast<float4*>(&Vc[(c0 + i) * 68 + tx * 8]);
                vb[i] = *reinterpret_cast<float4*>(&Vc[(c0 + i) * 68 + tx * 8 + 4]);
            }
#pragma unroll
            for (int r = 0; r < 4; ++r) {
#pragma unroll
                for (int i = 0; i < 4; ++i) {
                    float pv = (i == 0) ? p[r].x : (i == 1) ? p[r].y
                             : (i == 2) ? p[r].z : p[r].w;
                    accO[r][0] = fmaf(pv, va[i].x, accO[r][0]);
                    accO[r][1] = fmaf(pv, va[i].y, accO[r][1]);
                    accO[r][2] = fmaf(pv, va[i].z, accO[r][2]);
                    accO[r][3] = fmaf(pv, va[i].w, accO[r][3]);
                    accO[r][4] = fmaf(pv, vb[i].x, accO[r][4]);
                    accO[r][5] = fmaf(pv, vb[i].y, accO[r][5]);
                    accO[r][6] = fmaf(pv, vb[i].z, accO[r][6]);
                    accO[r][7] = fmaf(pv, vb[i].w, accO[r][7]);
                }
            }
        }
    }

    // Write unnormalized partials.
    const size_t base = ((size_t)b * NT + t) * MAXC + chunk;
    float* pO = g_pO + base * 4096;
    float* pm = g_pm + base * 64;
    float* pl = g_pl + base * 64;
#pragma unroll
    for (int r = 0; r < 4; ++r) {
        if (tx == 0) {
            pm[ty * 4 + r] = m_i[r];
            pl[ty * 4 + r] = l_i[r];
        }
        *reinterpret_cast<float4*>(&pO[(ty * 4 + r) * 64 + tx * 8]) =
            make_float4(accO[r][0], accO[r][1], accO[r][2], accO[r][3]);
        *reinterpret_cast<float4*>(&pO[(ty * 4 + r) * 64 + tx * 8 + 4]) =
            make_float4(accO[r][4], accO[r][5], accO[r][6], accO[r][7]);
    }
}

// ---------------------------------------------------------------------------
// Combine: merge the <=8 chunks of each (b, row-tile) with the flash merge
// formula and write the normalized output.
// ---------------------------------------------------------------------------
__global__ __launch_bounds__(256) void combine_kernel(float* __restrict__ out)
{
    const int t = blockIdx.x >> 3;
    const int b = blockIdx.x & 7;
    const int nc = (NT - t + CHUNK - 1) / CHUNK;
    const int tid = threadIdx.x;
    const int r  = tid >> 2;          // 0..63
    const int e0 = (tid & 3) * 16;    // 16 e each

    const size_t base = ((size_t)b * NT + t) * MAXC;

    float m = -INFINITY;
    for (int c = 0; c < nc; ++c)
        m = fmaxf(m, g_pm[(base + c) * 64 + r]);

    float w[MAXC];
    float lsum = 0.f;
    for (int c = 0; c < nc; ++c) {
        float wc = __expf(g_pm[(base + c) * 64 + r] - m);
        w[c] = wc;
        lsum += wc * g_pl[(base + c) * 64 + r];
    }
    const float inv = 1.f / lsum;

    float o[16];
#pragma unroll
    for (int k = 0; k < 16; ++k) o[k] = 0.f;

    for (int c = 0; c < nc; ++c) {
        const float* pO = g_pO + (base + c) * 4096 + (size_t)r * 64 + e0;
        float wc = w[c];
#pragma unroll
        for (int k = 0; k < 16; k += 4) {
            float4 v = *reinterpret_cast<const float4*>(pO + k);
            o[k + 0] = fmaf(wc, v.x, o[k + 0]);
            o[k + 1] = fmaf(wc, v.y, o[k + 1]);
            o[k + 2] = fmaf(wc, v.z, o[k + 2]);
            o[k + 3] = fmaf(wc, v.w, o[k + 3]);
        }
    }

    float* dst = out + ((size_t)b * N_ + t * 64 + r) * E_ + e0;
#pragma unroll
    for (int k = 0; k < 16; k += 4)
        *reinterpret_cast<float4*>(dst + k) =
            make_float4(o[k] * inv, o[k + 1] * inv, o[k + 2] * inv, o[k + 3] * inv);
}

// ---------------------------------------------------------------------------
extern "C" void kernel_launch(void* const* d_in, const int* in_sizes, int n_in,
                              void* d_out, int out_size)
{
    (void)in_sizes; (void)n_in; (void)out_size;
    const float* input = (const float*)d_in[0];
    const float* Wk    = (const float*)d_in[1];
    // d_in[2] is q — dead in the reference, intentionally unused.
    const float* Wv    = (const float*)d_in[3];
    float* out = (float*)d_out;

    // Opt-in to >48KB dynamic smem for the partial kernel (idempotent,
    // non-stream call; legal during graph capture).
    cudaFuncSetAttribute(attn_partial,
                         cudaFuncAttributeMaxDynamicSharedMemorySize,
                         ATTN_SMEM_BYTES);

    proj_kernel<<<128, 256>>>(input, Wk, Wv);
    attn_partial<<<B_ * BLK_PER_B, 128, ATTN_SMEM_BYTES>>>();
    combine_kernel<<<B_ * NT, 256>>>(out);
}

// round 5
// speedup vs baseline: 1.4168x; 1.2287x over previous
#include <cuda_runtime.h>
#include <cuda_bf16.h>
#include <math.h>
#include <stdint.h>

#define B_ 8
#define N_ 2048
#define H_ 1024
#define E_ 64
#define NT 32            // number of 64-row tiles per batch
#define CHUNK 4          // j-tiles (64 cols each) per partial block
#define MAXC 8           // max chunks per row-tile = ceil(32/4)
#define BLK_PER_B 144    // sum_t ceil((32-t)/4)

// Scratch (no allocation allowed in kernel_launch).
__device__ float g_keys[B_ * N_ * E_];
__device__ float g_vals[B_ * N_ * E_];
__device__ float g_pO[B_ * NT * MAXC * 64 * 64];
__device__ float g_pm[B_ * NT * MAXC * 64];
__device__ float g_pl[B_ * NT * MAXC * 64];
// Pre-transposed, bf16-split weight matrix Bt[n][k] = [Wk|Wv][k][n], n<128, k<1024.
__device__ __nv_bfloat16 g_Wh[128 * 1024];
__device__ __nv_bfloat16 g_Wl[128 * 1024];

// ---------------------------------------------------------------------------
// Helpers (base-ISA only: ldmatrix + mma.sync — sm_100 plain target!)
// ---------------------------------------------------------------------------
__device__ __forceinline__ uint32_t smem_u32(const void* p) {
    uint32_t a;
    asm("{ .reg .u64 t; cvta.to.shared.u64 t, %1; cvt.u32.u64 %0, t; }"
        : "=r"(a) : "l"(p));
    return a;
}

#define SW128(o) ((o) ^ ((((uint32_t)(o)) >> 3) & 0x70))

#define LDSM_X4(r0, r1, r2, r3, addr) \
    asm volatile("ldmatrix.sync.aligned.m8n8.x4.shared.b16 {%0,%1,%2,%3}, [%4];" \
                 : "=r"(r0), "=r"(r1), "=r"(r2), "=r"(r3) : "r"(addr))

#define MMA_BF16(d0, d1, d2, d3, a0, a1, a2, a3, b0, b1) \
    asm volatile("mma.sync.aligned.m16n8k16.row.col.f32.bf16.bf16.f32 " \
                 "{%0,%1,%2,%3}, {%4,%5,%6,%7}, {%8,%9}, {%0,%1,%2,%3};" \
                 : "+f"(d0), "+f"(d1), "+f"(d2), "+f"(d3) \
                 : "r"(a0), "r"(a1), "r"(a2), "r"(a3), "r"(b0), "r"(b1))

__device__ __forceinline__ uint32_t pack2_hi(float a, float b) {
    __nv_bfloat162 h = __floats2bfloat162_rn(a, b);
    return *reinterpret_cast<uint32_t*>(&h);
}

// ---------------------------------------------------------------------------
// prep_w: Bt[n][k] = W[k][n] split into bf16 hi/lo. n<64 -> Wk, else Wv.
// ---------------------------------------------------------------------------
__global__ __launch_bounds__(256) void prep_w(const float* __restrict__ Wk,
                                              const float* __restrict__ Wv)
{
    const int n = blockIdx.x;          // 0..127
    const float* src = (n < 64) ? (Wk + n) : (Wv + (n - 64));
    for (int k = threadIdx.x; k < H_; k += 256) {
        float x = src[(size_t)k * E_];
        __nv_bfloat16 h = __float2bfloat16(x);
        float lo = x - __bfloat162float(h);
        g_Wh[n * H_ + k] = h;
        g_Wl[n * H_ + k] = __float2bfloat16(lo);
    }
}

// ---------------------------------------------------------------------------
// proj_mma: C[16384,128] = A[16384,1024] @ Bt^T, bf16 hi/lo split via
// mma.sync.m16n8k16. 8 warps, block tile 128x128, warp tile 32x64, BK=64.
// smem tiles (bf16, SW128-swizzled 128B rows): Ah, Al [128][64], Wh, Wl [128][64].
// ---------------------------------------------------------------------------
#define OFF_AH 0
#define OFF_AL (OFF_AH + 16384)
#define OFF_WH (OFF_AL + 16384)
#define OFF_WL (OFF_WH + 16384)
#define PROJ_SMEM (OFF_WL + 16384)

__global__ __launch_bounds__(256) void proj_mma(const float* __restrict__ A)
{
    extern __shared__ char sm[];
    const uint32_t sb = smem_u32(sm);
    const int tid = threadIdx.x;
    const int wid = tid >> 5;
    const int lane = tid & 31;
    const int M0 = blockIdx.x * 128;

    const int wm0 = (wid & 3) * 32;    // warp row offset in block tile
    const int wn0 = (wid >> 2) * 64;   // warp col offset (0 -> keys, 64 -> vals)

    float acc[2][8][4];
#pragma unroll
    for (int mi = 0; mi < 2; ++mi)
#pragma unroll
        for (int ni = 0; ni < 8; ++ni)
#pragma unroll
            for (int q = 0; q < 4; ++q) acc[mi][ni][q] = 0.f;

    // Per-thread ldmatrix row/chunk (within a 16x16 tile): row = lane&15,
    // k-chunk (16B) = lane>>4.
    const int lrow = lane & 15;
    const int lchk = lane >> 4;

    for (int kt = 0; kt < 16; ++kt) {
        // ---- load + convert A tile: 128 rows x 64 fp32 -> bf16 hi/lo ----
#pragma unroll
        for (int l = 0; l < 8; ++l) {
            int idx = tid + l * 256;        // 0..2047 float4s
            int row = idx >> 4;             // 0..127
            int c4  = (idx & 15) << 2;      // 0..60
            float4 a = *reinterpret_cast<const float4*>(
                A + (size_t)(M0 + row) * H_ + kt * 64 + c4);
            float hx = __bfloat162float(__float2bfloat16(a.x));
            float hy = __bfloat162float(__float2bfloat16(a.y));
            float hz = __bfloat162float(__float2bfloat16(a.z));
            float hw = __bfloat162float(__float2bfloat16(a.w));
            uint32_t so = SW128((uint32_t)(row * 128 + c4 * 2));
            *reinterpret_cast<uint2*>(sm + OFF_AH + so) =
                make_uint2(pack2_hi(a.x, a.y), pack2_hi(a.z, a.w));
            *reinterpret_cast<uint2*>(sm + OFF_AL + so) =
                make_uint2(pack2_hi(a.x - hx, a.y - hy), pack2_hi(a.z - hz, a.w - hw));
        }
        // ---- load W tiles (pre-split bf16): 128 rows(n) x 64 k ----
#pragma unroll
        for (int l = 0; l < 4; ++l) {
            int idx = tid + l * 256;        // 0..1023 16B-chunks
            int row = idx >> 3;             // n 0..127
            int s8  = (idx & 7) << 3;       // k-offset in elems, 0..56
            uint32_t so = SW128((uint32_t)(row * 128 + s8 * 2));
            *reinterpret_cast<uint4*>(sm + OFF_WH + so) =
                *reinterpret_cast<const uint4*>(&g_Wh[row * H_ + kt * 64 + s8]);
            *reinterpret_cast<uint4*>(sm + OFF_WL + so) =
                *reinterpret_cast<const uint4*>(&g_Wl[row * H_ + kt * 64 + s8]);
        }
        __syncthreads();

#pragma unroll
        for (int ks = 0; ks < 4; ++ks) {
            // A fragments (2 m-tiles, hi & lo)
            uint32_t ah[2][4], al[2][4];
#pragma unroll
            for (int mi = 0; mi < 2; ++mi) {
                uint32_t off = SW128((uint32_t)(
                    (wm0 + mi * 16 + lrow) * 128 + (ks * 2 + lchk) * 16));
                LDSM_X4(ah[mi][0], ah[mi][1], ah[mi][2], ah[mi][3],
                        sb + OFF_AH + off);
                LDSM_X4(al[mi][0], al[mi][1], al[mi][2], al[mi][3],
                        sb + OFF_AL + off);
            }
            // B fragments (4 groups of n=16, hi & lo)
            uint32_t bh[4][4], bl[4][4];
#pragma unroll
            for (int g = 0; g < 4; ++g) {
                uint32_t off = SW128((uint32_t)(
                    (wn0 + g * 16 + lrow) * 128 + (ks * 2 + lchk) * 16));
                LDSM_X4(bh[g][0], bh[g][1], bh[g][2], bh[g][3],
                        sb + OFF_WH + off);
                LDSM_X4(bl[g][0], bl[g][1], bl[g][2], bl[g][3],
                        sb + OFF_WL + off);
            }
            // MMAs: acc += Ah*Wh + Al*Wh + Ah*Wl
#pragma unroll
            for (int mi = 0; mi < 2; ++mi) {
#pragma unroll
                for (int ni = 0; ni < 8; ++ni) {
                    const int g = ni >> 1;
                    const int s = ni & 1;     // 0: regs {0,2}, 1: regs {1,3}
                    uint32_t b0h = bh[g][s], b1h = bh[g][s + 2];
                    uint32_t b0l = bl[g][s], b1l = bl[g][s + 2];
                    float* d = acc[mi][ni];
                    MMA_BF16(d[0], d[1], d[2], d[3],
                             ah[mi][0], ah[mi][1], ah[mi][2], ah[mi][3], b0h, b1h);
                    MMA_BF16(d[0], d[1], d[2], d[3],
                             al[mi][0], al[mi][1], al[mi][2], al[mi][3], b0h, b1h);
                    MMA_BF16(d[0], d[1], d[2], d[3],
                             ah[mi][0], ah[mi][1], ah[mi][2], ah[mi][3], b0l, b1l);
                }
            }
        }
        __syncthreads();
    }

    // ---- epilogue: acc -> g_keys (wn0=0) / g_vals (wn0=64) ----
    float* outm = (wn0 == 0) ? g_keys : g_vals;
    const int colb = (lane & 3) * 2;
    const int rowb = M0 + wm0 + (lane >> 2);
#pragma unroll
    for (int mi = 0; mi < 2; ++mi) {
#pragma unroll
        for (int ni = 0; ni < 8; ++ni) {
            const int col = ni * 8 + colb;
            const int r0 = rowb + mi * 16;
            *reinterpret_cast<float2*>(&outm[(size_t)r0 * E_ + col]) =
                make_float2(acc[mi][ni][0], acc[mi][ni][1]);
            *reinterpret_cast<float2*>(&outm[(size_t)(r0 + 8) * E_ + col]) =
                make_float2(acc[mi][ni][2], acc[mi][ni][3]);
        }
    }
}

// ---------------------------------------------------------------------------
// Attention partial pass (unchanged, known-good): one block = (batch, row
// tile, chunk of <=4 j-tiles), 128 threads, 4x8 micro-tiles, fp32 SIMT.
// ---------------------------------------------------------------------------
#define SM_KSH 0
#define SM_UE  (64 * 64)
#define SM_VC  (SM_UE + 64 * 68)
#define SM_FLOATS (SM_VC + 64 * 68)
#define ATTN_SMEM_BYTES (SM_FLOATS * 4)

__global__ __launch_bounds__(128) void attn_partial()
{
    extern __shared__ float smf[];
    float* Ksh = smf + SM_KSH;
    float* Ue  = smf + SM_UE;
    float* Vc  = smf + SM_VC;

    const int tid = threadIdx.x;
    const int ty = tid >> 3;
    const int tx = tid & 7;

    const int b = blockIdx.x / BLK_PER_B;
    int ent = blockIdx.x - b * BLK_PER_B;
    int t = 0, acc = 0;
    for (int tt = 0; tt < NT; ++tt) {
        int nc = (NT - tt + CHUNK - 1) / CHUNK;
        if (ent < acc + nc) { t = tt; break; }
        acc += nc;
    }
    const int chunk = ent - acc;
    const int j0 = t + chunk * CHUNK;
    const int j1 = min(NT, j0 + CHUNK);

    const float* keys = g_keys + ((size_t)b * N_ + t * 64) * E_;
    const float* vals = g_vals + (size_t)b * N_ * E_;

#pragma unroll
    for (int l = 0; l < 8; ++l) {
        int idx = tid + l * 128;
        int row = idx >> 4;
        int e4  = (idx & 15) << 2;
        float4 kk = *reinterpret_cast<const float4*>(keys + (size_t)row * E_ + e4);
        Ksh[(e4 + 0) * 64 + row] = kk.x;
        Ksh[(e4 + 1) * 64 + row] = kk.y;
        Ksh[(e4 + 2) * 64 + row] = kk.z;
        Ksh[(e4 + 3) * 64 + row] = kk.w;
    }

    float m_i[4], l_i[4], accO[4][8];
#pragma unroll
    for (int r = 0; r < 4; ++r) {
        m_i[r] = -INFINITY;
        l_i[r] = 0.f;
#pragma unroll
        for (int c = 0; c < 8; ++c) accO[r][c] = 0.f;
    }

    for (int jt = j0; jt < j1; ++jt) {
        __syncthreads();

#pragma unroll
        for (int l = 0; l < 8; ++l) {
            int idx = tid + l * 128;
            int row = idx >> 4;
            int e4  = (idx & 15) << 2;
            float4 v = *reinterpret_cast<const float4*>(
                vals + (size_t)(jt * 64 + row) * E_ + e4);
            Ue[(e4 + 0) * 68 + row] = v.x;
            Ue[(e4 + 1) * 68 + row] = v.y;
            Ue[(e4 + 2) * 68 + row] = v.z;
            Ue[(e4 + 3) * 68 + row] = v.w;
            *reinterpret_cast<float4*>(&Vc[row * 68 + e4]) = v;
        }
        __syncthreads();

        float S[4][8];
#pragma unroll
        for (int r = 0; r < 4; ++r)
#pragma unroll
            for (int c = 0; c < 8; ++c) S[r][c] = 0.f;

#pragma unroll 4
        for (int e = 0; e < 64; ++e) {
            float4 kf = *reinterpret_cast<float4*>(&Ksh[e * 64 + ty * 4]);
            float4 v0 = *reinterpret_cast<float4*>(&Ue[e * 68 + tx * 8]);
            float4 v1 = *reinterpret_cast<float4*>(&Ue[e * 68 + tx * 8 + 4]);
            float ka[4] = {kf.x, kf.y, kf.z, kf.w};
            float va[8] = {v0.x, v0.y, v0.z, v0.w, v1.x, v1.y, v1.z, v1.w};
#pragma unroll
            for (int r = 0; r < 4; ++r)
#pragma unroll
                for (int c = 0; c < 8; ++c)
                    S[r][c] = fmaf(ka[r], va[c], S[r][c]);
        }
        __syncthreads();

        const float sc = 0.125f;
        if (jt == t) {
#pragma unroll
            for (int r = 0; r < 4; ++r)
#pragma unroll
                for (int c = 0; c < 8; ++c)
                    S[r][c] = (tx * 8 + c >= ty * 4 + r) ? S[r][c] * sc : -1e30f;
        } else {
#pragma unroll
            for (int r = 0; r < 4; ++r)
#pragma unroll
                for (int c = 0; c < 8; ++c) S[r][c] *= sc;
        }

#pragma unroll
        for (int r = 0; r < 4; ++r) {
            float tmax = S[r][0];
#pragma unroll
            for (int c = 1; c < 8; ++c) tmax = fmaxf(tmax, S[r][c]);
#pragma unroll
            for (int msk = 1; msk < 8; msk <<= 1)
                tmax = fmaxf(tmax, __shfl_xor_sync(0xffffffffu, tmax, msk));
            float mnew = fmaxf(m_i[r], tmax);
            float alpha = __expf(m_i[r] - mnew);
            float ps = 0.f;
#pragma unroll
            for (int c = 0; c < 8; ++c) {
                float p = __expf(S[r][c] - mnew);
                S[r][c] = p;
                ps += p;
            }
#pragma unroll
            for (int msk = 1; msk < 8; msk <<= 1)
                ps += __shfl_xor_sync(0xffffffffu, ps, msk);
            l_i[r] = l_i[r] * alpha + ps;
            m_i[r] = mnew;
#pragma unroll
            for (int c = 0; c < 8; ++c) accO[r][c] *= alpha;
        }

#pragma unroll
        for (int r = 0; r < 4; ++r) {
            *reinterpret_cast<float4*>(&Ue[(ty * 4 + r) * 68 + tx * 8]) =
                make_float4(S[r][0], S[r][1], S[r][2], S[r][3]);
            *reinterpret_cast<float4*>(&Ue[(ty * 4 + r) * 68 + tx * 8 + 4]) =
                make_float4(S[r][4], S[r][5], S[r][6], S[r][7]);
        }
        __syncthreads();

#pragma unroll 4
        for (int c0 = 0; c0 < 64; c0 += 4) {
            float4 p[4];
#pragma unroll
            for (int r = 0; r < 4; ++r)
                p[r] = *reinterpret_cast<float4*>(&Ue[(ty * 4 + r) * 68 + c0]);
            float4 va[4], vb[4];
#pragma unroll
            for (int i = 0; i < 4; ++i) {
                va[i] = *reinterpret_cast<float4*>(&Vc[(c0 + i) * 68 + tx * 8]);
                vb[i] = *reinterpret_cast<float4*>(&Vc[(c0 + i) * 68 + tx * 8 + 4]);
            }
#pragma unroll
            for (int r = 0; r < 4; ++r) {
#pragma unroll
                for (int i = 0; i < 4; ++i) {
                    float pv = (i == 0) ? p[r].x : (i == 1) ? p[r].y
                             : (i == 2) ? p[r].z : p[r].w;
                    accO[r][0] = fmaf(pv, va[i].x, accO[r][0]);
                    accO[r][1] = fmaf(pv, va[i].y, accO[r][1]);
                    accO[r][2] = fmaf(pv, va[i].z, accO[r][2]);
                    accO[r][3] = fmaf(pv, va[i].w, accO[r][3]);
                    accO[r][4] = fmaf(pv, vb[i].x, accO[r][4]);
                    accO[r][5] = fmaf(pv, vb[i].y, accO[r][5]);
                    accO[r][6] = fmaf(pv, vb[i].z, accO[r][6]);
                    accO[r][7] = fmaf(pv, vb[i].w, accO[r][7]);
                }
            }
        }
    }

    const size_t base = ((size_t)b * NT + t) * MAXC + chunk;
    float* pO = g_pO + base * 4096;
    float* pm = g_pm + base * 64;
    float* pl = g_pl + base * 64;
#pragma unroll
    for (int r = 0; r < 4; ++r) {
        if (tx == 0) {
            pm[ty * 4 + r] = m_i[r];
            pl[ty * 4 + r] = l_i[r];
        }
        *reinterpret_cast<float4*>(&pO[(ty * 4 + r) * 64 + tx * 8]) =
            make_float4(accO[r][0], accO[r][1], accO[r][2], accO[r][3]);
        *reinterpret_cast<float4*>(&pO[(ty * 4 + r) * 64 + tx * 8 + 4]) =
            make_float4(accO[r][4], accO[r][5], accO[r][6], accO[r][7]);
    }
}

// ---------------------------------------------------------------------------
// Combine: merge the <=8 chunks of each (b, row-tile), write normalized out.
// ---------------------------------------------------------------------------
__global__ __launch_bounds__(256) void combine_kernel(float* __restrict__ out)
{
    const int t = blockIdx.x >> 3;
    const int b = blockIdx.x & 7;
    const int nc = (NT - t + CHUNK - 1) / CHUNK;
    const int tid = threadIdx.x;
    const int r  = tid >> 2;
    const int e0 = (tid & 3) * 16;

    const size_t base = ((size_t)b * NT + t) * MAXC;

    float m = -INFINITY;
    for (int c = 0; c < nc; ++c)
        m = fmaxf(m, g_pm[(base + c) * 64 + r]);

    float w[MAXC];
    float lsum = 0.f;
    for (int c = 0; c < nc; ++c) {
        float wc = __expf(g_pm[(base + c) * 64 + r] - m);
        w[c] = wc;
        lsum += wc * g_pl[(base + c) * 64 + r];
    }
    const float inv = 1.f / lsum;

    float o[16];
#pragma unroll
    for (int k = 0; k < 16; ++k) o[k] = 0.f;

    for (int c = 0; c < nc; ++c) {
        const float* pO = g_pO + (base + c) * 4096 + (size_t)r * 64 + e0;
        float wc = w[c];
#pragma unroll
        for (int k = 0; k < 16; k += 4) {
            float4 v = *reinterpret_cast<const float4*>(pO + k);
            o[k + 0] = fmaf(wc, v.x, o[k + 0]);
            o[k + 1] = fmaf(wc, v.y, o[k + 1]);
            o[k + 2] = fmaf(wc, v.z, o[k + 2]);
            o[k + 3] = fmaf(wc, v.w, o[k + 3]);
        }
    }

    float* dst = out + ((size_t)b * N_ + t * 64 + r) * E_ + e0;
#pragma unroll
    for (int k = 0; k < 16; k += 4)
        *reinterpret_cast<float4*>(dst + k) =
            make_float4(o[k] * inv, o[k + 1] * inv, o[k + 2] * inv, o[k + 3] * inv);
}

// ---------------------------------------------------------------------------
extern "C" void kernel_launch(void* const* d_in, const int* in_sizes, int n_in,
                              void* d_out, int out_size)
{
    (void)in_sizes; (void)n_in; (void)out_size;
    const float* input = (const float*)d_in[0];
    const float* Wk    = (const float*)d_in[1];
    // d_in[2] is q — dead in the reference, intentionally unused.
    const float* Wv    = (const float*)d_in[3];
    float* out = (float*)d_out;

    cudaFuncSetAttribute(proj_mma,
                         cudaFuncAttributeMaxDynamicSharedMemorySize, PROJ_SMEM);
    cudaFuncSetAttribute(attn_partial,
                         cudaFuncAttributeMaxDynamicSharedMemorySize, ATTN_SMEM_BYTES);

    prep_w<<<128, 256>>>(Wk, Wv);
    proj_mma<<<128, 256, PROJ_SMEM>>>(input);
    attn_partial<<<B_ * BLK_PER_B, 128, ATTN_SMEM_BYTES>>>();
    combine_kernel<<<B_ * NT, 256>>>(out);
}

// round 6
// speedup vs baseline: 2.8652x; 2.0224x over previous
#include <cuda_runtime.h>
#include <cuda_bf16.h>
#include <math.h>
#include <stdint.h>

#define B_ 8
#define N_ 2048
#define H_ 1024
#define E_ 64
#define NT 32            // number of 64-row tiles per batch
#define CHUNK 4          // j-tiles (64 cols each) per partial block
#define MAXC 8           // max chunks per row-tile = ceil(32/4)
#define BLK_PER_B 144    // sum_t ceil((32-t)/4)

// Scratch (no allocation allowed in kernel_launch).
__device__ float g_pO[B_ * NT * MAXC * 64 * 64];
__device__ float g_pm[B_ * NT * MAXC * 64];
__device__ float g_pl[B_ * NT * MAXC * 64];
// K/V stored directly as bf16 hi/lo (written by proj epilogue). 2MB each -> L2-resident.
__device__ __nv_bfloat16 g_kh[B_ * N_ * E_];
__device__ __nv_bfloat16 g_kl[B_ * N_ * E_];
__device__ __nv_bfloat16 g_vh[B_ * N_ * E_];
__device__ __nv_bfloat16 g_vl[B_ * N_ * E_];
// Pre-transposed, bf16-split weight matrix Bt[n][k] = [Wk|Wv][k][n].
__device__ __nv_bfloat16 g_Wh[128 * 1024];
__device__ __nv_bfloat16 g_Wl[128 * 1024];

// ---------------------------------------------------------------------------
// Helpers (base-ISA only: ldmatrix + mma.sync — plain sm_100 target)
// ---------------------------------------------------------------------------
__device__ __forceinline__ uint32_t smem_u32(const void* p) {
    uint32_t a;
    asm("{ .reg .u64 t; cvta.to.shared.u64 t, %1; cvt.u32.u64 %0, t; }"
        : "=r"(a) : "l"(p));
    return a;
}

#define SW128(o) ((o) ^ ((((uint32_t)(o)) >> 3) & 0x70))

#define LDSM_X4(r0, r1, r2, r3, addr) \
    asm volatile("ldmatrix.sync.aligned.m8n8.x4.shared.b16 {%0,%1,%2,%3}, [%4];" \
                 : "=r"(r0), "=r"(r1), "=r"(r2), "=r"(r3) : "r"(addr))

#define LDSM_X4_T(r0, r1, r2, r3, addr) \
    asm volatile("ldmatrix.sync.aligned.m8n8.x4.trans.shared.b16 {%0,%1,%2,%3}, [%4];" \
                 : "=r"(r0), "=r"(r1), "=r"(r2), "=r"(r3) : "r"(addr))

#define MMA_BF16(d0, d1, d2, d3, a0, a1, a2, a3, b0, b1) \
    asm volatile("mma.sync.aligned.m16n8k16.row.col.f32.bf16.bf16.f32 " \
                 "{%0,%1,%2,%3}, {%4,%5,%6,%7}, {%8,%9}, {%0,%1,%2,%3};" \
                 : "+f"(d0), "+f"(d1), "+f"(d2), "+f"(d3) \
                 : "r"(a0), "r"(a1), "r"(a2), "r"(a3), "r"(b0), "r"(b1))

__device__ __forceinline__ uint32_t pack2_hi(float a, float b) {
    __nv_bfloat162 h = __floats2bfloat162_rn(a, b);
    return *reinterpret_cast<uint32_t*>(&h);
}
__device__ __forceinline__ float bf16_rt(float x) {   // round-trip through bf16
    return __bfloat162float(__float2bfloat16(x));
}

// ---------------------------------------------------------------------------
// prep_w: Bt[n][k] = W[k][n] split into bf16 hi/lo. n<64 -> Wk, else Wv.
// ---------------------------------------------------------------------------
__global__ __launch_bounds__(256) void prep_w(const float* __restrict__ Wk,
                                              const float* __restrict__ Wv)
{
    const int n = blockIdx.x;          // 0..127
    const float* src = (n < 64) ? (Wk + n) : (Wv + (n - 64));
    for (int k = threadIdx.x; k < H_; k += 256) {
        float x = src[(size_t)k * E_];
        __nv_bfloat16 h = __float2bfloat16(x);
        float lo = x - __bfloat162float(h);
        g_Wh[n * H_ + k] = h;
        g_Wl[n * H_ + k] = __float2bfloat16(lo);
    }
}

// ---------------------------------------------------------------------------
// proj_mma: C[16384,128] = A[16384,1024] @ Bt^T, bf16 hi/lo split via
// mma.sync.m16n8k16. 8 warps, block tile 128x128, warp tile 32x64, BK=64.
// Epilogue writes K/V directly as bf16 hi/lo to g_kh/g_kl/g_vh/g_vl.
// ---------------------------------------------------------------------------
#define OFF_AH 0
#define OFF_AL (OFF_AH + 16384)
#define OFF_WH (OFF_AL + 16384)
#define OFF_WL (OFF_WH + 16384)
#define PROJ_SMEM (OFF_WL + 16384)

__global__ __launch_bounds__(256) void proj_mma(const float* __restrict__ A)
{
    extern __shared__ char sm[];
    const uint32_t sb = smem_u32(sm);
    const int tid = threadIdx.x;
    const int wid = tid >> 5;
    const int lane = tid & 31;
    const int M0 = blockIdx.x * 128;

    const int wm0 = (wid & 3) * 32;    // warp row offset
    const int wn0 = (wid >> 2) * 64;   // 0 -> keys, 64 -> vals

    float acc[2][8][4];
#pragma unroll
    for (int mi = 0; mi < 2; ++mi)
#pragma unroll
        for (int ni = 0; ni < 8; ++ni)
#pragma unroll
            for (int q = 0; q < 4; ++q) acc[mi][ni][q] = 0.f;

    const int lrow = lane & 15;
    const int lchk = lane >> 4;

    for (int kt = 0; kt < 16; ++kt) {
#pragma unroll
        for (int l = 0; l < 8; ++l) {
            int idx = tid + l * 256;
            int row = idx >> 4;
            int c4  = (idx & 15) << 2;
            float4 a = *reinterpret_cast<const float4*>(
                A + (size_t)(M0 + row) * H_ + kt * 64 + c4);
            float hx = bf16_rt(a.x), hy = bf16_rt(a.y);
            float hz = bf16_rt(a.z), hw = bf16_rt(a.w);
            uint32_t so = SW128((uint32_t)(row * 128 + c4 * 2));
            *reinterpret_cast<uint2*>(sm + OFF_AH + so) =
                make_uint2(pack2_hi(a.x, a.y), pack2_hi(a.z, a.w));
            *reinterpret_cast<uint2*>(sm + OFF_AL + so) =
                make_uint2(pack2_hi(a.x - hx, a.y - hy), pack2_hi(a.z - hz, a.w - hw));
        }
#pragma unroll
        for (int l = 0; l < 4; ++l) {
            int idx = tid + l * 256;
            int row = idx >> 3;
            int s8  = (idx & 7) << 3;
            uint32_t so = SW128((uint32_t)(row * 128 + s8 * 2));
            *reinterpret_cast<uint4*>(sm + OFF_WH + so) =
                *reinterpret_cast<const uint4*>(&g_Wh[row * H_ + kt * 64 + s8]);
            *reinterpret_cast<uint4*>(sm + OFF_WL + so) =
                *reinterpret_cast<const uint4*>(&g_Wl[row * H_ + kt * 64 + s8]);
        }
        __syncthreads();

#pragma unroll
        for (int ks = 0; ks < 4; ++ks) {
            uint32_t ah[2][4], al[2][4];
#pragma unroll
            for (int mi = 0; mi < 2; ++mi) {
                uint32_t off = SW128((uint32_t)(
                    (wm0 + mi * 16 + lrow) * 128 + (ks * 2 + lchk) * 16));
                LDSM_X4(ah[mi][0], ah[mi][1], ah[mi][2], ah[mi][3], sb + OFF_AH + off);
                LDSM_X4(al[mi][0], al[mi][1], al[mi][2], al[mi][3], sb + OFF_AL + off);
            }
            uint32_t bh[4][4], bl[4][4];
#pragma unroll
            for (int g = 0; g < 4; ++g) {
                uint32_t off = SW128((uint32_t)(
                    (wn0 + g * 16 + lrow) * 128 + (ks * 2 + lchk) * 16));
                LDSM_X4(bh[g][0], bh[g][1], bh[g][2], bh[g][3], sb + OFF_WH + off);
                LDSM_X4(bl[g][0], bl[g][1], bl[g][2], bl[g][3], sb + OFF_WL + off);
            }
#pragma unroll
            for (int mi = 0; mi < 2; ++mi) {
#pragma unroll
                for (int ni = 0; ni < 8; ++ni) {
                    const int g = ni >> 1;
                    const int s = ni & 1;
                    uint32_t b0h = bh[g][s], b1h = bh[g][s + 2];
                    uint32_t b0l = bl[g][s], b1l = bl[g][s + 2];
                    float* d = acc[mi][ni];
                    MMA_BF16(d[0], d[1], d[2], d[3],
                             ah[mi][0], ah[mi][1], ah[mi][2], ah[mi][3], b0h, b1h);
                    MMA_BF16(d[0], d[1], d[2], d[3],
                             al[mi][0], al[mi][1], al[mi][2], al[mi][3], b0h, b1h);
                    MMA_BF16(d[0], d[1], d[2], d[3],
                             ah[mi][0], ah[mi][1], ah[mi][2], ah[mi][3], b0l, b1l);
                }
            }
        }
        __syncthreads();
    }

    // ---- epilogue: acc -> bf16 hi/lo K or V arrays ----
    __nv_bfloat16* outh = (wn0 == 0) ? g_kh : g_vh;
    __nv_bfloat16* outl = (wn0 == 0) ? g_kl : g_vl;
    const int colb = (lane & 3) * 2;
    const int rowb = M0 + wm0 + (lane >> 2);
#pragma unroll
    for (int mi = 0; mi < 2; ++mi) {
#pragma unroll
        for (int ni = 0; ni < 8; ++ni) {
            const int col = ni * 8 + colb;
#pragma unroll
            for (int hq = 0; hq < 2; ++hq) {
                const int r = rowb + mi * 16 + hq * 8;
                float d0 = acc[mi][ni][hq * 2 + 0];
                float d1 = acc[mi][ni][hq * 2 + 1];
                *reinterpret_cast<uint32_t*>(&outh[(size_t)r * E_ + col]) =
                    pack2_hi(d0, d1);
                *reinterpret_cast<uint32_t*>(&outl[(size_t)r * E_ + col]) =
                    pack2_hi(d0 - bf16_rt(d0), d1 - bf16_rt(d1));
            }
        }
    }
}

// ---------------------------------------------------------------------------
// attn_partial (mma.sync): one block = (batch, 64-row tile, chunk of <=4
// j-tiles). 128 threads / 4 warps; warp owns 16 rows x 64 cols per j-tile.
// S = Kh.Vh + Kl.Vh + Kh.Vl ; P kept in registers (C-frag == A-frag layout);
// O = Ph.V^T h + Pl.V^T h + Ph.V^T l with V^T fragments via ldmatrix.trans
// on the SAME Vb smem tile used by the S-gemm.
// smem (bf16, SW128 rows of 128B): Kh,Kl,Vh,Vl [64][64] -> 32KB.
// ---------------------------------------------------------------------------
#define AT_KH 0
#define AT_KL 8192
#define AT_VH 16384
#define AT_VL 24576
#define ATTN_SMEM_BYTES 32768

__global__ __launch_bounds__(128) void attn_partial()
{
    extern __shared__ char sm[];
    const uint32_t sb = smem_u32(sm);
    const int tid = threadIdx.x;
    const int wid = tid >> 5;
    const int lane = tid & 31;

    // block -> (b, t, chunk)
    const int b = blockIdx.x / BLK_PER_B;
    int ent = blockIdx.x - b * BLK_PER_B;
    int t = 0, acc0 = 0;
    for (int tt = 0; tt < NT; ++tt) {
        int nc = (NT - tt + CHUNK - 1) / CHUNK;
        if (ent < acc0 + nc) { t = tt; break; }
        acc0 += nc;
    }
    const int chunk = ent - acc0;
    const int j0 = t + chunk * CHUNK;
    const int j1 = min(NT, j0 + CHUNK);

    const int wm0 = wid * 16;
    const int lrow = lane & 15;
    const int lchk = lane >> 4;

    // ---- load K tile (bf16 h/l), 64 rows x 64 e ----
    {
        const size_t kbase = ((size_t)b * N_ + t * 64) * E_;
#pragma unroll
        for (int l = 0; l < 4; ++l) {
            int idx = tid + l * 128;        // 512 16B-chunks
            int row = idx >> 3;
            int e8  = (idx & 7) << 3;
            uint32_t so = SW128((uint32_t)(row * 128 + e8 * 2));
            *reinterpret_cast<uint4*>(sm + AT_KH + so) =
                *reinterpret_cast<const uint4*>(&g_kh[kbase + (size_t)row * E_ + e8]);
            *reinterpret_cast<uint4*>(sm + AT_KL + so) =
                *reinterpret_cast<const uint4*>(&g_kl[kbase + (size_t)row * E_ + e8]);
        }
    }

    float m_i[2], l_i[2], accO[8][4];
#pragma unroll
    for (int h = 0; h < 2; ++h) { m_i[h] = -INFINITY; l_i[h] = 0.f; }
#pragma unroll
    for (int ne = 0; ne < 8; ++ne)
#pragma unroll
        for (int q = 0; q < 4; ++q) accO[ne][q] = 0.f;

    for (int jt = j0; jt < j1; ++jt) {
        __syncthreads();   // K stores (1st iter) / prev O-gemm ldmatrix done

        // ---- load V tile (bf16 h/l) ----
        {
            const size_t vbase = ((size_t)b * N_ + jt * 64) * E_;
#pragma unroll
            for (int l = 0; l < 4; ++l) {
                int idx = tid + l * 128;
                int row = idx >> 3;
                int e8  = (idx & 7) << 3;
                uint32_t so = SW128((uint32_t)(row * 128 + e8 * 2));
                *reinterpret_cast<uint4*>(sm + AT_VH + so) =
                    *reinterpret_cast<const uint4*>(&g_vh[vbase + (size_t)row * E_ + e8]);
                *reinterpret_cast<uint4*>(sm + AT_VL + so) =
                    *reinterpret_cast<const uint4*>(&g_vl[vbase + (size_t)row * E_ + e8]);
            }
        }
        __syncthreads();

        // ---- S-gemm: Sa[ni][q], rows wm0+lane/4 (+8), cols ni*8+(lane&3)*2+{0,1}
        float Sa[8][4];
#pragma unroll
        for (int ni = 0; ni < 8; ++ni)
#pragma unroll
            for (int q = 0; q < 4; ++q) Sa[ni][q] = 0.f;

#pragma unroll
        for (int ks = 0; ks < 4; ++ks) {
            uint32_t ah[4], al[4];
            uint32_t offa = SW128((uint32_t)(
                (wm0 + lrow) * 128 + (ks * 2 + lchk) * 16));
            LDSM_X4(ah[0], ah[1], ah[2], ah[3], sb + AT_KH + offa);
            LDSM_X4(al[0], al[1], al[2], al[3], sb + AT_KL + offa);
            uint32_t bh[4][4], bl[4][4];
#pragma unroll
            for (int g = 0; g < 4; ++g) {
                uint32_t offb = SW128((uint32_t)(
                    (g * 16 + lrow) * 128 + (ks * 2 + lchk) * 16));
                LDSM_X4(bh[g][0], bh[g][1], bh[g][2], bh[g][3], sb + AT_VH + offb);
                LDSM_X4(bl[g][0], bl[g][1], bl[g][2], bl[g][3], sb + AT_VL + offb);
            }
#pragma unroll
            for (int ni = 0; ni < 8; ++ni) {
                const int g = ni >> 1;
                const int s = ni & 1;
                uint32_t b0h = bh[g][s], b1h = bh[g][s + 2];
                uint32_t b0l = bl[g][s], b1l = bl[g][s + 2];
                float* d = Sa[ni];
                MMA_BF16(d[0], d[1], d[2], d[3], ah[0], ah[1], ah[2], ah[3], b0h, b1h);
                MMA_BF16(d[0], d[1], d[2], d[3], al[0], al[1], al[2], al[3], b0h, b1h);
                MMA_BF16(d[0], d[1], d[2], d[3], ah[0], ah[1], ah[2], ah[3], b0l, b1l);
            }
        }

        // ---- scale + mask ----
        const float sc = 0.125f;   // 1/sqrt(64)
        if (jt == t) {
#pragma unroll
            for (int ni = 0; ni < 8; ++ni)
#pragma unroll
                for (int q = 0; q < 4; ++q) {
                    int i_loc = wm0 + (lane >> 2) + ((q >> 1) << 3);
                    int j_loc = ni * 8 + (lane & 3) * 2 + (q & 1);
                    Sa[ni][q] = (j_loc >= i_loc) ? Sa[ni][q] * sc : -1e30f;
                }
        } else {
#pragma unroll
            for (int ni = 0; ni < 8; ++ni)
#pragma unroll
                for (int q = 0; q < 4; ++q) Sa[ni][q] *= sc;
        }

        // ---- online softmax (2 row-slots per thread; quad reduction) ----
#pragma unroll
        for (int h = 0; h < 2; ++h) {
            float tmax = -INFINITY;
#pragma unroll
            for (int ni = 0; ni < 8; ++ni)
                tmax = fmaxf(tmax, fmaxf(Sa[ni][h * 2], Sa[ni][h * 2 + 1]));
            tmax = fmaxf(tmax, __shfl_xor_sync(0xffffffffu, tmax, 1));
            tmax = fmaxf(tmax, __shfl_xor_sync(0xffffffffu, tmax, 2));
            float mnew = fmaxf(m_i[h], tmax);
            float alpha = __expf(m_i[h] - mnew);
            float ps = 0.f;
#pragma unroll
            for (int ni = 0; ni < 8; ++ni) {
                float p0 = __expf(Sa[ni][h * 2] - mnew);
                float p1 = __expf(Sa[ni][h * 2 + 1] - mnew);
                Sa[ni][h * 2] = p0;
                Sa[ni][h * 2 + 1] = p1;
                ps += p0 + p1;
            }
            ps += __shfl_xor_sync(0xffffffffu, ps, 1);
            ps += __shfl_xor_sync(0xffffffffu, ps, 2);
            l_i[h] = l_i[h] * alpha + ps;
            m_i[h] = mnew;
#pragma unroll
            for (int ne = 0; ne < 8; ++ne) {
                accO[ne][h * 2] *= alpha;
                accO[ne][h * 2 + 1] *= alpha;
            }
        }

        // ---- O-gemm: accO += P @ V, B-frags via ldmatrix.trans on Vb ----
#pragma unroll
        for (int kc = 0; kc < 4; ++kc) {
            const int n0 = 2 * kc, n1 = 2 * kc + 1;
            // P fragments (C-frag layout == A-frag layout), hi/lo split
            uint32_t pah[4], pal[4];
            {
                float p00 = Sa[n0][0], p01 = Sa[n0][1];
                float p02 = Sa[n0][2], p03 = Sa[n0][3];
                float p10 = Sa[n1][0], p11 = Sa[n1][1];
                float p12 = Sa[n1][2], p13 = Sa[n1][3];
                pah[0] = pack2_hi(p00, p01);
                pah[1] = pack2_hi(p02, p03);
                pah[2] = pack2_hi(p10, p11);
                pah[3] = pack2_hi(p12, p13);
                pal[0] = pack2_hi(p00 - bf16_rt(p00), p01 - bf16_rt(p01));
                pal[1] = pack2_hi(p02 - bf16_rt(p02), p03 - bf16_rt(p03));
                pal[2] = pack2_hi(p10 - bf16_rt(p10), p11 - bf16_rt(p11));
                pal[3] = pack2_hi(p12 - bf16_rt(p12), p13 - bf16_rt(p13));
            }
            uint32_t tbh[4][4], tbl[4][4];
#pragma unroll
            for (int g = 0; g < 4; ++g) {
                uint32_t offt = SW128((uint32_t)(
                    (kc * 16 + lrow) * 128 + g * 32 + lchk * 16));
                LDSM_X4_T(tbh[g][0], tbh[g][1], tbh[g][2], tbh[g][3], sb + AT_VH + offt);
                LDSM_X4_T(tbl[g][0], tbl[g][1], tbl[g][2], tbl[g][3], sb + AT_VL + offt);
            }
#pragma unroll
            for (int ne = 0; ne < 8; ++ne) {
                const int g = ne >> 1;
                const int s = ne & 1;
                uint32_t b0h = tbh[g][2 * s], b1h = tbh[g][2 * s + 1];
                uint32_t b0l = tbl[g][2 * s], b1l = tbl[g][2 * s + 1];
                float* d = accO[ne];
                MMA_BF16(d[0], d[1], d[2], d[3], pah[0], pah[1], pah[2], pah[3], b0h, b1h);
                MMA_BF16(d[0], d[1], d[2], d[3], pal[0], pal[1], pal[2], pal[3], b0h, b1h);
                MMA_BF16(d[0], d[1], d[2], d[3], pah[0], pah[1], pah[2], pah[3], b0l, b1l);
            }
        }
    }

    // ---- write unnormalized partials ----
    const size_t base = ((size_t)b * NT + t) * MAXC + chunk;
    float* pO = g_pO + base * 4096;
    const int r0 = wm0 + (lane >> 2);
    if ((lane & 3) == 0) {
        g_pm[base * 64 + r0]     = m_i[0];
        g_pm[base * 64 + r0 + 8] = m_i[1];
        g_pl[base * 64 + r0]     = l_i[0];
        g_pl[base * 64 + r0 + 8] = l_i[1];
    }
#pragma unroll
    for (int ne = 0; ne < 8; ++ne) {
        const int e = ne * 8 + (lane & 3) * 2;
        *reinterpret_cast<float2*>(&pO[(size_t)r0 * 64 + e]) =
            make_float2(accO[ne][0], accO[ne][1]);
        *reinterpret_cast<float2*>(&pO[(size_t)(r0 + 8) * 64 + e]) =
            make_float2(accO[ne][2], accO[ne][3]);
    }
}

// ---------------------------------------------------------------------------
// Combine: merge the <=8 chunks of each (b, row-tile), write normalized out.
// ---------------------------------------------------------------------------
__global__ __launch_bounds__(256) void combine_kernel(float* __restrict__ out)
{
    const int t = blockIdx.x >> 3;
    const int b = blockIdx.x & 7;
    const int nc = (NT - t + CHUNK - 1) / CHUNK;
    const int tid = threadIdx.x;
    const int r  = tid >> 2;
    const int e0 = (tid & 3) * 16;

    const size_t base = ((size_t)b * NT + t) * MAXC;

    float m = -INFINITY;
    for (int c = 0; c < nc; ++c)
        m = fmaxf(m, g_pm[(base + c) * 64 + r]);

    float w[MAXC];
    float lsum = 0.f;
    for (int c = 0; c < nc; ++c) {
        float wc = __expf(g_pm[(base + c) * 64 + r] - m);
        w[c] = wc;
        lsum += wc * g_pl[(base + c) * 64 + r];
    }
    const float inv = 1.f / lsum;

    float o[16];
#pragma unroll
    for (int k = 0; k < 16; ++k) o[k] = 0.f;

    for (int c = 0; c < nc; ++c) {
        const float* pO = g_pO + (base + c) * 4096 + (size_t)r * 64 + e0;
        float wc = w[c];
#pragma unroll
        for (int k = 0; k < 16; k += 4) {
            float4 v = *reinterpret_cast<const float4*>(pO + k);
            o[k + 0] = fmaf(wc, v.x, o[k + 0]);
            o[k + 1] = fmaf(wc, v.y, o[k + 1]);
            o[k + 2] = fmaf(wc, v.z, o[k + 2]);
            o[k + 3] = fmaf(wc, v.w, o[k + 3]);
        }
    }

    float* dst = out + ((size_t)b * N_ + t * 64 + r) * E_ + e0;
#pragma unroll
    for (int k = 0; k < 16; k += 4)
        *reinterpret_cast<float4*>(dst + k) =
            make_float4(o[k] * inv, o[k + 1] * inv, o[k + 2] * inv, o[k + 3] * inv);
}

// ---------------------------------------------------------------------------
extern "C" void kernel_launch(void* const* d_in, const int* in_sizes, int n_in,
                              void* d_out, int out_size)
{
    (void)in_sizes; (void)n_in; (void)out_size;
    const float* input = (const float*)d_in[0];
    const float* Wk    = (const float*)d_in[1];
    // d_in[2] is q — dead in the reference, intentionally unused.
    const float* Wv    = (const float*)d_in[3];
    float* out = (float*)d_out;

    cudaFuncSetAttribute(proj_mma,
                         cudaFuncAttributeMaxDynamicSharedMemorySize, PROJ_SMEM);
    cudaFuncSetAttribute(attn_partial,
                         cudaFuncAttributeMaxDynamicSharedMemorySize, ATTN_SMEM_BYTES);

    prep_w<<<128, 256>>>(Wk, Wv);
    proj_mma<<<128, 256, PROJ_SMEM>>>(input);
    attn_partial<<<B_ * BLK_PER_B, 128, ATTN_SMEM_BYTES>>>();
    combine_kernel<<<B_ * NT, 256>>>(out);
}

// round 8
// speedup vs baseline: 3.4951x; 1.2198x over previous
#include <cuda_runtime.h>
#include <cuda_bf16.h>
#include <math.h>
#include <stdint.h>

#define B_ 8
#define N_ 2048
#define H_ 1024
#define E_ 64
#define NT 32            // number of 64-row tiles per batch
#define CHUNK 8          // j-tiles (64 cols each) per partial block
#define MAXC 4           // max chunks per row-tile = ceil(32/8)
#define BLK_PER_B 80     // sum_t ceil((32-t)/8)

// Scratch (no allocation allowed in kernel_launch).
__device__ float g_pO[B_ * NT * MAXC * 64 * 64];
__device__ float g_pm[B_ * NT * MAXC * 64];
__device__ float g_pl[B_ * NT * MAXC * 64];
// K/V stored directly as bf16 hi/lo (written by proj epilogue). L2-resident.
__device__ __nv_bfloat16 g_kh[B_ * N_ * E_];
__device__ __nv_bfloat16 g_kl[B_ * N_ * E_];
__device__ __nv_bfloat16 g_vh[B_ * N_ * E_];
__device__ __nv_bfloat16 g_vl[B_ * N_ * E_];
// Pre-transposed, bf16-split weight matrix Bt[n][k] = [Wk|Wv][k][n].
__device__ __nv_bfloat16 g_Wh[128 * 1024];
__device__ __nv_bfloat16 g_Wl[128 * 1024];

// ---------------------------------------------------------------------------
// Helpers (base-ISA: ldmatrix + mma.sync + cp.async — plain sm_100 target)
// ---------------------------------------------------------------------------
__device__ __forceinline__ uint32_t smem_u32(const void* p) {
    uint32_t a;
    asm("{ .reg .u64 t; cvta.to.shared.u64 t, %1; cvt.u32.u64 %0, t; }"
        : "=r"(a) : "l"(p));
    return a;
}

#define SW128(o) ((o) ^ ((((uint32_t)(o)) >> 3) & 0x70))

#define LDSM_X4(r0, r1, r2, r3, addr) \
    asm volatile("ldmatrix.sync.aligned.m8n8.x4.shared.b16 {%0,%1,%2,%3}, [%4];" \
                 : "=r"(r0), "=r"(r1), "=r"(r2), "=r"(r3) : "r"(addr))

#define LDSM_X4_T(r0, r1, r2, r3, addr) \
    asm volatile("ldmatrix.sync.aligned.m8n8.x4.trans.shared.b16 {%0,%1,%2,%3}, [%4];" \
                 : "=r"(r0), "=r"(r1), "=r"(r2), "=r"(r3) : "r"(addr))

#define MMA_BF16(d0, d1, d2, d3, a0, a1, a2, a3, b0, b1) \
    asm volatile("mma.sync.aligned.m16n8k16.row.col.f32.bf16.bf16.f32 " \
                 "{%0,%1,%2,%3}, {%4,%5,%6,%7}, {%8,%9}, {%0,%1,%2,%3};" \
                 : "+f"(d0), "+f"(d1), "+f"(d2), "+f"(d3) \
                 : "r"(a0), "r"(a1), "r"(a2), "r"(a3), "r"(b0), "r"(b1))

#define CP16(dst, src) \
    asm volatile("cp.async.cg.shared.global [%0], [%1], 16;" \
                 :: "r"(dst), "l"(src) : "memory")
#define CP_COMMIT asm volatile("cp.async.commit_group;" ::: "memory")
#define CP_WAIT(n) asm volatile("cp.async.wait_group %0;" :: "n"(n) : "memory")

__device__ __forceinline__ uint32_t pack2_hi(float a, float b) {
    __nv_bfloat162 h = __floats2bfloat162_rn(a, b);
    return *reinterpret_cast<uint32_t*>(&h);
}
__device__ __forceinline__ float bf16_rt(float x) {
    return __bfloat162float(__float2bfloat16(x));
}

// ---------------------------------------------------------------------------
// prep_w: Bt[n][k] = W[k][n] split into bf16 hi/lo. n<64 -> Wk, else Wv.
// ---------------------------------------------------------------------------
__global__ __launch_bounds__(256) void prep_w(const float* __restrict__ Wk,
                                              const float* __restrict__ Wv)
{
    const int n = blockIdx.x;
    const float* src = (n < 64) ? (Wk + n) : (Wv + (n - 64));
    for (int k = threadIdx.x; k < H_; k += 256) {
        float x = src[(size_t)k * E_];
        __nv_bfloat16 h = __float2bfloat16(x);
        g_Wh[n * H_ + k] = h;
        g_Wl[n * H_ + k] = __float2bfloat16(x - __bfloat162float(h));
    }
}

// ---------------------------------------------------------------------------
// proj_mma: C[16384,128] = A @ Bt^T, bf16 hi/lo via mma.sync, double-buffered.
// Buffers: 2 x 64KB; per buffer AH/AL/WH/WL 16KB each (SW128 rows of 128B).
// W via cp.async (pre-split bf16); A via register prefetch + in-loop convert.
// ---------------------------------------------------------------------------
#define OFF_AH 0
#define OFF_AL 16384
#define OFF_WH 32768
#define OFF_WL 49152
#define PBUF   65536
#define PROJ_SMEM (2 * PBUF)

__device__ __forceinline__ void proj_cp_w(uint32_t sb, uint32_t bufoff,
                                          int kt, int tid)
{
#pragma unroll
    for (int l = 0; l < 4; ++l) {      // 1024 16B-chunks: full 128 n-rows
        int idx = tid + l * 256;       // 0..1023
        int row = idx >> 3;            // n 0..127
        int s8  = (idx & 7) << 3;      // k-offset 0..56
        uint32_t so = SW128((uint32_t)(row * 128 + s8 * 2));
        CP16(sb + bufoff + OFF_WH + so, &g_Wh[row * H_ + kt * 64 + s8]);
        CP16(sb + bufoff + OFF_WL + so, &g_Wl[row * H_ + kt * 64 + s8]);
    }
}

__device__ __forceinline__ void proj_load_a(const float* __restrict__ A,
                                            int M0, int kt, int tid, float4* ar)
{
#pragma unroll
    for (int l = 0; l < 8; ++l) {
        int idx = tid + l * 256;
        int row = idx >> 4;
        int c4  = (idx & 15) << 2;
        ar[l] = *reinterpret_cast<const float4*>(
            A + (size_t)(M0 + row) * H_ + kt * 64 + c4);
    }
}

__device__ __forceinline__ void proj_store_a(char* sm, uint32_t bufoff,
                                             int tid, const float4* ar)
{
#pragma unroll
    for (int l = 0; l < 8; ++l) {
        int idx = tid + l * 256;
        int row = idx >> 4;
        int c4  = (idx & 15) << 2;
        float4 a = ar[l];
        float hx = bf16_rt(a.x), hy = bf16_rt(a.y);
        float hz = bf16_rt(a.z), hw = bf16_rt(a.w);
        uint32_t so = SW128((uint32_t)(row * 128 + c4 * 2));
        *reinterpret_cast<uint2*>(sm + bufoff + OFF_AH + so) =
            make_uint2(pack2_hi(a.x, a.y), pack2_hi(a.z, a.w));
        *reinterpret_cast<uint2*>(sm + bufoff + OFF_AL + so) =
            make_uint2(pack2_hi(a.x - hx, a.y - hy), pack2_hi(a.z - hz, a.w - hw));
    }
}

__global__ __launch_bounds__(256) void proj_mma(const float* __restrict__ A)
{
    extern __shared__ char sm[];
    const uint32_t sb = smem_u32(sm);
    const int tid = threadIdx.x;
    const int wid = tid >> 5;
    const int lane = tid & 31;
    const int M0 = blockIdx.x * 128;

    const int wm0 = (wid & 3) * 32;
    const int wn0 = (wid >> 2) * 64;   // 0 -> keys, 64 -> vals

    float acc[2][8][4];
#pragma unroll
    for (int mi = 0; mi < 2; ++mi)
#pragma unroll
        for (int ni = 0; ni < 8; ++ni)
#pragma unroll
            for (int q = 0; q < 4; ++q) acc[mi][ni][q] = 0.f;

    const int lrow = lane & 15;
    const int lchk = lane >> 4;

    float4 areg[8];

    // ---- prologue: fill buf0 (W async + A reg->convert), prefetch kt=1 ----
    proj_cp_w(sb, 0, 0, tid);
    CP_COMMIT;
    proj_load_a(A, M0, 0, tid, areg);
    proj_store_a(sm, 0, tid, areg);
    proj_cp_w(sb, PBUF, 1, tid);
    CP_COMMIT;
    proj_load_a(A, M0, 1, tid, areg);
    CP_WAIT(1);          // W(0) landed
    __syncthreads();

    for (int kt = 0; kt < 16; ++kt) {
        const uint32_t bo = (kt & 1) ? PBUF : 0;

        // ---- MMAs on current buffer ----
#pragma unroll
        for (int ks = 0; ks < 4; ++ks) {
            uint32_t ah[2][4], al[2][4];
#pragma unroll
            for (int mi = 0; mi < 2; ++mi) {
                uint32_t off = SW128((uint32_t)(
                    (wm0 + mi * 16 + lrow) * 128 + (ks * 2 + lchk) * 16));
                LDSM_X4(ah[mi][0], ah[mi][1], ah[mi][2], ah[mi][3],
                        sb + bo + OFF_AH + off);
                LDSM_X4(al[mi][0], al[mi][1], al[mi][2], al[mi][3],
                        sb + bo + OFF_AL + off);
            }
            uint32_t bh[4][4], bl[4][4];
#pragma unroll
            for (int g = 0; g < 4; ++g) {
                uint32_t off = SW128((uint32_t)(
                    (wn0 + g * 16 + lrow) * 128 + (ks * 2 + lchk) * 16));
                LDSM_X4(bh[g][0], bh[g][1], bh[g][2], bh[g][3],
                        sb + bo + OFF_WH + off);
                LDSM_X4(bl[g][0], bl[g][1], bl[g][2], bl[g][3],
                        sb + bo + OFF_WL + off);
            }
#pragma unroll
            for (int mi = 0; mi < 2; ++mi) {
#pragma unroll
                for (int ni = 0; ni < 8; ++ni) {
                    const int g = ni >> 1;
                    const int s = ni & 1;
                    uint32_t b0h = bh[g][s], b1h = bh[g][s + 2];
                    uint32_t b0l = bl[g][s], b1l = bl[g][s + 2];
                    float* d = acc[mi][ni];
                    MMA_BF16(d[0], d[1], d[2], d[3],
                             ah[mi][0], ah[mi][1], ah[mi][2], ah[mi][3], b0h, b1h);
                    MMA_BF16(d[0], d[1], d[2], d[3],
                             al[mi][0], al[mi][1], al[mi][2], al[mi][3], b0h, b1h);
                    MMA_BF16(d[0], d[1], d[2], d[3],
                             ah[mi][0], ah[mi][1], ah[mi][2], ah[mi][3], b0l, b1l);
                }
            }
        }

        // ---- store prefetched A(kt+1) into the other buffer ----
        if (kt < 15)
            proj_store_a(sm, (kt & 1) ? 0 : PBUF, tid, areg);
        __syncthreads();   // all warps done reading buf bo

        if (kt < 14) {
            proj_cp_w(sb, bo, kt + 2, tid);   // W(kt+2) -> freed buffer
            CP_COMMIT;
            proj_load_a(A, M0, kt + 2, tid, areg);
            CP_WAIT(1);    // W(kt+1) landed
        } else {
            CP_WAIT(0);
        }
        __syncthreads();
    }

    // ---- epilogue: acc -> bf16 hi/lo K or V arrays ----
    __nv_bfloat16* outh = (wn0 == 0) ? g_kh : g_vh;
    __nv_bfloat16* outl = (wn0 == 0) ? g_kl : g_vl;
    const int colb = (lane & 3) * 2;
    const int rowb = M0 + wm0 + (lane >> 2);
#pragma unroll
    for (int mi = 0; mi < 2; ++mi) {
#pragma unroll
        for (int ni = 0; ni < 8; ++ni) {
            const int col = ni * 8 + colb;
#pragma unroll
            for (int hq = 0; hq < 2; ++hq) {
                const int r = rowb + mi * 16 + hq * 8;
                float d0 = acc[mi][ni][hq * 2 + 0];
                float d1 = acc[mi][ni][hq * 2 + 1];
                *reinterpret_cast<uint32_t*>(&outh[(size_t)r * E_ + col]) =
                    pack2_hi(d0, d1);
                *reinterpret_cast<uint32_t*>(&outl[(size_t)r * E_ + col]) =
                    pack2_hi(d0 - bf16_rt(d0), d1 - bf16_rt(d1));
            }
        }
    }
}

// ---------------------------------------------------------------------------
// attn_partial (mma.sync, cp.async double-buffered V): one block = (batch,
// 64-row tile, chunk of <=8 j-tiles). 128 threads / 4 warps.
// smem: KH,KL (8KB each) + 2 x (VH,VL) -> 48KB.
// ---------------------------------------------------------------------------
#define AT_KH 0
#define AT_KL 8192
#define AT_V0 16384              // VH at +0, VL at +8192
#define AT_V1 32768
#define ATTN_SMEM_BYTES 49152

__device__ __forceinline__ void attn_cp_kv(uint32_t sb, uint32_t offH,
                                           const __nv_bfloat16* __restrict__ srcH,
                                           const __nv_bfloat16* __restrict__ srcL,
                                           size_t gbase, int tid)
{
#pragma unroll
    for (int l = 0; l < 4; ++l) {
        int idx = tid + l * 128;       // 0..511 16B-chunks (64 rows x 128B)
        int row = idx >> 3;
        int e8  = (idx & 7) << 3;
        uint32_t so = SW128((uint32_t)(row * 128 + e8 * 2));
        CP16(sb + offH + so,        srcH + gbase + (size_t)row * E_ + e8);
        CP16(sb + offH + 8192 + so, srcL + gbase + (size_t)row * E_ + e8);
    }
}

__global__ __launch_bounds__(128) void attn_partial()
{
    extern __shared__ char sm[];
    const uint32_t sb = smem_u32(sm);
    const int tid = threadIdx.x;
    const int wid = tid >> 5;
    const int lane = tid & 31;

    const int b = blockIdx.x / BLK_PER_B;
    int ent = blockIdx.x - b * BLK_PER_B;
    int t = 0, acc0 = 0;
    for (int tt = 0; tt < NT; ++tt) {
        int nc = (NT - tt + CHUNK - 1) / CHUNK;
        if (ent < acc0 + nc) { t = tt; break; }
        acc0 += nc;
    }
    const int chunk = ent - acc0;
    const int j0 = t + chunk * CHUNK;
    const int j1 = min(NT, j0 + CHUNK);

    const int wm0 = wid * 16;
    const int lrow = lane & 15;
    const int lchk = lane >> 4;

    // ---- prologue: K (group 0) + V(j0) (group 1) via cp.async ----
    attn_cp_kv(sb, AT_KH, g_kh, g_kl, ((size_t)b * N_ + t * 64) * E_, tid);
    CP_COMMIT;
    attn_cp_kv(sb, AT_V0, g_vh, g_vl, ((size_t)b * N_ + j0 * 64) * E_, tid);
    CP_COMMIT;

    float m_i[2], l_i[2], accO[8][4];
#pragma unroll
    for (int h = 0; h < 2; ++h) { m_i[h] = -INFINITY; l_i[h] = 0.f; }
#pragma unroll
    for (int ne = 0; ne < 8; ++ne)
#pragma unroll
        for (int q = 0; q < 4; ++q) accO[ne][q] = 0.f;

    for (int jt = j0; jt < j1; ++jt) {
        const uint32_t vb = ((jt - j0) & 1) ? AT_V1 : AT_V0;

        if (jt + 1 < j1) {
            attn_cp_kv(sb, ((jt + 1 - j0) & 1) ? AT_V1 : AT_V0, g_vh, g_vl,
                       ((size_t)b * N_ + (jt + 1) * 64) * E_, tid);
            CP_COMMIT;
            CP_WAIT(1);   // K + V(jt) complete
        } else {
            CP_WAIT(0);
        }
        __syncthreads();

        // ---- S-gemm ----
        float Sa[8][4];
#pragma unroll
        for (int ni = 0; ni < 8; ++ni)
#pragma unroll
            for (int q = 0; q < 4; ++q) Sa[ni][q] = 0.f;

#pragma unroll
        for (int ks = 0; ks < 4; ++ks) {
            uint32_t ah[4], al[4];
            uint32_t offa = SW128((uint32_t)(
                (wm0 + lrow) * 128 + (ks * 2 + lchk) * 16));
            LDSM_X4(ah[0], ah[1], ah[2], ah[3], sb + AT_KH + offa);
            LDSM_X4(al[0], al[1], al[2], al[3], sb + AT_KL + offa);
            uint32_t bh[4][4], bl[4][4];
#pragma unroll
            for (int g = 0; g < 4; ++g) {
                uint32_t offb = SW128((uint32_t)(
                    (g * 16 + lrow) * 128 + (ks * 2 + lchk) * 16));
                LDSM_X4(bh[g][0], bh[g][1], bh[g][2], bh[g][3], sb + vb + offb);
                LDSM_X4(bl[g][0], bl[g][1], bl[g][2], bl[g][3],
                        sb + vb + 8192 + offb);
            }
#pragma unroll
            for (int ni = 0; ni < 8; ++ni) {
                const int g = ni >> 1;
                const int s = ni & 1;
                uint32_t b0h = bh[g][s], b1h = bh[g][s + 2];
                uint32_t b0l = bl[g][s], b1l = bl[g][s + 2];
                float* d = Sa[ni];
                MMA_BF16(d[0], d[1], d[2], d[3], ah[0], ah[1], ah[2], ah[3], b0h, b1h);
                MMA_BF16(d[0], d[1], d[2], d[3], al[0], al[1], al[2], al[3], b0h, b1h);
                MMA_BF16(d[0], d[1], d[2], d[3], ah[0], ah[1], ah[2], ah[3], b0l, b1l);
            }
        }

        // ---- scale + mask ----
        const float sc = 0.125f;
        if (jt == t) {
#pragma unroll
            for (int ni = 0; ni < 8; ++ni)
#pragma unroll
                for (int q = 0; q < 4; ++q) {
                    int i_loc = wm0 + (lane >> 2) + ((q >> 1) << 3);
                    int j_loc = ni * 8 + (lane & 3) * 2 + (q & 1);
                    Sa[ni][q] = (j_loc >= i_loc) ? Sa[ni][q] * sc : -1e30f;
                }
        } else {
#pragma unroll
            for (int ni = 0; ni < 8; ++ni)
#pragma unroll
                for (int q = 0; q < 4; ++q) Sa[ni][q] *= sc;
        }

        // ---- online softmax ----
#pragma unroll
        for (int h = 0; h < 2; ++h) {
            float tmax = -INFINITY;
#pragma unroll
            for (int ni = 0; ni < 8; ++ni)
                tmax = fmaxf(tmax, fmaxf(Sa[ni][h * 2], Sa[ni][h * 2 + 1]));
            tmax = fmaxf(tmax, __shfl_xor_sync(0xffffffffu, tmax, 1));
            tmax = fmaxf(tmax, __shfl_xor_sync(0xffffffffu, tmax, 2));
            float mnew = fmaxf(m_i[h], tmax);
            float alpha = __expf(m_i[h] - mnew);
            float ps = 0.f;
#pragma unroll
            for (int ni = 0; ni < 8; ++ni) {
                float p0 = __expf(Sa[ni][h * 2] - mnew);
                float p1 = __expf(Sa[ni][h * 2 + 1] - mnew);
                Sa[ni][h * 2] = p0;
                Sa[ni][h * 2 + 1] = p1;
                ps += p0 + p1;
            }
            ps += __shfl_xor_sync(0xffffffffu, ps, 1);
            ps += __shfl_xor_sync(0xffffffffu, ps, 2);
            l_i[h] = l_i[h] * alpha + ps;
            m_i[h] = mnew;
#pragma unroll
            for (int ne = 0; ne < 8; ++ne) {
                accO[ne][h * 2] *= alpha;
                accO[ne][h * 2 + 1] *= alpha;
            }
        }

        // ---- O-gemm (V^T fragments via ldmatrix.trans on same V tile) ----
#pragma unroll
        for (int kc = 0; kc < 4; ++kc) {
            const int n0 = 2 * kc, n1 = 2 * kc + 1;
            uint32_t pah[4], pal[4];
            {
                float p00 = Sa[n0][0], p01 = Sa[n0][1];
                float p02 = Sa[n0][2], p03 = Sa[n0][3];
                float p10 = Sa[n1][0], p11 = Sa[n1][1];
                float p12 = Sa[n1][2], p13 = Sa[n1][3];
                pah[0] = pack2_hi(p00, p01);
                pah[1] = pack2_hi(p02, p03);
                pah[2] = pack2_hi(p10, p11);
                pah[3] = pack2_hi(p12, p13);
                pal[0] = pack2_hi(p00 - bf16_rt(p00), p01 - bf16_rt(p01));
                pal[1] = pack2_hi(p02 - bf16_rt(p02), p03 - bf16_rt(p03));
                pal[2] = pack2_hi(p10 - bf16_rt(p10), p11 - bf16_rt(p11));
                pal[3] = pack2_hi(p12 - bf16_rt(p12), p13 - bf16_rt(p13));
            }
            uint32_t tbh[4][4], tbl[4][4];
#pragma unroll
            for (int g = 0; g < 4; ++g) {
                uint32_t offt = SW128((uint32_t)(
                    (kc * 16 + lrow) * 128 + g * 32 + lchk * 16));
                LDSM_X4_T(tbh[g][0], tbh[g][1], tbh[g][2], tbh[g][3],
                          sb + vb + offt);
                LDSM_X4_T(tbl[g][0], tbl[g][1], tbl[g][2], tbl[g][3],
                          sb + vb + 8192 + offt);
            }
#pragma unroll
            for (int ne = 0; ne < 8; ++ne) {
                const int g = ne >> 1;
                const int s = ne & 1;
                uint32_t b0h = tbh[g][2 * s], b1h = tbh[g][2 * s + 1];
                uint32_t b0l = tbl[g][2 * s], b1l = tbl[g][2 * s + 1];
                float* d = accO[ne];
                MMA_BF16(d[0], d[1], d[2], d[3], pah[0], pah[1], pah[2], pah[3], b0h, b1h);
                MMA_BF16(d[0], d[1], d[2], d[3], pal[0], pal[1], pal[2], pal[3], b0h, b1h);
                MMA_BF16(d[0], d[1], d[2], d[3], pah[0], pah[1], pah[2], pah[3], b0l, b1l);
            }
        }
        __syncthreads();   // all warps done with V buffer before re-fill
    }

    // ---- write unnormalized partials ----
    const size_t base = ((size_t)b * NT + t) * MAXC + chunk;
    float* pO = g_pO + base * 4096;
    const int r0 = wm0 + (lane >> 2);
    if ((lane & 3) == 0) {
        g_pm[base * 64 + r0]     = m_i[0];
        g_pm[base * 64 + r0 + 8] = m_i[1];
        g_pl[base * 64 + r0]     = l_i[0];
        g_pl[base * 64 + r0 + 8] = l_i[1];
    }
#pragma unroll
    for (int ne = 0; ne < 8; ++ne) {
        const int e = ne * 8 + (lane & 3) * 2;
        *reinterpret_cast<float2*>(&pO[(size_t)r0 * 64 + e]) =
            make_float2(accO[ne][0], accO[ne][1]);
        *reinterpret_cast<float2*>(&pO[(size_t)(r0 + 8) * 64 + e]) =
            make_float2(accO[ne][2], accO[ne][3]);
    }
}

// ---------------------------------------------------------------------------
// Combine: merge the <=4 chunks of each (b, row-tile), write normalized out.
// ---------------------------------------------------------------------------
__global__ __launch_bounds__(256) void combine_kernel(float* __restrict__ out)
{
    const int t = blockIdx.x >> 3;
    const int b = blockIdx.x & 7;
    const int nc = (NT - t + CHUNK - 1) / CHUNK;
    const int tid = threadIdx.x;
    const int r  = tid >> 2;
    const int e0 = (tid & 3) * 16;

    const size_t base = ((size_t)b * NT + t) * MAXC;

    float m = -INFINITY;
    for (int c = 0; c < nc; ++c)
        m = fmaxf(m, g_pm[(base + c) * 64 + r]);

    float w[MAXC];
    float lsum = 0.f;
    for (int c = 0; c < nc; ++c) {
        float wc = __expf(g_pm[(base + c) * 64 + r] - m);
        w[c] = wc;
        lsum += wc * g_pl[(base + c) * 64 + r];
    }
    const float inv = 1.f / lsum;

    float o[16];
#pragma unroll
    for (int k = 0; k < 16; ++k) o[k] = 0.f;

    for (int c = 0; c < nc; ++c) {
        const float* pO = g_pO + (base + c) * 4096 + (size_t)r * 64 + e0;
        float wc = w[c];
#pragma unroll
        for (int k = 0; k < 16; k += 4) {
            float4 v = *reinterpret_cast<const float4*>(pO + k);
            o[k + 0] = fmaf(wc, v.x, o[k + 0]);
            o[k + 1] = fmaf(wc, v.y, o[k + 1]);
            o[k + 2] = fmaf(wc, v.z, o[k + 2]);
            o[k + 3] = fmaf(wc, v.w, o[k + 3]);
        }
    }

    float* dst = out + ((size_t)b * N_ + t * 64 + r) * E_ + e0;
#pragma unroll
    for (int k = 0; k < 16; k += 4)
        *reinterpret_cast<float4*>(dst + k) =
            make_float4(o[k] * inv, o[k + 1] * inv, o[k + 2] * inv, o[k + 3] * inv);
}

// ---------------------------------------------------------------------------
extern "C" void kernel_launch(void* const* d_in, const int* in_sizes, int n_in,
                              void* d_out, int out_size)
{
    (void)in_sizes; (void)n_in; (void)out_size;
    const float* input = (const float*)d_in[0];
    const float* Wk    = (const float*)d_in[1];
    // d_in[2] is q — dead in the reference, intentionally unused.
    const float* Wv    = (const float*)d_in[3];
    float* out = (float*)d_out;

    cudaFuncSetAttribute(proj_mma,
                         cudaFuncAttributeMaxDynamicSharedMemorySize, PROJ_SMEM);
    cudaFuncSetAttribute(attn_partial,
                         cudaFuncAttributeMaxDynamicSharedMemorySize, ATTN_SMEM_BYTES);

    prep_w<<<128, 256>>>(Wk, Wv);
    proj_mma<<<128, 256, PROJ_SMEM>>>(input);
    attn_partial<<<B_ * BLK_PER_B, 128, ATTN_SMEM_BYTES>>>();
    combine_kernel<<<B_ * NT, 256>>>(out);
}

// round 9
// speedup vs baseline: 4.6701x; 1.3362x over previous
#include <cuda_runtime.h>
#include <cuda_fp16.h>
#include <math.h>
#include <stdint.h>

#define B_ 8
#define N_ 2048
#define H_ 1024
#define E_ 64
#define NT 32            // number of 64-row tiles per batch
#define CHUNK 8          // j-tiles (64 cols each) per partial block
#define MAXC 4           // max chunks per row-tile = ceil(32/8)
#define BLK_PER_B 80     // sum_t ceil((32-t)/8)

// Scratch (no allocation allowed in kernel_launch).
__device__ float g_pO[B_ * NT * MAXC * 64 * 64];
__device__ float g_pm[B_ * NT * MAXC * 64];
__device__ float g_pl[B_ * NT * MAXC * 64];
// K stored as fp16 hi/lo (exact to 2^-22); V needs only fp16 hi (B-side of
// both attention gemms is rounded to fp16 — 2-pass scheme).
__device__ __half g_kh[B_ * N_ * E_];
__device__ __half g_kl[B_ * N_ * E_];
__device__ __half g_vh[B_ * N_ * E_];
// Pre-transposed fp16 weight matrix Bt[n][k] = fp16([Wk|Wv][k][n]).
__device__ __half g_Wh[128 * 1024];

// ---------------------------------------------------------------------------
// Helpers (base-ISA: ldmatrix + mma.sync + cp.async — plain sm_100 target)
// ---------------------------------------------------------------------------
__device__ __forceinline__ uint32_t smem_u32(const void* p) {
    uint32_t a;
    asm("{ .reg .u64 t; cvta.to.shared.u64 t, %1; cvt.u32.u64 %0, t; }"
        : "=r"(a) : "l"(p));
    return a;
}

#define SW128(o) ((o) ^ ((((uint32_t)(o)) >> 3) & 0x70))

#define LDSM_X4(r0, r1, r2, r3, addr) \
    asm volatile("ldmatrix.sync.aligned.m8n8.x4.shared.b16 {%0,%1,%2,%3}, [%4];" \
                 : "=r"(r0), "=r"(r1), "=r"(r2), "=r"(r3) : "r"(addr))

#define LDSM_X4_T(r0, r1, r2, r3, addr) \
    asm volatile("ldmatrix.sync.aligned.m8n8.x4.trans.shared.b16 {%0,%1,%2,%3}, [%4];" \
                 : "=r"(r0), "=r"(r1), "=r"(r2), "=r"(r3) : "r"(addr))

#define MMA_F16(d0, d1, d2, d3, a0, a1, a2, a3, b0, b1) \
    asm volatile("mma.sync.aligned.m16n8k16.row.col.f32.f16.f16.f32 " \
                 "{%0,%1,%2,%3}, {%4,%5,%6,%7}, {%8,%9}, {%0,%1,%2,%3};" \
                 : "+f"(d0), "+f"(d1), "+f"(d2), "+f"(d3) \
                 : "r"(a0), "r"(a1), "r"(a2), "r"(a3), "r"(b0), "r"(b1))

#define CP16(dst, src) \
    asm volatile("cp.async.cg.shared.global [%0], [%1], 16;" \
                 :: "r"(dst), "l"(src) : "memory")
#define CP_COMMIT asm volatile("cp.async.commit_group;" ::: "memory")
#define CP_WAIT(n) asm volatile("cp.async.wait_group %0;" :: "n"(n) : "memory")

__device__ __forceinline__ uint32_t pack2h(float a, float b) {
    __half2 h = __floats2half2_rn(a, b);
    return *reinterpret_cast<uint32_t*>(&h);
}
__device__ __forceinline__ float h_rt(float x) {   // round-trip through fp16
    return __half2float(__float2half_rn(x));
}

// ---------------------------------------------------------------------------
// prep_w: Bt[n][k] = fp16(W[k][n]). n<64 -> Wk, else Wv.
// ---------------------------------------------------------------------------
__global__ __launch_bounds__(256) void prep_w(const float* __restrict__ Wk,
                                              const float* __restrict__ Wv)
{
    const int n = blockIdx.x;
    const float* src = (n < 64) ? (Wk + n) : (Wv + (n - 64));
    for (int k = threadIdx.x; k < H_; k += 256)
        g_Wh[n * H_ + k] = __float2half_rn(src[(size_t)k * E_]);
}

// ---------------------------------------------------------------------------
// proj_mma: C[16384,128] = A @ Bt^T, fp16 hi/lo 2-pass, double-buffered.
// Buffers: 2 x 48KB; per buffer AH/AL/WH 16KB each (SW128 rows of 128B).
// W via cp.async (pre-rounded fp16); A via register prefetch + in-loop split.
// ---------------------------------------------------------------------------
#define OFF_AH 0
#define OFF_AL 16384
#define OFF_WH 32768
#define PBUF   49152
#define PROJ_SMEM (2 * PBUF)

__device__ __forceinline__ void proj_cp_w(uint32_t sb, uint32_t bufoff,
                                          int kt, int tid)
{
#pragma unroll
    for (int l = 0; l < 4; ++l) {      // 1024 16B-chunks: full 128 n-rows
        int idx = tid + l * 256;       // 0..1023
        int row = idx >> 3;            // n 0..127
        int s8  = (idx & 7) << 3;      // k-offset 0..56
        uint32_t so = SW128((uint32_t)(row * 128 + s8 * 2));
        CP16(sb + bufoff + OFF_WH + so, &g_Wh[row * H_ + kt * 64 + s8]);
    }
}

__device__ __forceinline__ void proj_load_a(const float* __restrict__ A,
                                            int M0, int kt, int tid, float4* ar)
{
#pragma unroll
    for (int l = 0; l < 8; ++l) {
        int idx = tid + l * 256;
        int row = idx >> 4;
        int c4  = (idx & 15) << 2;
        ar[l] = *reinterpret_cast<const float4*>(
            A + (size_t)(M0 + row) * H_ + kt * 64 + c4);
    }
}

__device__ __forceinline__ void proj_store_a(char* sm, uint32_t bufoff,
                                             int tid, const float4* ar)
{
#pragma unroll
    for (int l = 0; l < 8; ++l) {
        int idx = tid + l * 256;
        int row = idx >> 4;
        int c4  = (idx & 15) << 2;
        float4 a = ar[l];
        float hx = h_rt(a.x), hy = h_rt(a.y);
        float hz = h_rt(a.z), hw = h_rt(a.w);
        uint32_t so = SW128((uint32_t)(row * 128 + c4 * 2));
        *reinterpret_cast<uint2*>(sm + bufoff + OFF_AH + so) =
            make_uint2(pack2h(a.x, a.y), pack2h(a.z, a.w));
        *reinterpret_cast<uint2*>(sm + bufoff + OFF_AL + so) =
            make_uint2(pack2h(a.x - hx, a.y - hy), pack2h(a.z - hz, a.w - hw));
    }
}

__global__ __launch_bounds__(256) void proj_mma(const float* __restrict__ A)
{
    extern __shared__ char sm[];
    const uint32_t sb = smem_u32(sm);
    const int tid = threadIdx.x;
    const int wid = tid >> 5;
    const int lane = tid & 31;
    const int M0 = blockIdx.x * 128;

    const int wm0 = (wid & 3) * 32;
    const int wn0 = (wid >> 2) * 64;   // 0 -> keys, 64 -> vals

    float acc[2][8][4];
#pragma unroll
    for (int mi = 0; mi < 2; ++mi)
#pragma unroll
        for (int ni = 0; ni < 8; ++ni)
#pragma unroll
            for (int q = 0; q < 4; ++q) acc[mi][ni][q] = 0.f;

    const int lrow = lane & 15;
    const int lchk = lane >> 4;

    float4 areg[8];

    // ---- prologue: fill buf0 (W async + A reg->split), prefetch kt=1 ----
    proj_cp_w(sb, 0, 0, tid);
    CP_COMMIT;
    proj_load_a(A, M0, 0, tid, areg);
    proj_store_a(sm, 0, tid, areg);
    proj_cp_w(sb, PBUF, 1, tid);
    CP_COMMIT;
    proj_load_a(A, M0, 1, tid, areg);
    CP_WAIT(1);          // W(0) landed
    __syncthreads();

    for (int kt = 0; kt < 16; ++kt) {
        const uint32_t bo = (kt & 1) ? PBUF : 0;

        // ---- MMAs on current buffer: acc += Ah*Wh + Al*Wh ----
#pragma unroll
        for (int ks = 0; ks < 4; ++ks) {
            uint32_t ah[2][4], al[2][4];
#pragma unroll
            for (int mi = 0; mi < 2; ++mi) {
                uint32_t off = SW128((uint32_t)(
                    (wm0 + mi * 16 + lrow) * 128 + (ks * 2 + lchk) * 16));
                LDSM_X4(ah[mi][0], ah[mi][1], ah[mi][2], ah[mi][3],
                        sb + bo + OFF_AH + off);
                LDSM_X4(al[mi][0], al[mi][1], al[mi][2], al[mi][3],
                        sb + bo + OFF_AL + off);
            }
            uint32_t bh[4][4];
#pragma unroll
            for (int g = 0; g < 4; ++g) {
                uint32_t off = SW128((uint32_t)(
                    (wn0 + g * 16 + lrow) * 128 + (ks * 2 + lchk) * 16));
                LDSM_X4(bh[g][0], bh[g][1], bh[g][2], bh[g][3],
                        sb + bo + OFF_WH + off);
            }
#pragma unroll
            for (int mi = 0; mi < 2; ++mi) {
#pragma unroll
                for (int ni = 0; ni < 8; ++ni) {
                    const int g = ni >> 1;
                    const int s = ni & 1;
                    uint32_t b0h = bh[g][s], b1h = bh[g][s + 2];
                    float* d = acc[mi][ni];
                    MMA_F16(d[0], d[1], d[2], d[3],
                            ah[mi][0], ah[mi][1], ah[mi][2], ah[mi][3], b0h, b1h);
                    MMA_F16(d[0], d[1], d[2], d[3],
                            al[mi][0], al[mi][1], al[mi][2], al[mi][3], b0h, b1h);
                }
            }
        }

        // ---- store prefetched A(kt+1) into the other buffer ----
        if (kt < 15)
            proj_store_a(sm, (kt & 1) ? 0 : PBUF, tid, areg);
        __syncthreads();   // all warps done reading buf bo

        if (kt < 14) {
            proj_cp_w(sb, bo, kt + 2, tid);   // W(kt+2) -> freed buffer
            CP_COMMIT;
            proj_load_a(A, M0, kt + 2, tid, areg);
            CP_WAIT(1);    // W(kt+1) landed
        } else {
            CP_WAIT(0);
        }
        __syncthreads();
    }

    // ---- epilogue: keys -> fp16 hi+lo; vals -> fp16 hi only ----
    const int colb = (lane & 3) * 2;
    const int rowb = M0 + wm0 + (lane >> 2);
#pragma unroll
    for (int mi = 0; mi < 2; ++mi) {
#pragma unroll
        for (int ni = 0; ni < 8; ++ni) {
            const int col = ni * 8 + colb;
#pragma unroll
            for (int hq = 0; hq < 2; ++hq) {
                const int r = rowb + mi * 16 + hq * 8;
                float d0 = acc[mi][ni][hq * 2 + 0];
                float d1 = acc[mi][ni][hq * 2 + 1];
                if (wn0 == 0) {
                    *reinterpret_cast<uint32_t*>(&g_kh[(size_t)r * E_ + col]) =
                        pack2h(d0, d1);
                    *reinterpret_cast<uint32_t*>(&g_kl[(size_t)r * E_ + col]) =
                        pack2h(d0 - h_rt(d0), d1 - h_rt(d1));
                } else {
                    *reinterpret_cast<uint32_t*>(&g_vh[(size_t)r * E_ + col]) =
                        pack2h(d0, d1);
                }
            }
        }
    }
}

// ---------------------------------------------------------------------------
// attn_partial (mma.sync fp16 2-pass, cp.async double-buffered V): one block
// = (batch, 64-row tile, chunk of <=8 j-tiles). 128 threads / 4 warps.
// S = (Kh+Kl) . Vh ;  O = (Ph+Pl) . Vh^T  (V rounded to fp16: 2-pass scheme)
// smem: KH,KL (8KB each) + 2 x VH (8KB) -> 32KB.
// ---------------------------------------------------------------------------
#define AT_KH 0
#define AT_KL 8192
#define AT_V0 16384
#define AT_V1 24576
#define ATTN_SMEM_BYTES 32768

__device__ __forceinline__ void attn_cp_k(uint32_t sb, size_t gbase, int tid)
{
#pragma unroll
    for (int l = 0; l < 4; ++l) {
        int idx = tid + l * 128;       // 0..511 16B-chunks (64 rows x 128B)
        int row = idx >> 3;
        int e8  = (idx & 7) << 3;
        uint32_t so = SW128((uint32_t)(row * 128 + e8 * 2));
        CP16(sb + AT_KH + so, g_kh + gbase + (size_t)row * E_ + e8);
        CP16(sb + AT_KL + so, g_kl + gbase + (size_t)row * E_ + e8);
    }
}

__device__ __forceinline__ void attn_cp_v(uint32_t sb, uint32_t voff,
                                          size_t gbase, int tid)
{
#pragma unroll
    for (int l = 0; l < 4; ++l) {
        int idx = tid + l * 128;
        int row = idx >> 3;
        int e8  = (idx & 7) << 3;
        uint32_t so = SW128((uint32_t)(row * 128 + e8 * 2));
        CP16(sb + voff + so, g_vh + gbase + (size_t)row * E_ + e8);
    }
}

__global__ __launch_bounds__(128) void attn_partial()
{
    extern __shared__ char sm[];
    const uint32_t sb = smem_u32(sm);
    const int tid = threadIdx.x;
    const int wid = tid >> 5;
    const int lane = tid & 31;

    const int b = blockIdx.x / BLK_PER_B;
    int ent = blockIdx.x - b * BLK_PER_B;
    int t = 0, acc0 = 0;
    for (int tt = 0; tt < NT; ++tt) {
        int nc = (NT - tt + CHUNK - 1) / CHUNK;
        if (ent < acc0 + nc) { t = tt; break; }
        acc0 += nc;
    }
    const int chunk = ent - acc0;
    const int j0 = t + chunk * CHUNK;
    const int j1 = min(NT, j0 + CHUNK);

    const int wm0 = wid * 16;
    const int lrow = lane & 15;
    const int lchk = lane >> 4;

    // ---- prologue: K (group 0) + V(j0) (group 1) via cp.async ----
    attn_cp_k(sb, ((size_t)b * N_ + t * 64) * E_, tid);
    CP_COMMIT;
    attn_cp_v(sb, AT_V0, ((size_t)b * N_ + j0 * 64) * E_, tid);
    CP_COMMIT;

    float m_i[2], l_i[2], accO[8][4];
#pragma unroll
    for (int h = 0; h < 2; ++h) { m_i[h] = -INFINITY; l_i[h] = 0.f; }
#pragma unroll
    for (int ne = 0; ne < 8; ++ne)
#pragma unroll
        for (int q = 0; q < 4; ++q) accO[ne][q] = 0.f;

    for (int jt = j0; jt < j1; ++jt) {
        const uint32_t vb = ((jt - j0) & 1) ? AT_V1 : AT_V0;

        if (jt + 1 < j1) {
            attn_cp_v(sb, ((jt + 1 - j0) & 1) ? AT_V1 : AT_V0,
                      ((size_t)b * N_ + (jt + 1) * 64) * E_, tid);
            CP_COMMIT;
            CP_WAIT(1);   // K + V(jt) complete
        } else {
            CP_WAIT(0);
        }
        __syncthreads();

        // ---- S-gemm: S = Kh.Vh + Kl.Vh ----
        float Sa[8][4];
#pragma unroll
        for (int ni = 0; ni < 8; ++ni)
#pragma unroll
            for (int q = 0; q < 4; ++q) Sa[ni][q] = 0.f;

#pragma unroll
        for (int ks = 0; ks < 4; ++ks) {
            uint32_t ah[4], al[4];
            uint32_t offa = SW128((uint32_t)(
                (wm0 + lrow) * 128 + (ks * 2 + lchk) * 16));
            LDSM_X4(ah[0], ah[1], ah[2], ah[3], sb + AT_KH + offa);
            LDSM_X4(al[0], al[1], al[2], al[3], sb + AT_KL + offa);
            uint32_t bh[4][4];
#pragma unroll
            for (int g = 0; g < 4; ++g) {
                uint32_t offb = SW128((uint32_t)(
                    (g * 16 + lrow) * 128 + (ks * 2 + lchk) * 16));
                LDSM_X4(bh[g][0], bh[g][1], bh[g][2], bh[g][3], sb + vb + offb);
            }
#pragma unroll
            for (int ni = 0; ni < 8; ++ni) {
                const int g = ni >> 1;
                const int s = ni & 1;
                uint32_t b0h = bh[g][s], b1h = bh[g][s + 2];
                float* d = Sa[ni];
                MMA_F16(d[0], d[1], d[2], d[3], ah[0], ah[1], ah[2], ah[3], b0h, b1h);
                MMA_F16(d[0], d[1], d[2], d[3], al[0], al[1], al[2], al[3], b0h, b1h);
            }
        }

        // ---- scale + mask ----
        const float sc = 0.125f;
        if (jt == t) {
#pragma unroll
            for (int ni = 0; ni < 8; ++ni)
#pragma unroll
                for (int q = 0; q < 4; ++q) {
                    int i_loc = wm0 + (lane >> 2) + ((q >> 1) << 3);
                    int j_loc = ni * 8 + (lane & 3) * 2 + (q & 1);
                    Sa[ni][q] = (j_loc >= i_loc) ? Sa[ni][q] * sc : -1e30f;
                }
        } else {
#pragma unroll
            for (int ni = 0; ni < 8; ++ni)
#pragma unroll
                for (int q = 0; q < 4; ++q) Sa[ni][q] *= sc;
        }

        // ---- online softmax ----
#pragma unroll
        for (int h = 0; h < 2; ++h) {
            float tmax = -INFINITY;
#pragma unroll
            for (int ni = 0; ni < 8; ++ni)
                tmax = fmaxf(tmax, fmaxf(Sa[ni][h * 2], Sa[ni][h * 2 + 1]));
            tmax = fmaxf(tmax, __shfl_xor_sync(0xffffffffu, tmax, 1));
            tmax = fmaxf(tmax, __shfl_xor_sync(0xffffffffu, tmax, 2));
            float mnew = fmaxf(m_i[h], tmax);
            float alpha = __expf(m_i[h] - mnew);
            float ps = 0.f;
#pragma unroll
            for (int ni = 0; ni < 8; ++ni) {
                float p0 = __expf(Sa[ni][h * 2] - mnew);
                float p1 = __expf(Sa[ni][h * 2 + 1] - mnew);
                Sa[ni][h * 2] = p0;
                Sa[ni][h * 2 + 1] = p1;
                ps += p0 + p1;
            }
            ps += __shfl_xor_sync(0xffffffffu, ps, 1);
            ps += __shfl_xor_sync(0xffffffffu, ps, 2);
            l_i[h] = l_i[h] * alpha + ps;
            m_i[h] = mnew;
#pragma unroll
            for (int ne = 0; ne < 8; ++ne) {
                accO[ne][h * 2] *= alpha;
                accO[ne][h * 2 + 1] *= alpha;
            }
        }

        // ---- O-gemm: accO += (Ph+Pl) @ Vh (trans fragments on same tile) ----
#pragma unroll
        for (int kc = 0; kc < 4; ++kc) {
            const int n0 = 2 * kc, n1 = 2 * kc + 1;
            uint32_t pah[4], pal[4];
            {
                float p00 = Sa[n0][0], p01 = Sa[n0][1];
                float p02 = Sa[n0][2], p03 = Sa[n0][3];
                float p10 = Sa[n1][0], p11 = Sa[n1][1];
                float p12 = Sa[n1][2], p13 = Sa[n1][3];
                pah[0] = pack2h(p00, p01);
                pah[1] = pack2h(p02, p03);
                pah[2] = pack2h(p10, p11);
                pah[3] = pack2h(p12, p13);
                pal[0] = pack2h(p00 - h_rt(p00), p01 - h_rt(p01));
                pal[1] = pack2h(p02 - h_rt(p02), p03 - h_rt(p03));
                pal[2] = pack2h(p10 - h_rt(p10), p11 - h_rt(p11));
                pal[3] = pack2h(p12 - h_rt(p12), p13 - h_rt(p13));
            }
            uint32_t tbh[4][4];
#pragma unroll
            for (int g = 0; g < 4; ++g) {
                uint32_t offt = SW128((uint32_t)(
                    (kc * 16 + lrow) * 128 + g * 32 + lchk * 16));
                LDSM_X4_T(tbh[g][0], tbh[g][1], tbh[g][2], tbh[g][3],
                          sb + vb + offt);
            }
#pragma unroll
            for (int ne = 0; ne < 8; ++ne) {
                const int g = ne >> 1;
                const int s = ne & 1;
                uint32_t b0h = tbh[g][2 * s], b1h = tbh[g][2 * s + 1];
                float* d = accO[ne];
                MMA_F16(d[0], d[1], d[2], d[3], pah[0], pah[1], pah[2], pah[3], b0h, b1h);
                MMA_F16(d[0], d[1], d[2], d[3], pal[0], pal[1], pal[2], pal[3], b0h, b1h);
            }
        }
        __syncthreads();   // all warps done with V buffer before re-fill
    }

    // ---- write unnormalized partials ----
    const size_t base = ((size_t)b * NT + t) * MAXC + chunk;
    float* pO = g_pO + base * 4096;
    const int r0 = wm0 + (lane >> 2);
    if ((lane & 3) == 0) {
        g_pm[base * 64 + r0]     = m_i[0];
        g_pm[base * 64 + r0 + 8] = m_i[1];
        g_pl[base * 64 + r0]     = l_i[0];
        g_pl[base * 64 + r0 + 8] = l_i[1];
    }
#pragma unroll
    for (int ne = 0; ne < 8; ++ne) {
        const int e = ne * 8 + (lane & 3) * 2;
        *reinterpret_cast<float2*>(&pO[(size_t)r0 * 64 + e]) =
            make_float2(accO[ne][0], accO[ne][1]);
        *reinterpret_cast<float2*>(&pO[(size_t)(r0 + 8) * 64 + e]) =
            make_float2(accO[ne][2], accO[ne][3]);
    }
}

// ---------------------------------------------------------------------------
// Combine: merge the <=4 chunks of each (b, row-tile). 512 blocks (e-range
// split in half per block) for latency hiding.
// ---------------------------------------------------------------------------
__global__ __launch_bounds__(256) void combine_kernel(float* __restrict__ out)
{
    const int half = blockIdx.x & 1;
    const int bt = blockIdx.x >> 1;
    const int t = bt >> 3;
    const int b = bt & 7;
    const int nc = (NT - t + CHUNK - 1) / CHUNK;
    const int tid = threadIdx.x;
    const int r  = tid >> 2;
    const int e0 = half * 32 + (tid & 3) * 8;

    const size_t base = ((size_t)b * NT + t) * MAXC;

    float m = -INFINITY;
    for (int c = 0; c < nc; ++c)
        m = fmaxf(m, g_pm[(base + c) * 64 + r]);

    float w[MAXC];
    float lsum = 0.f;
    for (int c = 0; c < nc; ++c) {
        float wc = __expf(g_pm[(base + c) * 64 + r] - m);
        w[c] = wc;
        lsum += wc * g_pl[(base + c) * 64 + r];
    }
    const float inv = 1.f / lsum;

    float o[8];
#pragma unroll
    for (int k = 0; k < 8; ++k) o[k] = 0.f;

    for (int c = 0; c < nc; ++c) {
        const float* pO = g_pO + (base + c) * 4096 + (size_t)r * 64 + e0;
        float wc = w[c];
#pragma unroll
        for (int k = 0; k < 8; k += 4) {
            float4 v = *reinterpret_cast<const float4*>(pO + k);
            o[k + 0] = fmaf(wc, v.x, o[k + 0]);
            o[k + 1] = fmaf(wc, v.y, o[k + 1]);
            o[k + 2] = fmaf(wc, v.z, o[k + 2]);
            o[k + 3] = fmaf(wc, v.w, o[k + 3]);
        }
    }

    float* dst = out + ((size_t)b * N_ + t * 64 + r) * E_ + e0;
#pragma unroll
    for (int k = 0; k < 8; k += 4)
        *reinterpret_cast<float4*>(dst + k) =
            make_float4(o[k] * inv, o[k + 1] * inv, o[k + 2] * inv, o[k + 3] * inv);
}

// ---------------------------------------------------------------------------
extern "C" void kernel_launch(void* const* d_in, const int* in_sizes, int n_in,
                              void* d_out, int out_size)
{
    (void)in_sizes; (void)n_in; (void)out_size;
    const float* input = (const float*)d_in[0];
    const float* Wk    = (const float*)d_in[1];
    // d_in[2] is q — dead in the reference, intentionally unused.
    const float* Wv    = (const float*)d_in[3];
    float* out = (float*)d_out;

    cudaFuncSetAttribute(proj_mma,
                         cudaFuncAttributeMaxDynamicSharedMemorySize, PROJ_SMEM);
    cudaFuncSetAttribute(attn_partial,
                         cudaFuncAttributeMaxDynamicSharedMemorySize, ATTN_SMEM_BYTES);

    prep_w<<<128, 256>>>(Wk, Wv);
    proj_mma<<<128, 256, PROJ_SMEM>>>(input);
    attn_partial<<<B_ * BLK_PER_B, 128, ATTN_SMEM_BYTES>>>();
    combine_kernel<<<B_ * NT * 2, 256>>>(out);
}

// round 10
// speedup vs baseline: 5.5950x; 1.1980x over previous
#include <cuda_runtime.h>
#include <cuda_fp16.h>
#include <math.h>
#include <stdint.h>

#define B_ 8
#define N_ 2048
#define H_ 1024
#define E_ 64
#define NT 32            // number of 64-row tiles per batch
#define CHUNK 8          // j-tiles (64 cols each) per partial block
#define MAXC 4           // max chunks per row-tile = ceil(32/8)
#define BLK_PER_B 80     // sum_t ceil((32-t)/8)

// Scratch (no allocation allowed in kernel_launch).
__device__ float g_pO[B_ * NT * MAXC * 64 * 64];
__device__ float g_pm[B_ * NT * MAXC * 64];
__device__ float g_pl[B_ * NT * MAXC * 64];
// K stored as fp16 hi/lo (2-pass S-gemm); V fp16 hi only.
__device__ __half g_kh[B_ * N_ * E_];
__device__ __half g_kl[B_ * N_ * E_];
__device__ __half g_vh[B_ * N_ * E_];
// Pre-transposed fp16 weight matrix Bt[n][k] = fp16([Wk|Wv][k][n]).
__device__ __half g_Wh[128 * 1024];

// ---------------------------------------------------------------------------
// Helpers (base-ISA: ldmatrix + mma.sync + cp.async — plain sm_100 target)
// ---------------------------------------------------------------------------
__device__ __forceinline__ uint32_t smem_u32(const void* p) {
    uint32_t a;
    asm("{ .reg .u64 t; cvta.to.shared.u64 t, %1; cvt.u32.u64 %0, t; }"
        : "=r"(a) : "l"(p));
    return a;
}

#define SW128(o) ((o) ^ ((((uint32_t)(o)) >> 3) & 0x70))

#define LDSM_X4(r0, r1, r2, r3, addr) \
    asm volatile("ldmatrix.sync.aligned.m8n8.x4.shared.b16 {%0,%1,%2,%3}, [%4];" \
                 : "=r"(r0), "=r"(r1), "=r"(r2), "=r"(r3) : "r"(addr))

#define LDSM_X4_T(r0, r1, r2, r3, addr) \
    asm volatile("ldmatrix.sync.aligned.m8n8.x4.trans.shared.b16 {%0,%1,%2,%3}, [%4];" \
                 : "=r"(r0), "=r"(r1), "=r"(r2), "=r"(r3) : "r"(addr))

#define MMA_F16(d0, d1, d2, d3, a0, a1, a2, a3, b0, b1) \
    asm volatile("mma.sync.aligned.m16n8k16.row.col.f32.f16.f16.f32 " \
                 "{%0,%1,%2,%3}, {%4,%5,%6,%7}, {%8,%9}, {%0,%1,%2,%3};" \
                 : "+f"(d0), "+f"(d1), "+f"(d2), "+f"(d3) \
                 : "r"(a0), "r"(a1), "r"(a2), "r"(a3), "r"(b0), "r"(b1))

#define CP16(dst, src) \
    asm volatile("cp.async.cg.shared.global [%0], [%1], 16;" \
                 :: "r"(dst), "l"(src) : "memory")
#define CP_COMMIT asm volatile("cp.async.commit_group;" ::: "memory")
#define CP_WAIT(n) asm volatile("cp.async.wait_group %0;" :: "n"(n) : "memory")

__device__ __forceinline__ uint32_t pack2h(float a, float b) {
    __half2 h = __floats2half2_rn(a, b);
    return *reinterpret_cast<uint32_t*>(&h);
}
__device__ __forceinline__ float h_rt(float x) {   // round-trip through fp16
    return __half2float(__float2half_rn(x));
}

// ---------------------------------------------------------------------------
// prep_w: Bt[n][k] = fp16(W[k][n]). n<64 -> Wk, else Wv.
// ---------------------------------------------------------------------------
__global__ __launch_bounds__(256) void prep_w(const float* __restrict__ Wk,
                                              const float* __restrict__ Wv)
{
    const int n = blockIdx.x;
    const float* src = (n < 64) ? (Wk + n) : (Wv + (n - 64));
    for (int k = threadIdx.x; k < H_; k += 256)
        g_Wh[n * H_ + k] = __float2half_rn(src[(size_t)k * E_]);
}

// ---------------------------------------------------------------------------
// proj_mma: C[16384,128] = A @ Bt^T, single-pass fp16 (A and W both rounded;
// their independent ~2^-12 roundings add only sqrt(2)x vs W-only rounding).
// Double-buffered: 2 x 32KB (AH, WH 16KB each, SW128 rows of 128B).
// ---------------------------------------------------------------------------
#define OFF_AH 0
#define OFF_WH 16384
#define PBUF   32768
#define PROJ_SMEM (2 * PBUF)

__device__ __forceinline__ void proj_cp_w(uint32_t sb, uint32_t bufoff,
                                          int kt, int tid)
{
#pragma unroll
    for (int l = 0; l < 4; ++l) {      // 1024 16B-chunks: full 128 n-rows
        int idx = tid + l * 256;       // 0..1023
        int row = idx >> 3;            // n 0..127
        int s8  = (idx & 7) << 3;      // k-offset 0..56
        uint32_t so = SW128((uint32_t)(row * 128 + s8 * 2));
        CP16(sb + bufoff + OFF_WH + so, &g_Wh[row * H_ + kt * 64 + s8]);
    }
}

__device__ __forceinline__ void proj_load_a(const float* __restrict__ A,
                                            int M0, int kt, int tid, float4* ar)
{
#pragma unroll
    for (int l = 0; l < 8; ++l) {
        int idx = tid + l * 256;
        int row = idx >> 4;
        int c4  = (idx & 15) << 2;
        ar[l] = *reinterpret_cast<const float4*>(
            A + (size_t)(M0 + row) * H_ + kt * 64 + c4);
    }
}

__device__ __forceinline__ void proj_store_a(char* sm, uint32_t bufoff,
                                             int tid, const float4* ar)
{
#pragma unroll
    for (int l = 0; l < 8; ++l) {
        int idx = tid + l * 256;
        int row = idx >> 4;
        int c4  = (idx & 15) << 2;
        float4 a = ar[l];
        uint32_t so = SW128((uint32_t)(row * 128 + c4 * 2));
        *reinterpret_cast<uint2*>(sm + bufoff + OFF_AH + so) =
            make_uint2(pack2h(a.x, a.y), pack2h(a.z, a.w));
    }
}

__global__ __launch_bounds__(256) void proj_mma(const float* __restrict__ A)
{
    extern __shared__ char sm[];
    const uint32_t sb = smem_u32(sm);
    const int tid = threadIdx.x;
    const int wid = tid >> 5;
    const int lane = tid & 31;
    const int M0 = blockIdx.x * 128;

    const int wm0 = (wid & 3) * 32;
    const int wn0 = (wid >> 2) * 64;   // 0 -> keys, 64 -> vals

    float acc[2][8][4];
#pragma unroll
    for (int mi = 0; mi < 2; ++mi)
#pragma unroll
        for (int ni = 0; ni < 8; ++ni)
#pragma unroll
            for (int q = 0; q < 4; ++q) acc[mi][ni][q] = 0.f;

    const int lrow = lane & 15;
    const int lchk = lane >> 4;

    float4 areg[8];

    // ---- prologue: fill buf0 (W async + A reg->fp16), prefetch kt=1 ----
    proj_cp_w(sb, 0, 0, tid);
    CP_COMMIT;
    proj_load_a(A, M0, 0, tid, areg);
    proj_store_a(sm, 0, tid, areg);
    proj_cp_w(sb, PBUF, 1, tid);
    CP_COMMIT;
    proj_load_a(A, M0, 1, tid, areg);
    CP_WAIT(1);          // W(0) landed
    __syncthreads();

    for (int kt = 0; kt < 16; ++kt) {
        const uint32_t bo = (kt & 1) ? PBUF : 0;

        // ---- MMAs on current buffer: acc += Ah*Wh ----
#pragma unroll
        for (int ks = 0; ks < 4; ++ks) {
            uint32_t ah[2][4];
#pragma unroll
            for (int mi = 0; mi < 2; ++mi) {
                uint32_t off = SW128((uint32_t)(
                    (wm0 + mi * 16 + lrow) * 128 + (ks * 2 + lchk) * 16));
                LDSM_X4(ah[mi][0], ah[mi][1], ah[mi][2], ah[mi][3],
                        sb + bo + OFF_AH + off);
            }
            uint32_t bh[4][4];
#pragma unroll
            for (int g = 0; g < 4; ++g) {
                uint32_t off = SW128((uint32_t)(
                    (wn0 + g * 16 + lrow) * 128 + (ks * 2 + lchk) * 16));
                LDSM_X4(bh[g][0], bh[g][1], bh[g][2], bh[g][3],
                        sb + bo + OFF_WH + off);
            }
#pragma unroll
            for (int mi = 0; mi < 2; ++mi) {
#pragma unroll
                for (int ni = 0; ni < 8; ++ni) {
                    const int g = ni >> 1;
                    const int s = ni & 1;
                    float* d = acc[mi][ni];
                    MMA_F16(d[0], d[1], d[2], d[3],
                            ah[mi][0], ah[mi][1], ah[mi][2], ah[mi][3],
                            bh[g][s], bh[g][s + 2]);
                }
            }
        }

        // ---- store prefetched A(kt+1) into the other buffer ----
        if (kt < 15)
            proj_store_a(sm, (kt & 1) ? 0 : PBUF, tid, areg);
        __syncthreads();   // all warps done reading buf bo

        if (kt < 14) {
            proj_cp_w(sb, bo, kt + 2, tid);   // W(kt+2) -> freed buffer
            CP_COMMIT;
            proj_load_a(A, M0, kt + 2, tid, areg);
            CP_WAIT(1);    // W(kt+1) landed
        } else {
            CP_WAIT(0);
        }
        __syncthreads();
    }

    // ---- epilogue: keys -> fp16 hi+lo; vals -> fp16 hi only ----
    const int colb = (lane & 3) * 2;
    const int rowb = M0 + wm0 + (lane >> 2);
#pragma unroll
    for (int mi = 0; mi < 2; ++mi) {
#pragma unroll
        for (int ni = 0; ni < 8; ++ni) {
            const int col = ni * 8 + colb;
#pragma unroll
            for (int hq = 0; hq < 2; ++hq) {
                const int r = rowb + mi * 16 + hq * 8;
                float d0 = acc[mi][ni][hq * 2 + 0];
                float d1 = acc[mi][ni][hq * 2 + 1];
                if (wn0 == 0) {
                    *reinterpret_cast<uint32_t*>(&g_kh[(size_t)r * E_ + col]) =
                        pack2h(d0, d1);
                    *reinterpret_cast<uint32_t*>(&g_kl[(size_t)r * E_ + col]) =
                        pack2h(d0 - h_rt(d0), d1 - h_rt(d1));
                } else {
                    *reinterpret_cast<uint32_t*>(&g_vh[(size_t)r * E_ + col]) =
                        pack2h(d0, d1);
                }
            }
        }
    }
}

// ---------------------------------------------------------------------------
// attn_partial (mma.sync fp16 2-pass, cp.async double-buffered V): one block
// = (batch, 64-row tile, chunk of <=8 j-tiles). 128 threads / 4 warps.
// S = (Kh+Kl) . Vh ;  O = (Ph+Pl) . Vh^T
// smem: KH,KL (8KB each) + 2 x VH (8KB) -> 32KB.
// ---------------------------------------------------------------------------
#define AT_KH 0
#define AT_KL 8192
#define AT_V0 16384
#define AT_V1 24576
#define ATTN_SMEM_BYTES 32768

__device__ __forceinline__ void attn_cp_k(uint32_t sb, size_t gbase, int tid)
{
#pragma unroll
    for (int l = 0; l < 4; ++l) {
        int idx = tid + l * 128;       // 0..511 16B-chunks (64 rows x 128B)
        int row = idx >> 3;
        int e8  = (idx & 7) << 3;
        uint32_t so = SW128((uint32_t)(row * 128 + e8 * 2));
        CP16(sb + AT_KH + so, g_kh + gbase + (size_t)row * E_ + e8);
        CP16(sb + AT_KL + so, g_kl + gbase + (size_t)row * E_ + e8);
    }
}

__device__ __forceinline__ void attn_cp_v(uint32_t sb, uint32_t voff,
                                          size_t gbase, int tid)
{
#pragma unroll
    for (int l = 0; l < 4; ++l) {
        int idx = tid + l * 128;
        int row = idx >> 3;
        int e8  = (idx & 7) << 3;
        uint32_t so = SW128((uint32_t)(row * 128 + e8 * 2));
        CP16(sb + voff + so, g_vh + gbase + (size_t)row * E_ + e8);
    }
}

__global__ __launch_bounds__(128) void attn_partial()
{
    extern __shared__ char sm[];
    const uint32_t sb = smem_u32(sm);
    const int tid = threadIdx.x;
    const int wid = tid >> 5;
    const int lane = tid & 31;

    const int b = blockIdx.x / BLK_PER_B;
    int ent = blockIdx.x - b * BLK_PER_B;
    int t = 0, acc0 = 0;
    for (int tt = 0; tt < NT; ++tt) {
        int nc = (NT - tt + CHUNK - 1) / CHUNK;
        if (ent < acc0 + nc) { t = tt; break; }
        acc0 += nc;
    }
    const int chunk = ent - acc0;
    const int j0 = t + chunk * CHUNK;
    const int j1 = min(NT, j0 + CHUNK);

    const int wm0 = wid * 16;
    const int lrow = lane & 15;
    const int lchk = lane >> 4;

    // ---- prologue: K (group 0) + V(j0) (group 1) via cp.async ----
    attn_cp_k(sb, ((size_t)b * N_ + t * 64) * E_, tid);
    CP_COMMIT;
    attn_cp_v(sb, AT_V0, ((size_t)b * N_ + j0 * 64) * E_, tid);
    CP_COMMIT;

    float m_i[2], l_i[2], accO[8][4];
#pragma unroll
    for (int h = 0; h < 2; ++h) { m_i[h] = -INFINITY; l_i[h] = 0.f; }
#pragma unroll
    for (int ne = 0; ne < 8; ++ne)
#pragma unroll
        for (int q = 0; q < 4; ++q) accO[ne][q] = 0.f;

    for (int jt = j0; jt < j1; ++jt) {
        const uint32_t vb = ((jt - j0) & 1) ? AT_V1 : AT_V0;

        if (jt + 1 < j1) {
            attn_cp_v(sb, ((jt + 1 - j0) & 1) ? AT_V1 : AT_V0,
                      ((size_t)b * N_ + (jt + 1) * 64) * E_, tid);
            CP_COMMIT;
            CP_WAIT(1);   // K + V(jt) complete
        } else {
            CP_WAIT(0);
        }
        __syncthreads();

        // ---- S-gemm: S = Kh.Vh + Kl.Vh ----
        float Sa[8][4];
#pragma unroll
        for (int ni = 0; ni < 8; ++ni)
#pragma unroll
            for (int q = 0; q < 4; ++q) Sa[ni][q] = 0.f;

#pragma unroll
        for (int ks = 0; ks < 4; ++ks) {
            uint32_t ah[4], al[4];
            uint32_t offa = SW128((uint32_t)(
                (wm0 + lrow) * 128 + (ks * 2 + lchk) * 16));
            LDSM_X4(ah[0], ah[1], ah[2], ah[3], sb + AT_KH + offa);
            LDSM_X4(al[0], al[1], al[2], al[3], sb + AT_KL + offa);
            uint32_t bh[4][4];
#pragma unroll
            for (int g = 0; g < 4; ++g) {
                uint32_t offb = SW128((uint32_t)(
                    (g * 16 + lrow) * 128 + (ks * 2 + lchk) * 16));
                LDSM_X4(bh[g][0], bh[g][1], bh[g][2], bh[g][3], sb + vb + offb);
            }
#pragma unroll
            for (int ni = 0; ni < 8; ++ni) {
                const int g = ni >> 1;
                const int s = ni & 1;
                uint32_t b0h = bh[g][s], b1h = bh[g][s + 2];
                float* d = Sa[ni];
                MMA_F16(d[0], d[1], d[2], d[3], ah[0], ah[1], ah[2], ah[3], b0h, b1h);
                MMA_F16(d[0], d[1], d[2], d[3], al[0], al[1], al[2], al[3], b0h, b1h);
            }
        }

        // ---- scale + mask ----
        const float sc = 0.125f;
        if (jt == t) {
#pragma unroll
            for (int ni = 0; ni < 8; ++ni)
#pragma unroll
                for (int q = 0; q < 4; ++q) {
                    int i_loc = wm0 + (lane >> 2) + ((q >> 1) << 3);
                    int j_loc = ni * 8 + (lane & 3) * 2 + (q & 1);
                    Sa[ni][q] = (j_loc >= i_loc) ? Sa[ni][q] * sc : -1e30f;
                }
        } else {
#pragma unroll
            for (int ni = 0; ni < 8; ++ni)
#pragma unroll
                for (int q = 0; q < 4; ++q) Sa[ni][q] *= sc;
        }

        // ---- online softmax ----
#pragma unroll
        for (int h = 0; h < 2; ++h) {
            float tmax = -INFINITY;
#pragma unroll
            for (int ni = 0; ni < 8; ++ni)
                tmax = fmaxf(tmax, fmaxf(Sa[ni][h * 2], Sa[ni][h * 2 + 1]));
            tmax = fmaxf(tmax, __shfl_xor_sync(0xffffffffu, tmax, 1));
            tmax = fmaxf(tmax, __shfl_xor_sync(0xffffffffu, tmax, 2));
            float mnew = fmaxf(m_i[h], tmax);
            float alpha = __expf(m_i[h] - mnew);
            float ps = 0.f;
#pragma unroll
            for (int ni = 0; ni < 8; ++ni) {
                float p0 = __expf(Sa[ni][h * 2] - mnew);
                float p1 = __expf(Sa[ni][h * 2 + 1] - mnew);
                Sa[ni][h * 2] = p0;
                Sa[ni][h * 2 + 1] = p1;
                ps += p0 + p1;
            }
            ps += __shfl_xor_sync(0xffffffffu, ps, 1);
            ps += __shfl_xor_sync(0xffffffffu, ps, 2);
            l_i[h] = l_i[h] * alpha + ps;
            m_i[h] = mnew;
#pragma unroll
            for (int ne = 0; ne < 8; ++ne) {
                accO[ne][h * 2] *= alpha;
                accO[ne][h * 2 + 1] *= alpha;
            }
        }

        // ---- O-gemm: accO += (Ph+Pl) @ Vh (trans fragments on same tile) ----
#pragma unroll
        for (int kc = 0; kc < 4; ++kc) {
            const int n0 = 2 * kc, n1 = 2 * kc + 1;
            uint32_t pah[4], pal[4];
            {
                float p00 = Sa[n0][0], p01 = Sa[n0][1];
                float p02 = Sa[n0][2], p03 = Sa[n0][3];
                float p10 = Sa[n1][0], p11 = Sa[n1][1];
                float p12 = Sa[n1][2], p13 = Sa[n1][3];
                pah[0] = pack2h(p00, p01);
                pah[1] = pack2h(p02, p03);
                pah[2] = pack2h(p10, p11);
                pah[3] = pack2h(p12, p13);
                pal[0] = pack2h(p00 - h_rt(p00), p01 - h_rt(p01));
                pal[1] = pack2h(p02 - h_rt(p02), p03 - h_rt(p03));
                pal[2] = pack2h(p10 - h_rt(p10), p11 - h_rt(p11));
                pal[3] = pack2h(p12 - h_rt(p12), p13 - h_rt(p13));
            }
            uint32_t tbh[4][4];
#pragma unroll
            for (int g = 0; g < 4; ++g) {
                uint32_t offt = SW128((uint32_t)(
                    (kc * 16 + lrow) * 128 + g * 32 + lchk * 16));
                LDSM_X4_T(tbh[g][0], tbh[g][1], tbh[g][2], tbh[g][3],
                          sb + vb + offt);
            }
#pragma unroll
            for (int ne = 0; ne < 8; ++ne) {
                const int g = ne >> 1;
                const int s = ne & 1;
                uint32_t b0h = tbh[g][2 * s], b1h = tbh[g][2 * s + 1];
                float* d = accO[ne];
                MMA_F16(d[0], d[1], d[2], d[3], pah[0], pah[1], pah[2], pah[3], b0h, b1h);
                MMA_F16(d[0], d[1], d[2], d[3], pal[0], pal[1], pal[2], pal[3], b0h, b1h);
            }
        }
        __syncthreads();   // all warps done with V buffer before re-fill
    }

    // ---- write unnormalized partials ----
    const size_t base = ((size_t)b * NT + t) * MAXC + chunk;
    float* pO = g_pO + base * 4096;
    const int r0 = wm0 + (lane >> 2);
    if ((lane & 3) == 0) {
        g_pm[base * 64 + r0]     = m_i[0];
        g_pm[base * 64 + r0 + 8] = m_i[1];
        g_pl[base * 64 + r0]     = l_i[0];
        g_pl[base * 64 + r0 + 8] = l_i[1];
    }
#pragma unroll
    for (int ne = 0; ne < 8; ++ne) {
        const int e = ne * 8 + (lane & 3) * 2;
        *reinterpret_cast<float2*>(&pO[(size_t)r0 * 64 + e]) =
            make_float2(accO[ne][0], accO[ne][1]);
        *reinterpret_cast<float2*>(&pO[(size_t)(r0 + 8) * 64 + e]) =
            make_float2(accO[ne][2], accO[ne][3]);
    }
}

// ---------------------------------------------------------------------------
// Combine: merge the <=4 chunks of each (b, row-tile). 512 blocks.
// ---------------------------------------------------------------------------
__global__ __launch_bounds__(256) void combine_kernel(float* __restrict__ out)
{
    const int half = blockIdx.x & 1;
    const int bt = blockIdx.x >> 1;
    const int t = bt >> 3;
    const int b = bt & 7;
    const int nc = (NT - t + CHUNK - 1) / CHUNK;
    const int tid = threadIdx.x;
    const int r  = tid >> 2;
    const int e0 = half * 32 + (tid & 3) * 8;

    const size_t base = ((size_t)b * NT + t) * MAXC;

    float m = -INFINITY;
    for (int c = 0; c < nc; ++c)
        m = fmaxf(m, g_pm[(base + c) * 64 + r]);

    float w[MAXC];
    float lsum = 0.f;
    for (int c = 0; c < nc; ++c) {
        float wc = __expf(g_pm[(base + c) * 64 + r] - m);
        w[c] = wc;
        lsum += wc * g_pl[(base + c) * 64 + r];
    }
    const float inv = 1.f / lsum;

    float o[8];
#pragma unroll
    for (int k = 0; k < 8; ++k) o[k] = 0.f;

    for (int c = 0; c < nc; ++c) {
        const float* pO = g_pO + (base + c) * 4096 + (size_t)r * 64 + e0;
        float wc = w[c];
#pragma unroll
        for (int k = 0; k < 8; k += 4) {
            float4 v = *reinterpret_cast<const float4*>(pO + k);
            o[k + 0] = fmaf(wc, v.x, o[k + 0]);
            o[k + 1] = fmaf(wc, v.y, o[k + 1]);
            o[k + 2] = fmaf(wc, v.z, o[k + 2]);
            o[k + 3] = fmaf(wc, v.w, o[k + 3]);
        }
    }

    float* dst = out + ((size_t)b * N_ + t * 64 + r) * E_ + e0;
#pragma unroll
    for (int k = 0; k < 8; k += 4)
        *reinterpret_cast<float4*>(dst + k) =
            make_float4(o[k] * inv, o[k + 1] * inv, o[k + 2] * inv, o[k + 3] * inv);
}

// ---------------------------------------------------------------------------
extern "C" void kernel_launch(void* const* d_in, const int* in_sizes, int n_in,
                              void* d_out, int out_size)
{
    (void)in_sizes; (void)n_in; (void)out_size;
    const float* input = (const float*)d_in[0];
    const float* Wk    = (const float*)d_in[1];
    // d_in[2] is q — dead in the reference, intentionally unused.
    const float* Wv    = (const float*)d_in[3];
    float* out = (float*)d_out;

    cudaFuncSetAttribute(proj_mma,
                         cudaFuncAttributeMaxDynamicSharedMemorySize, PROJ_SMEM);
    cudaFuncSetAttribute(attn_partial,
                         cudaFuncAttributeMaxDynamicSharedMemorySize, ATTN_SMEM_BYTES);

    prep_w<<<128, 256>>>(Wk, Wv);
    proj_mma<<<128, 256, PROJ_SMEM>>>(input);
    attn_partial<<<B_ * BLK_PER_B, 128, ATTN_SMEM_BYTES>>>();
    combine_kernel<<<B_ * NT * 2, 256>>>(out);
}

// round 12
// speedup vs baseline: 6.2439x; 1.1160x over previous
#include <cuda_runtime.h>
#include <cuda_fp16.h>
#include <math.h>
#include <stdint.h>

#define B_ 8
#define N_ 2048
#define H_ 1024
#define E_ 64
#define NT 32            // number of 64-row tiles per batch
#define CHUNK 8          // j-tiles (64 cols each) per partial block
#define MAXC 4           // max chunks per row-tile = ceil(32/8)
#define BLK_PER_B 80     // sum_t ceil((32-t)/8)

// Scratch (no allocation allowed in kernel_launch).
__device__ float g_pO[B_ * NT * MAXC * 64 * 64];
__device__ float g_pm[B_ * NT * MAXC * 64];
__device__ float g_pl[B_ * NT * MAXC * 64];
// K stored as fp16 hi/lo (2-pass S-gemm); V fp16 hi only.
__device__ __half g_kh[B_ * N_ * E_];
__device__ __half g_kl[B_ * N_ * E_];
__device__ __half g_vh[B_ * N_ * E_];
// Pre-transposed fp16 weight matrix Bt[n][k] = fp16([Wk|Wv][k][n]).
__device__ __half g_Wh[128 * 1024];

// ---------------------------------------------------------------------------
// Helpers (base-ISA: ldmatrix + mma.sync + cp.async — plain sm_100 target)
// ---------------------------------------------------------------------------
__device__ __forceinline__ uint32_t smem_u32(const void* p) {
    uint32_t a;
    asm("{ .reg .u64 t; cvta.to.shared.u64 t, %1; cvt.u32.u64 %0, t; }"
        : "=r"(a) : "l"(p));
    return a;
}

#define SW128(o) ((o) ^ ((((uint32_t)(o)) >> 3) & 0x70))

#define LDSM_X4(r0, r1, r2, r3, addr) \
    asm volatile("ldmatrix.sync.aligned.m8n8.x4.shared.b16 {%0,%1,%2,%3}, [%4];" \
                 : "=r"(r0), "=r"(r1), "=r"(r2), "=r"(r3) : "r"(addr))

#define LDSM_X4_T(r0, r1, r2, r3, addr) \
    asm volatile("ldmatrix.sync.aligned.m8n8.x4.trans.shared.b16 {%0,%1,%2,%3}, [%4];" \
                 : "=r"(r0), "=r"(r1), "=r"(r2), "=r"(r3) : "r"(addr))

#define MMA_F16(d0, d1, d2, d3, a0, a1, a2, a3, b0, b1) \
    asm volatile("mma.sync.aligned.m16n8k16.row.col.f32.f16.f16.f32 " \
                 "{%0,%1,%2,%3}, {%4,%5,%6,%7}, {%8,%9}, {%0,%1,%2,%3};" \
                 : "+f"(d0), "+f"(d1), "+f"(d2), "+f"(d3) \
                 : "r"(a0), "r"(a1), "r"(a2), "r"(a3), "r"(b0), "r"(b1))

#define CP16(dst, src) \
    asm volatile("cp.async.cg.shared.global [%0], [%1], 16;" \
                 :: "r"(dst), "l"(src) : "memory")
#define CP_COMMIT asm volatile("cp.async.commit_group;" ::: "memory")
#define CP_WAIT(n) asm volatile("cp.async.wait_group %0;" :: "n"(n) : "memory")

__device__ __forceinline__ uint32_t pack2h(float a, float b) {
    __half2 h = __floats2half2_rn(a, b);
    return *reinterpret_cast<uint32_t*>(&h);
}
__device__ __forceinline__ float h_rt(float x) {   // round-trip through fp16
    return __half2float(__float2half_rn(x));
}

// ---------------------------------------------------------------------------
// prep_w: Bt[n][k] = fp16(W[k][n]). n<64 -> Wk, else Wv.
// ---------------------------------------------------------------------------
__global__ __launch_bounds__(256) void prep_w(const float* __restrict__ Wk,
                                              const float* __restrict__ Wv)
{
    const int n = blockIdx.x;
    const float* src = (n < 64) ? (Wk + n) : (Wv + (n - 64));
    for (int k = threadIdx.x; k < H_; k += 256)
        g_Wh[n * H_ + k] = __float2half_rn(src[(size_t)k * E_]);
}

// ---------------------------------------------------------------------------
// proj_mma: C[16384,128] = A @ Bt^T, single-pass fp16, double-buffered.
// 2 x 32KB buffers (AH, WH 16KB each, SW128 rows of 128B).
// ---------------------------------------------------------------------------
#define OFF_AH 0
#define OFF_WH 16384
#define PBUF   32768
#define PROJ_SMEM (2 * PBUF)

__device__ __forceinline__ void proj_cp_w(uint32_t sb, uint32_t bufoff,
                                          int kt, int tid)
{
#pragma unroll
    for (int l = 0; l < 4; ++l) {      // 1024 16B-chunks: full 128 n-rows
        int idx = tid + l * 256;
        int row = idx >> 3;            // n 0..127
        int s8  = (idx & 7) << 3;      // k-offset 0..56
        uint32_t so = SW128((uint32_t)(row * 128 + s8 * 2));
        CP16(sb + bufoff + OFF_WH + so, &g_Wh[row * H_ + kt * 64 + s8]);
    }
}

__device__ __forceinline__ void proj_load_a(const float* __restrict__ A,
                                            int M0, int kt, int tid, float4* ar)
{
#pragma unroll
    for (int l = 0; l < 8; ++l) {
        int idx = tid + l * 256;
        int row = idx >> 4;
        int c4  = (idx & 15) << 2;
        ar[l] = *reinterpret_cast<const float4*>(
            A + (size_t)(M0 + row) * H_ + kt * 64 + c4);
    }
}

__device__ __forceinline__ void proj_store_a(char* sm, uint32_t bufoff,
                                             int tid, const float4* ar)
{
#pragma unroll
    for (int l = 0; l < 8; ++l) {
        int idx = tid + l * 256;
        int row = idx >> 4;
        int c4  = (idx & 15) << 2;
        float4 a = ar[l];
        uint32_t so = SW128((uint32_t)(row * 128 + c4 * 2));
        *reinterpret_cast<uint2*>(sm + bufoff + OFF_AH + so) =
            make_uint2(pack2h(a.x, a.y), pack2h(a.z, a.w));
    }
}

__global__ __launch_bounds__(256) void proj_mma(const float* __restrict__ A)
{
    extern __shared__ char sm[];
    const uint32_t sb = smem_u32(sm);
    const int tid = threadIdx.x;
    const int wid = tid >> 5;
    const int lane = tid & 31;
    const int M0 = blockIdx.x * 128;

    const int wm0 = (wid & 3) * 32;
    const int wn0 = (wid >> 2) * 64;   // 0 -> keys, 64 -> vals

    float acc[2][8][4];
#pragma unroll
    for (int mi = 0; mi < 2; ++mi)
#pragma unroll
        for (int ni = 0; ni < 8; ++ni)
#pragma unroll
            for (int q = 0; q < 4; ++q) acc[mi][ni][q] = 0.f;

    const int lrow = lane & 15;
    const int lchk = lane >> 4;

    float4 areg[8];

    // ---- prologue ----
    proj_cp_w(sb, 0, 0, tid);
    CP_COMMIT;
    proj_load_a(A, M0, 0, tid, areg);
    proj_store_a(sm, 0, tid, areg);
    proj_cp_w(sb, PBUF, 1, tid);
    CP_COMMIT;
    proj_load_a(A, M0, 1, tid, areg);
    CP_WAIT(1);          // W(0) landed
    __syncthreads();

    for (int kt = 0; kt < 16; ++kt) {
        const uint32_t bo = (kt & 1) ? PBUF : 0;

#pragma unroll
        for (int ks = 0; ks < 4; ++ks) {
            uint32_t ah[2][4];
#pragma unroll
            for (int mi = 0; mi < 2; ++mi) {
                uint32_t off = SW128((uint32_t)(
                    (wm0 + mi * 16 + lrow) * 128 + (ks * 2 + lchk) * 16));
                LDSM_X4(ah[mi][0], ah[mi][1], ah[mi][2], ah[mi][3],
                        sb + bo + OFF_AH + off);
            }
            uint32_t bh[4][4];
#pragma unroll
            for (int g = 0; g < 4; ++g) {
                uint32_t off = SW128((uint32_t)(
                    (wn0 + g * 16 + lrow) * 128 + (ks * 2 + lchk) * 16));
                LDSM_X4(bh[g][0], bh[g][1], bh[g][2], bh[g][3],
                        sb + bo + OFF_WH + off);
            }
#pragma unroll
            for (int mi = 0; mi < 2; ++mi) {
#pragma unroll
                for (int ni = 0; ni < 8; ++ni) {
                    const int g = ni >> 1;
                    const int s = ni & 1;
                    float* d = acc[mi][ni];
                    MMA_F16(d[0], d[1], d[2], d[3],
                            ah[mi][0], ah[mi][1], ah[mi][2], ah[mi][3],
                            bh[g][s], bh[g][s + 2]);
                }
            }
        }

        if (kt < 15)
            proj_store_a(sm, (kt & 1) ? 0 : PBUF, tid, areg);
        __syncthreads();

        if (kt < 14) {
            proj_cp_w(sb, bo, kt + 2, tid);
            CP_COMMIT;
            proj_load_a(A, M0, kt + 2, tid, areg);
            CP_WAIT(1);
        } else {
            CP_WAIT(0);
        }
        __syncthreads();
    }

    // ---- epilogue: keys -> fp16 hi+lo; vals -> fp16 hi only ----
    const int colb = (lane & 3) * 2;
    const int rowb = M0 + wm0 + (lane >> 2);
#pragma unroll
    for (int mi = 0; mi < 2; ++mi) {
#pragma unroll
        for (int ni = 0; ni < 8; ++ni) {
            const int col = ni * 8 + colb;
#pragma unroll
            for (int hq = 0; hq < 2; ++hq) {
                const int r = rowb + mi * 16 + hq * 8;
                float d0 = acc[mi][ni][hq * 2 + 0];
                float d1 = acc[mi][ni][hq * 2 + 1];
                if (wn0 == 0) {
                    *reinterpret_cast<uint32_t*>(&g_kh[(size_t)r * E_ + col]) =
                        pack2h(d0, d1);
                    *reinterpret_cast<uint32_t*>(&g_kl[(size_t)r * E_ + col]) =
                        pack2h(d0 - h_rt(d0), d1 - h_rt(d1));
                } else {
                    *reinterpret_cast<uint32_t*>(&g_vh[(size_t)r * E_ + col]) =
                        pack2h(d0, d1);
                }
            }
        }
    }
}

// ---------------------------------------------------------------------------
// attn_partial: S = (Kh+Kl).Vh (2-pass) ; O = Ph.Vh^T (1-pass — P's fp16
// rounding bypasses the exp amplifier, ~2-5e-4 contribution).
// smem: KH,KL (8KB each) + 2 x VH (8KB) -> 32KB.
// ---------------------------------------------------------------------------
#define AT_KH 0
#define AT_KL 8192
#define AT_V0 16384
#define AT_V1 24576
#define ATTN_SMEM_BYTES 32768

__device__ __forceinline__ void attn_cp_k(uint32_t sb, size_t gbase, int tid)
{
#pragma unroll
    for (int l = 0; l < 4; ++l) {
        int idx = tid + l * 128;       // 0..511 16B-chunks (64 rows x 128B)
        int row = idx >> 3;
        int e8  = (idx & 7) << 3;
        uint32_t so = SW128((uint32_t)(row * 128 + e8 * 2));
        CP16(sb + AT_KH + so, g_kh + gbase + (size_t)row * E_ + e8);
        CP16(sb + AT_KL + so, g_kl + gbase + (size_t)row * E_ + e8);
    }
}

__device__ __forceinline__ void attn_cp_v(uint32_t sb, uint32_t voff,
                                          size_t gbase, int tid)
{
#pragma unroll
    for (int l = 0; l < 4; ++l) {
        int idx = tid + l * 128;
        int row = idx >> 3;
        int e8  = (idx & 7) << 3;
        uint32_t so = SW128((uint32_t)(row * 128 + e8 * 2));
        CP16(sb + voff + so, g_vh + gbase + (size_t)row * E_ + e8);
    }
}

__global__ __launch_bounds__(128) void attn_partial()
{
    extern __shared__ char sm[];
    const uint32_t sb = smem_u32(sm);
    const int tid = threadIdx.x;
    const int wid = tid >> 5;
    const int lane = tid & 31;

    const int b = blockIdx.x / BLK_PER_B;
    int ent = blockIdx.x - b * BLK_PER_B;
    int t = 0, acc0 = 0;
    for (int tt = 0; tt < NT; ++tt) {
        int nc = (NT - tt + CHUNK - 1) / CHUNK;
        if (ent < acc0 + nc) { t = tt; break; }
        acc0 += nc;
    }
    const int chunk = ent - acc0;
    const int j0 = t + chunk * CHUNK;
    const int j1 = min(NT, j0 + CHUNK);

    const int wm0 = wid * 16;
    const int lrow = lane & 15;
    const int lchk = lane >> 4;

    // ---- prologue ----
    attn_cp_k(sb, ((size_t)b * N_ + t * 64) * E_, tid);
    CP_COMMIT;
    attn_cp_v(sb, AT_V0, ((size_t)b * N_ + j0 * 64) * E_, tid);
    CP_COMMIT;

    float m_i[2], l_i[2], accO[8][4];
#pragma unroll
    for (int h = 0; h < 2; ++h) { m_i[h] = -INFINITY; l_i[h] = 0.f; }
#pragma unroll
    for (int ne = 0; ne < 8; ++ne)
#pragma unroll
        for (int q = 0; q < 4; ++q) accO[ne][q] = 0.f;

    for (int jt = j0; jt < j1; ++jt) {
        const uint32_t vb = ((jt - j0) & 1) ? AT_V1 : AT_V0;

        if (jt + 1 < j1) {
            attn_cp_v(sb, ((jt + 1 - j0) & 1) ? AT_V1 : AT_V0,
                      ((size_t)b * N_ + (jt + 1) * 64) * E_, tid);
            CP_COMMIT;
            CP_WAIT(1);   // K + V(jt) complete
        } else {
            CP_WAIT(0);
        }
        __syncthreads();

        // ---- S-gemm: S = Kh.Vh + Kl.Vh ----
        float Sa[8][4];
#pragma unroll
        for (int ni = 0; ni < 8; ++ni)
#pragma unroll
            for (int q = 0; q < 4; ++q) Sa[ni][q] = 0.f;

#pragma unroll
        for (int ks = 0; ks < 4; ++ks) {
            uint32_t ah[4], al[4];
            uint32_t offa = SW128((uint32_t)(
                (wm0 + lrow) * 128 + (ks * 2 + lchk) * 16));
            LDSM_X4(ah[0], ah[1], ah[2], ah[3], sb + AT_KH + offa);
            LDSM_X4(al[0], al[1], al[2], al[3], sb + AT_KL + offa);
            uint32_t bh[4][4];
#pragma unroll
            for (int g = 0; g < 4; ++g) {
                uint32_t offb = SW128((uint32_t)(
                    (g * 16 + lrow) * 128 + (ks * 2 + lchk) * 16));
                LDSM_X4(bh[g][0], bh[g][1], bh[g][2], bh[g][3], sb + vb + offb);
            }
#pragma unroll
            for (int ni = 0; ni < 8; ++ni) {
                const int g = ni >> 1;
                const int s = ni & 1;
                uint32_t b0h = bh[g][s], b1h = bh[g][s + 2];
                float* d = Sa[ni];
                MMA_F16(d[0], d[1], d[2], d[3], ah[0], ah[1], ah[2], ah[3], b0h, b1h);
                MMA_F16(d[0], d[1], d[2], d[3], al[0], al[1], al[2], al[3], b0h, b1h);
            }
        }

        // ---- scale + mask ----
        const float sc = 0.125f;
        if (jt == t) {
#pragma unroll
            for (int ni = 0; ni < 8; ++ni)
#pragma unroll
                for (int q = 0; q < 4; ++q) {
                    int i_loc = wm0 + (lane >> 2) + ((q >> 1) << 3);
                    int j_loc = ni * 8 + (lane & 3) * 2 + (q & 1);
                    Sa[ni][q] = (j_loc >= i_loc) ? Sa[ni][q] * sc : -1e30f;
                }
        } else {
#pragma unroll
            for (int ni = 0; ni < 8; ++ni)
#pragma unroll
                for (int q = 0; q < 4; ++q) Sa[ni][q] *= sc;
        }

        // ---- online softmax ----
#pragma unroll
        for (int h = 0; h < 2; ++h) {
            float tmax = -INFINITY;
#pragma unroll
            for (int ni = 0; ni < 8; ++ni)
                tmax = fmaxf(tmax, fmaxf(Sa[ni][h * 2], Sa[ni][h * 2 + 1]));
            tmax = fmaxf(tmax, __shfl_xor_sync(0xffffffffu, tmax, 1));
            tmax = fmaxf(tmax, __shfl_xor_sync(0xffffffffu, tmax, 2));
            float mnew = fmaxf(m_i[h], tmax);
            float alpha = __expf(m_i[h] - mnew);
            float ps = 0.f;
#pragma unroll
            for (int ni = 0; ni < 8; ++ni) {
                float p0 = __expf(Sa[ni][h * 2] - mnew);
                float p1 = __expf(Sa[ni][h * 2 + 1] - mnew);
                Sa[ni][h * 2] = p0;
                Sa[ni][h * 2 + 1] = p1;
                ps += p0 + p1;
            }
            ps += __shfl_xor_sync(0xffffffffu, ps, 1);
            ps += __shfl_xor_sync(0xffffffffu, ps, 2);
            l_i[h] = l_i[h] * alpha + ps;
            m_i[h] = mnew;
#pragma unroll
            for (int ne = 0; ne < 8; ++ne) {
                accO[ne][h * 2] *= alpha;
                accO[ne][h * 2 + 1] *= alpha;
            }
        }

        // ---- O-gemm: accO += Ph @ Vh (single-pass, trans fragments) ----
#pragma unroll
        for (int kc = 0; kc < 4; ++kc) {
            const int n0 = 2 * kc, n1 = 2 * kc + 1;
            uint32_t pah[4];
            pah[0] = pack2h(Sa[n0][0], Sa[n0][1]);
            pah[1] = pack2h(Sa[n0][2], Sa[n0][3]);
            pah[2] = pack2h(Sa[n1][0], Sa[n1][1]);
            pah[3] = pack2h(Sa[n1][2], Sa[n1][3]);
            uint32_t tbh[4][4];
#pragma unroll
            for (int g = 0; g < 4; ++g) {
                uint32_t offt = SW128((uint32_t)(
                    (kc * 16 + lrow) * 128 + g * 32 + lchk * 16));
                LDSM_X4_T(tbh[g][0], tbh[g][1], tbh[g][2], tbh[g][3],
                          sb + vb + offt);
            }
#pragma unroll
            for (int ne = 0; ne < 8; ++ne) {
                const int g = ne >> 1;
                const int s = ne & 1;
                float* d = accO[ne];
                MMA_F16(d[0], d[1], d[2], d[3], pah[0], pah[1], pah[2], pah[3],
                        tbh[g][2 * s], tbh[g][2 * s + 1]);
            }
        }
        __syncthreads();   // all warps done with V buffer before re-fill
    }

    // ---- write unnormalized partials ----
    const size_t base = ((size_t)b * NT + t) * MAXC + chunk;
    float* pO = g_pO + base * 4096;
    const int r0 = wm0 + (lane >> 2);
    if ((lane & 3) == 0) {
        g_pm[base * 64 + r0]     = m_i[0];
        g_pm[base * 64 + r0 + 8] = m_i[1];
        g_pl[base * 64 + r0]     = l_i[0];
        g_pl[base * 64 + r0 + 8] = l_i[1];
    }
#pragma unroll
    for (int ne = 0; ne < 8; ++ne) {
        const int e = ne * 8 + (lane & 3) * 2;
        *reinterpret_cast<float2*>(&pO[(size_t)r0 * 64 + e]) =
            make_float2(accO[ne][0], accO[ne][1]);
        *reinterpret_cast<float2*>(&pO[(size_t)(r0 + 8) * 64 + e]) =
            make_float2(accO[ne][2], accO[ne][3]);
    }
}

// ---------------------------------------------------------------------------
// Combine: merge the <=4 chunks of each (b, row-tile). 512 blocks, all
// partial-O loads batched up-front for MLP.
// ---------------------------------------------------------------------------
__global__ __launch_bounds__(256) void combine_kernel(float* __restrict__ out)
{
    const int half = blockIdx.x & 1;
    const int bt = blockIdx.x >> 1;
    const int t = bt >> 3;
    const int b = bt & 7;
    const int nc = (NT - t + CHUNK - 1) / CHUNK;
    const int tid = threadIdx.x;
    const int r  = tid >> 2;
    const int e0 = half * 32 + (tid & 3) * 8;

    const size_t base = ((size_t)b * NT + t) * MAXC;

    // Batch all pm/pl loads.
    float pm[MAXC], pl[MAXC];
#pragma unroll
    for (int c = 0; c < MAXC; ++c) {
        if (c < nc) {
            pm[c] = g_pm[(base + c) * 64 + r];
            pl[c] = g_pl[(base + c) * 64 + r];
        } else { pm[c] = -INFINITY; pl[c] = 0.f; }
    }
    // Batch all partial-O loads (up to 8 independent LDG.128).
    float4 va[MAXC], vb4[MAXC];
#pragma unroll
    for (int c = 0; c < MAXC; ++c) {
        if (c < nc) {
            const float* pO = g_pO + (base + c) * 4096 + (size_t)r * 64 + e0;
            va[c]  = *reinterpret_cast<const float4*>(pO);
            vb4[c] = *reinterpret_cast<const float4*>(pO + 4);
        }
    }

    float m = -INFINITY;
#pragma unroll
    for (int c = 0; c < MAXC; ++c) m = fmaxf(m, pm[c]);

    float w[MAXC], lsum = 0.f;
#pragma unroll
    for (int c = 0; c < MAXC; ++c) {
        float wc = __expf(pm[c] - m);
        w[c] = wc;
        lsum += wc * pl[c];
    }
    const float inv = 1.f / lsum;

    float o[8];
#pragma unroll
    for (int k = 0; k < 8; ++k) o[k] = 0.f;
#pragma unroll
    for (int c = 0; c < MAXC; ++c) {
        if (c < nc) {
            float wc = w[c];
            o[0] = fmaf(wc, va[c].x, o[0]);
            o[1] = fmaf(wc, va[c].y, o[1]);
            o[2] = fmaf(wc, va[c].z, o[2]);
            o[3] = fmaf(wc, va[c].w, o[3]);
            o[4] = fmaf(wc, vb4[c].x, o[4]);
            o[5] = fmaf(wc, vb4[c].y, o[5]);
            o[6] = fmaf(wc, vb4[c].z, o[6]);
            o[7] = fmaf(wc, vb4[c].w, o[7]);
        }
    }

    float* dst = out + ((size_t)b * N_ + t * 64 + r) * E_ + e0;
    *reinterpret_cast<float4*>(dst) =
        make_float4(o[0] * inv, o[1] * inv, o[2] * inv, o[3] * inv);
    *reinterpret_cast<float4*>(dst + 4) =
        make_float4(o[4] * inv, o[5] * inv, o[6] * inv, o[7] * inv);
}

// ---------------------------------------------------------------------------
extern "C" void kernel_launch(void* const* d_in, const int* in_sizes, int n_in,
                              void* d_out, int out_size)
{
    (void)in_sizes; (void)n_in; (void)out_size;
    const float* input = (const float*)d_in[0];
    const float* Wk    = (const float*)d_in[1];
    // d_in[2] is q — dead in the reference, intentionally unused.
    const float* Wv    = (const float*)d_in[3];
    float* out = (float*)d_out;

    cudaFuncSetAttribute(proj_mma,
                         cudaFuncAttributeMaxDynamicSharedMemorySize, PROJ_SMEM);
    cudaFuncSetAttribute(attn_partial,
                         cudaFuncAttributeMaxDynamicSharedMemorySize, ATTN_SMEM_BYTES);

    prep_w<<<128, 256>>>(Wk, Wv);
    proj_mma<<<128, 256, PROJ_SMEM>>>(input);
    attn_partial<<<B_ * BLK_PER_B, 128, ATTN_SMEM_BYTES>>>();
    combine_kernel<<<B_ * NT * 2, 256>>>(out);
}

// round 14
// speedup vs baseline: 7.0000x; 1.1211x over previous
#include <cuda_runtime.h>
#include <cuda_fp16.h>
#include <math.h>
#include <stdint.h>

#define B_ 8
#define N_ 2048
#define H_ 1024
#define E_ 64
#define NT 32            // number of 64-row tiles per batch
#define CHUNK 8          // j-tiles (64 cols each) per partial block
#define MAXC 4           // max chunks per row-tile = ceil(32/8)
#define BLK_PER_B 80     // sum_t ceil((32-t)/8)

// Scratch (no allocation allowed in kernel_launch).
__device__ __half g_pOh[B_ * NT * MAXC * 64 * 64];   // unnormalized partial O (fp16)
__device__ float g_pm[B_ * NT * MAXC * 64];
__device__ float g_pl[B_ * NT * MAXC * 64];
// K and V stored fp16 (single-pass S-gemm: both operands rounded).
__device__ __half g_kh[B_ * N_ * E_];
__device__ __half g_vh[B_ * N_ * E_];
// Pre-transposed fp16 weight matrix Bt[n][k] = fp16([Wk|Wv][k][n]).
__device__ __half g_Wh[128 * 1024];

// ---------------------------------------------------------------------------
// Helpers (base-ISA: ldmatrix + mma.sync + cp.async — plain sm_100 target)
// ---------------------------------------------------------------------------
__device__ __forceinline__ uint32_t smem_u32(const void* p) {
    uint32_t a;
    asm("{ .reg .u64 t; cvta.to.shared.u64 t, %1; cvt.u32.u64 %0, t; }"
        : "=r"(a) : "l"(p));
    return a;
}

#define SW128(o) ((o) ^ ((((uint32_t)(o)) >> 3) & 0x70))

#define LDSM_X4(r0, r1, r2, r3, addr) \
    asm volatile("ldmatrix.sync.aligned.m8n8.x4.shared.b16 {%0,%1,%2,%3}, [%4];" \
                 : "=r"(r0), "=r"(r1), "=r"(r2), "=r"(r3) : "r"(addr))

#define LDSM_X4_T(r0, r1, r2, r3, addr) \
    asm volatile("ldmatrix.sync.aligned.m8n8.x4.trans.shared.b16 {%0,%1,%2,%3}, [%4];" \
                 : "=r"(r0), "=r"(r1), "=r"(r2), "=r"(r3) : "r"(addr))

#define MMA_F16(d0, d1, d2, d3, a0, a1, a2, a3, b0, b1) \
    asm volatile("mma.sync.aligned.m16n8k16.row.col.f32.f16.f16.f32 " \
                 "{%0,%1,%2,%3}, {%4,%5,%6,%7}, {%8,%9}, {%0,%1,%2,%3};" \
                 : "+f"(d0), "+f"(d1), "+f"(d2), "+f"(d3) \
                 : "r"(a0), "r"(a1), "r"(a2), "r"(a3), "r"(b0), "r"(b1))

#define CP16(dst, src) \
    asm volatile("cp.async.cg.shared.global [%0], [%1], 16;" \
                 :: "r"(dst), "l"(src) : "memory")
#define CP_COMMIT asm volatile("cp.async.commit_group;" ::: "memory")
#define CP_WAIT(n) asm volatile("cp.async.wait_group %0;" :: "n"(n) : "memory")

__device__ __forceinline__ uint32_t pack2h(float a, float b) {
    __half2 h = __floats2half2_rn(a, b);
    return *reinterpret_cast<uint32_t*>(&h);
}
__device__ __forceinline__ float2 unpack2h(uint32_t u) {
    __half2 h = *reinterpret_cast<__half2*>(&u);
    return __half22float2(h);
}

// ---------------------------------------------------------------------------
// prep_w: Bt[n][k] = fp16(W[k][n]). n<64 -> Wk, else Wv.
// ---------------------------------------------------------------------------
__global__ __launch_bounds__(256) void prep_w(const float* __restrict__ Wk,
                                              const float* __restrict__ Wv)
{
    const int n = blockIdx.x;
    const float* src = (n < 64) ? (Wk + n) : (Wv + (n - 64));
    for (int k = threadIdx.x; k < H_; k += 256)
        g_Wh[n * H_ + k] = __float2half_rn(src[(size_t)k * E_]);
}

// ---------------------------------------------------------------------------
// proj_mma: C[16384,128] = A @ Bt^T, single-pass fp16, double-buffered.
// 2 x 32KB buffers (AH, WH 16KB each, SW128 rows of 128B).
// ---------------------------------------------------------------------------
#define OFF_AH 0
#define OFF_WH 16384
#define PBUF   32768
#define PROJ_SMEM (2 * PBUF)

__device__ __forceinline__ void proj_cp_w(uint32_t sb, uint32_t bufoff,
                                          int kt, int tid)
{
#pragma unroll
    for (int l = 0; l < 4; ++l) {      // 1024 16B-chunks: full 128 n-rows
        int idx = tid + l * 256;
        int row = idx >> 3;            // n 0..127
        int s8  = (idx & 7) << 3;      // k-offset 0..56
        uint32_t so = SW128((uint32_t)(row * 128 + s8 * 2));
        CP16(sb + bufoff + OFF_WH + so, &g_Wh[row * H_ + kt * 64 + s8]);
    }
}

__device__ __forceinline__ void proj_load_a(const float* __restrict__ A,
                                            int M0, int kt, int tid, float4* ar)
{
#pragma unroll
    for (int l = 0; l < 8; ++l) {
        int idx = tid + l * 256;
        int row = idx >> 4;
        int c4  = (idx & 15) << 2;
        ar[l] = *reinterpret_cast<const float4*>(
            A + (size_t)(M0 + row) * H_ + kt * 64 + c4);
    }
}

__device__ __forceinline__ void proj_store_a(char* sm, uint32_t bufoff,
                                             int tid, const float4* ar)
{
#pragma unroll
    for (int l = 0; l < 8; ++l) {
        int idx = tid + l * 256;
        int row = idx >> 4;
        int c4  = (idx & 15) << 2;
        float4 a = ar[l];
        uint32_t so = SW128((uint32_t)(row * 128 + c4 * 2));
        *reinterpret_cast<uint2*>(sm + bufoff + OFF_AH + so) =
            make_uint2(pack2h(a.x, a.y), pack2h(a.z, a.w));
    }
}

__global__ __launch_bounds__(256) void proj_mma(const float* __restrict__ A)
{
    extern __shared__ char sm[];
    const uint32_t sb = smem_u32(sm);
    const int tid = threadIdx.x;
    const int wid = tid >> 5;
    const int lane = tid & 31;
    const int M0 = blockIdx.x * 128;

    const int wm0 = (wid & 3) * 32;
    const int wn0 = (wid >> 2) * 64;   // 0 -> keys, 64 -> vals

    float acc[2][8][4];
#pragma unroll
    for (int mi = 0; mi < 2; ++mi)
#pragma unroll
        for (int ni = 0; ni < 8; ++ni)
#pragma unroll
            for (int q = 0; q < 4; ++q) acc[mi][ni][q] = 0.f;

    const int lrow = lane & 15;
    const int lchk = lane >> 4;

    float4 areg[8];

    // ---- prologue ----
    proj_cp_w(sb, 0, 0, tid);
    CP_COMMIT;
    proj_load_a(A, M0, 0, tid, areg);
    proj_store_a(sm, 0, tid, areg);
    proj_cp_w(sb, PBUF, 1, tid);
    CP_COMMIT;
    proj_load_a(A, M0, 1, tid, areg);
    CP_WAIT(1);          // W(0) landed
    __syncthreads();

    for (int kt = 0; kt < 16; ++kt) {
        const uint32_t bo = (kt & 1) ? PBUF : 0;

#pragma unroll
        for (int ks = 0; ks < 4; ++ks) {
            uint32_t ah[2][4];
#pragma unroll
            for (int mi = 0; mi < 2; ++mi) {
                uint32_t off = SW128((uint32_t)(
                    (wm0 + mi * 16 + lrow) * 128 + (ks * 2 + lchk) * 16));
                LDSM_X4(ah[mi][0], ah[mi][1], ah[mi][2], ah[mi][3],
                        sb + bo + OFF_AH + off);
            }
            uint32_t bh[4][4];
#pragma unroll
            for (int g = 0; g < 4; ++g) {
                uint32_t off = SW128((uint32_t)(
                    (wn0 + g * 16 + lrow) * 128 + (ks * 2 + lchk) * 16));
                LDSM_X4(bh[g][0], bh[g][1], bh[g][2], bh[g][3],
                        sb + bo + OFF_WH + off);
            }
#pragma unroll
            for (int mi = 0; mi < 2; ++mi) {
#pragma unroll
                for (int ni = 0; ni < 8; ++ni) {
                    const int g = ni >> 1;
                    const int s = ni & 1;
                    float* d = acc[mi][ni];
                    MMA_F16(d[0], d[1], d[2], d[3],
                            ah[mi][0], ah[mi][1], ah[mi][2], ah[mi][3],
                            bh[g][s], bh[g][s + 2]);
                }
            }
        }

        if (kt < 15)
            proj_store_a(sm, (kt & 1) ? 0 : PBUF, tid, areg);
        __syncthreads();

        if (kt < 14) {
            proj_cp_w(sb, bo, kt + 2, tid);
            CP_COMMIT;
            proj_load_a(A, M0, kt + 2, tid, areg);
            CP_WAIT(1);
        } else {
            CP_WAIT(0);
        }
        __syncthreads();
    }

    // ---- epilogue: fp16 K or V ----
    __half* outm = (wn0 == 0) ? g_kh : g_vh;
    const int colb = (lane & 3) * 2;
    const int rowb = M0 + wm0 + (lane >> 2);
#pragma unroll
    for (int mi = 0; mi < 2; ++mi) {
#pragma unroll
        for (int ni = 0; ni < 8; ++ni) {
            const int col = ni * 8 + colb;
#pragma unroll
            for (int hq = 0; hq < 2; ++hq) {
                const int r = rowb + mi * 16 + hq * 8;
                *reinterpret_cast<uint32_t*>(&outm[(size_t)r * E_ + col]) =
                    pack2h(acc[mi][ni][hq * 2 + 0], acc[mi][ni][hq * 2 + 1]);
            }
        }
    }
}

// ---------------------------------------------------------------------------
// attn_partial: S = Kh.Vh (1-pass) ; O = Ph.Vh^T (1-pass).
// K fragments hoisted into registers (j-loop-invariant).
// smem: KH (8KB) + 2 x VH (8KB) -> 24KB.
// ---------------------------------------------------------------------------
#define AT_KH 0
#define AT_V0 8192
#define AT_V1 16384
#define ATTN_SMEM_BYTES 24576

__device__ __forceinline__ void attn_cp_tile(uint32_t sb, uint32_t off,
                                             const __half* __restrict__ src,
                                             size_t gbase, int tid)
{
#pragma unroll
    for (int l = 0; l < 4; ++l) {
        int idx = tid + l * 128;       // 0..511 16B-chunks (64 rows x 128B)
        int row = idx >> 3;
        int e8  = (idx & 7) << 3;
        uint32_t so = SW128((uint32_t)(row * 128 + e8 * 2));
        CP16(sb + off + so, src + gbase + (size_t)row * E_ + e8);
    }
}

__global__ __launch_bounds__(128) void attn_partial()
{
    extern __shared__ char sm[];
    const uint32_t sb = smem_u32(sm);
    const int tid = threadIdx.x;
    const int wid = tid >> 5;
    const int lane = tid & 31;

    const int b = blockIdx.x / BLK_PER_B;
    int ent = blockIdx.x - b * BLK_PER_B;
    int t = 0, acc0 = 0;
    for (int tt = 0; tt < NT; ++tt) {
        int nc = (NT - tt + CHUNK - 1) / CHUNK;
        if (ent < acc0 + nc) { t = tt; break; }
        acc0 += nc;
    }
    const int chunk = ent - acc0;
    const int j0 = t + chunk * CHUNK;
    const int j1 = min(NT, j0 + CHUNK);

    const int wm0 = wid * 16;
    const int lrow = lane & 15;
    const int lchk = lane >> 4;

    // ---- prologue: K (group 0) + V(j0) (group 1) via cp.async ----
    attn_cp_tile(sb, AT_KH, g_kh, ((size_t)b * N_ + t * 64) * E_, tid);
    CP_COMMIT;
    attn_cp_tile(sb, AT_V0, g_vh, ((size_t)b * N_ + j0 * 64) * E_, tid);
    CP_COMMIT;

    // ---- hoist K fragments (j-loop-invariant): K group done after wait(1) ----
    CP_WAIT(1);
    __syncthreads();
    uint32_t kfr[4][4];
#pragma unroll
    for (int ks = 0; ks < 4; ++ks) {
        uint32_t offa = SW128((uint32_t)(
            (wm0 + lrow) * 128 + (ks * 2 + lchk) * 16));
        LDSM_X4(kfr[ks][0], kfr[ks][1], kfr[ks][2], kfr[ks][3], sb + AT_KH + offa);
    }

    float m_i[2], l_i[2], accO[8][4];
#pragma unroll
    for (int h = 0; h < 2; ++h) { m_i[h] = -INFINITY; l_i[h] = 0.f; }
#pragma unroll
    for (int ne = 0; ne < 8; ++ne)
#pragma unroll
        for (int q = 0; q < 4; ++q) accO[ne][q] = 0.f;

    for (int jt = j0; jt < j1; ++jt) {
        const uint32_t vb = ((jt - j0) & 1) ? AT_V1 : AT_V0;

        if (jt + 1 < j1) {
            attn_cp_tile(sb, ((jt + 1 - j0) & 1) ? AT_V1 : AT_V0, g_vh,
                         ((size_t)b * N_ + (jt + 1) * 64) * E_, tid);
            CP_COMMIT;
            CP_WAIT(1);   // V(jt) complete
        } else {
            CP_WAIT(0);
        }
        __syncthreads();

        // ---- S-gemm: S = Kh.Vh (single pass, K frags in registers) ----
        float Sa[8][4];
#pragma unroll
        for (int ni = 0; ni < 8; ++ni)
#pragma unroll
            for (int q = 0; q < 4; ++q) Sa[ni][q] = 0.f;

#pragma unroll
        for (int ks = 0; ks < 4; ++ks) {
            uint32_t bh[4][4];
#pragma unroll
            for (int g = 0; g < 4; ++g) {
                uint32_t offb = SW128((uint32_t)(
                    (g * 16 + lrow) * 128 + (ks * 2 + lchk) * 16));
                LDSM_X4(bh[g][0], bh[g][1], bh[g][2], bh[g][3], sb + vb + offb);
            }
#pragma unroll
            for (int ni = 0; ni < 8; ++ni) {
                const int g = ni >> 1;
                const int s = ni & 1;
                float* d = Sa[ni];
                MMA_F16(d[0], d[1], d[2], d[3],
                        kfr[ks][0], kfr[ks][1], kfr[ks][2], kfr[ks][3],
                        bh[g][s], bh[g][s + 2]);
            }
        }

        // ---- scale + mask ----
        const float sc = 0.125f;
        if (jt == t) {
#pragma unroll
            for (int ni = 0; ni < 8; ++ni)
#pragma unroll
                for (int q = 0; q < 4; ++q) {
                    int i_loc = wm0 + (lane >> 2) + ((q >> 1) << 3);
                    int j_loc = ni * 8 + (lane & 3) * 2 + (q & 1);
                    Sa[ni][q] = (j_loc >= i_loc) ? Sa[ni][q] * sc : -1e30f;
                }
        } else {
#pragma unroll
            for (int ni = 0; ni < 8; ++ni)
#pragma unroll
                for (int q = 0; q < 4; ++q) Sa[ni][q] *= sc;
        }

        // ---- online softmax ----
#pragma unroll
        for (int h = 0; h < 2; ++h) {
            float tmax = -INFINITY;
#pragma unroll
            for (int ni = 0; ni < 8; ++ni)
                tmax = fmaxf(tmax, fmaxf(Sa[ni][h * 2], Sa[ni][h * 2 + 1]));
            tmax = fmaxf(tmax, __shfl_xor_sync(0xffffffffu, tmax, 1));
            tmax = fmaxf(tmax, __shfl_xor_sync(0xffffffffu, tmax, 2));
            float mnew = fmaxf(m_i[h], tmax);
            float alpha = __expf(m_i[h] - mnew);
            float ps = 0.f;
#pragma unroll
            for (int ni = 0; ni < 8; ++ni) {
                float p0 = __expf(Sa[ni][h * 2] - mnew);
                float p1 = __expf(Sa[ni][h * 2 + 1] - mnew);
                Sa[ni][h * 2] = p0;
                Sa[ni][h * 2 + 1] = p1;
                ps += p0 + p1;
            }
            ps += __shfl_xor_sync(0xffffffffu, ps, 1);
            ps += __shfl_xor_sync(0xffffffffu, ps, 2);
            l_i[h] = l_i[h] * alpha + ps;
            m_i[h] = mnew;
#pragma unroll
            for (int ne = 0; ne < 8; ++ne) {
                accO[ne][h * 2] *= alpha;
                accO[ne][h * 2 + 1] *= alpha;
            }
        }

        // ---- O-gemm: accO += Ph @ Vh (single pass, trans fragments) ----
#pragma unroll
        for (int kc = 0; kc < 4; ++kc) {
            const int n0 = 2 * kc, n1 = 2 * kc + 1;
            uint32_t pah[4];
            pah[0] = pack2h(Sa[n0][0], Sa[n0][1]);
            pah[1] = pack2h(Sa[n0][2], Sa[n0][3]);
            pah[2] = pack2h(Sa[n1][0], Sa[n1][1]);
            pah[3] = pack2h(Sa[n1][2], Sa[n1][3]);
            uint32_t tbh[4][4];
#pragma unroll
            for (int g = 0; g < 4; ++g) {
                uint32_t offt = SW128((uint32_t)(
                    (kc * 16 + lrow) * 128 + g * 32 + lchk * 16));
                LDSM_X4_T(tbh[g][0], tbh[g][1], tbh[g][2], tbh[g][3],
                          sb + vb + offt);
            }
#pragma unroll
            for (int ne = 0; ne < 8; ++ne) {
                const int g = ne >> 1;
                const int s = ne & 1;
                float* d = accO[ne];
                MMA_F16(d[0], d[1], d[2], d[3], pah[0], pah[1], pah[2], pah[3],
                        tbh[g][2 * s], tbh[g][2 * s + 1]);
            }
        }
        __syncthreads();   // all warps done with V buffer before re-fill
    }

    // ---- write unnormalized partials (fp16) ----
    const size_t base = ((size_t)b * NT + t) * MAXC + chunk;
    __half* pO = g_pOh + base * 4096;
    const int r0 = wm0 + (lane >> 2);
    if ((lane & 3) == 0) {
        g_pm[base * 64 + r0]     = m_i[0];
        g_pm[base * 64 + r0 + 8] = m_i[1];
        g_pl[base * 64 + r0]     = l_i[0];
        g_pl[base * 64 + r0 + 8] = l_i[1];
    }
#pragma unroll
    for (int ne = 0; ne < 8; ++ne) {
        const int e = ne * 8 + (lane & 3) * 2;
        *reinterpret_cast<uint32_t*>(&pO[(size_t)r0 * 64 + e]) =
            pack2h(accO[ne][0], accO[ne][1]);
        *reinterpret_cast<uint32_t*>(&pO[(size_t)(r0 + 8) * 64 + e]) =
            pack2h(accO[ne][2], accO[ne][3]);
    }
}

// ---------------------------------------------------------------------------
// Combine: merge the <=4 chunks of each (b, row-tile). 512 blocks, fp16
// partials batched up-front for MLP.
// ---------------------------------------------------------------------------
__global__ __launch_bounds__(256) void combine_kernel(float* __restrict__ out)
{
    const int half = blockIdx.x & 1;
    const int bt = blockIdx.x >> 1;
    const int t = bt >> 3;
    const int b = bt & 7;
    const int nc = (NT - t + CHUNK - 1) / CHUNK;
    const int tid = threadIdx.x;
    const int r  = tid >> 2;
    const int e0 = half * 32 + (tid & 3) * 8;

    const size_t base = ((size_t)b * NT + t) * MAXC;

    float pm[MAXC], pl[MAXC];
#pragma unroll
    for (int c = 0; c < MAXC; ++c) {
        if (c < nc) {
            pm[c] = g_pm[(base + c) * 64 + r];
            pl[c] = g_pl[(base + c) * 64 + r];
        } else { pm[c] = -INFINITY; pl[c] = 0.f; }
    }
    // Batch all partial-O loads (8 halves = 16B per chunk).
    uint4 raw[MAXC];
#pragma unroll
    for (int c = 0; c < MAXC; ++c) {
        if (c < nc)
            raw[c] = *reinterpret_cast<const uint4*>(
                g_pOh + (base + c) * 4096 + (size_t)r * 64 + e0);
    }

    float m = -INFINITY;
#pragma unroll
    for (int c = 0; c < MAXC; ++c) m = fmaxf(m, pm[c]);

    float w[MAXC], lsum = 0.f;
#pragma unroll
    for (int c = 0; c < MAXC; ++c) {
        float wc = __expf(pm[c] - m);
        w[c] = wc;
        lsum += wc * pl[c];
    }
    const float inv = 1.f / lsum;

    float o[8];
#pragma unroll
    for (int k = 0; k < 8; ++k) o[k] = 0.f;
#pragma unroll
    for (int c = 0; c < MAXC; ++c) {
        if (c < nc) {
            float wc = w[c];
            float2 p0 = unpack2h(raw[c].x);
            float2 p1 = unpack2h(raw[c].y);
            float2 p2 = unpack2h(raw[c].z);
            float2 p3 = unpack2h(raw[c].w);
            o[0] = fmaf(wc, p0.x, o[0]);
            o[1] = fmaf(wc, p0.y, o[1]);
            o[2] = fmaf(wc, p1.x, o[2]);
            o[3] = fmaf(wc, p1.y, o[3]);
            o[4] = fmaf(wc, p2.x, o[4]);
            o[5] = fmaf(wc, p2.y, o[5]);
            o[6] = fmaf(wc, p3.x, o[6]);
            o[7] = fmaf(wc, p3.y, o[7]);
        }
    }

    float* dst = out + ((size_t)b * N_ + t * 64 + r) * E_ + e0;
    *reinterpret_cast<float4*>(dst) =
        make_float4(o[0] * inv, o[1] * inv, o[2] * inv, o[3] * inv);
    *reinterpret_cast<float4*>(dst + 4) =
        make_float4(o[4] * inv, o[5] * inv, o[6] * inv, o[7] * inv);
}

// ---------------------------------------------------------------------------
extern "C" void kernel_launch(void* const* d_in, const int* in_sizes, int n_in,
                              void* d_out, int out_size)
{
    (void)in_sizes; (void)n_in; (void)out_size;
    const float* input = (const float*)d_in[0];
    const float* Wk    = (const float*)d_in[1];
    // d_in[2] is q — dead in the reference, intentionally unused.
    const float* Wv    = (const float*)d_in[3];
    float* out = (float*)d_out;

    cudaFuncSetAttribute(proj_mma,
                         cudaFuncAttributeMaxDynamicSharedMemorySize, PROJ_SMEM);
    cudaFuncSetAttribute(attn_partial,
                         cudaFuncAttributeMaxDynamicSharedMemorySize, ATTN_SMEM_BYTES);

    prep_w<<<128, 256>>>(Wk, Wv);
    proj_mma<<<128, 256, PROJ_SMEM>>>(input);
    attn_partial<<<B_ * BLK_PER_B, 128, ATTN_SMEM_BYTES>>>();
    combine_kernel<<<B_ * NT * 2, 256>>>(out);
}

// round 15
// speedup vs baseline: 7.2425x; 1.0346x over previous
#include <cuda_runtime.h>
#include <cuda_fp16.h>
#include <math.h>
#include <stdint.h>

#define B_ 8
#define N_ 2048
#define H_ 1024
#define E_ 64
#define NT 32            // number of 64-row tiles per batch
#define CHUNK 8          // j-tiles (64 cols each) per partial block
#define MAXC 4           // max chunks per row-tile = ceil(32/8)
#define BLK_PER_B 80     // sum_t ceil((32-t)/8)

// Scratch (no allocation allowed in kernel_launch).
__device__ __half g_pOh[B_ * NT * MAXC * 64 * 64];   // unnormalized partial O (fp16)
__device__ float g_pm[B_ * NT * MAXC * 64];
__device__ float g_pl[B_ * NT * MAXC * 64];
// K and V stored fp16 (single-pass S-gemm: both operands rounded).
__device__ __half g_kh[B_ * N_ * E_];
__device__ __half g_vh[B_ * N_ * E_];
// Pre-transposed fp16 weight matrix Bt[n][k] = fp16([Wk|Wv][k][n]).
__device__ __half g_Wh[128 * 1024];

// ---------------------------------------------------------------------------
// Helpers (base-ISA: ldmatrix + mma.sync + cp.async — plain sm_100 target)
// ---------------------------------------------------------------------------
__device__ __forceinline__ uint32_t smem_u32(const void* p) {
    uint32_t a;
    asm("{ .reg .u64 t; cvta.to.shared.u64 t, %1; cvt.u32.u64 %0, t; }"
        : "=r"(a) : "l"(p));
    return a;
}

#define SW128(o) ((o) ^ ((((uint32_t)(o)) >> 3) & 0x70))

#define LDSM_X4(r0, r1, r2, r3, addr) \
    asm volatile("ldmatrix.sync.aligned.m8n8.x4.shared.b16 {%0,%1,%2,%3}, [%4];" \
                 : "=r"(r0), "=r"(r1), "=r"(r2), "=r"(r3) : "r"(addr))

#define LDSM_X4_T(r0, r1, r2, r3, addr) \
    asm volatile("ldmatrix.sync.aligned.m8n8.x4.trans.shared.b16 {%0,%1,%2,%3}, [%4];" \
                 : "=r"(r0), "=r"(r1), "=r"(r2), "=r"(r3) : "r"(addr))

#define MMA_F16(d0, d1, d2, d3, a0, a1, a2, a3, b0, b1) \
    asm volatile("mma.sync.aligned.m16n8k16.row.col.f32.f16.f16.f32 " \
                 "{%0,%1,%2,%3}, {%4,%5,%6,%7}, {%8,%9}, {%0,%1,%2,%3};" \
                 : "+f"(d0), "+f"(d1), "+f"(d2), "+f"(d3) \
                 : "r"(a0), "r"(a1), "r"(a2), "r"(a3), "r"(b0), "r"(b1))

#define CP16(dst, src) \
    asm volatile("cp.async.cg.shared.global [%0], [%1], 16;" \
                 :: "r"(dst), "l"(src) : "memory")
#define CP_COMMIT asm volatile("cp.async.commit_group;" ::: "memory")
#define CP_WAIT(n) asm volatile("cp.async.wait_group %0;" :: "n"(n) : "memory")

__device__ __forceinline__ uint32_t pack2h(float a, float b) {
    __half2 h = __floats2half2_rn(a, b);
    return *reinterpret_cast<uint32_t*>(&h);
}
__device__ __forceinline__ float2 unpack2h(uint32_t u) {
    __half2 h = *reinterpret_cast<__half2*>(&u);
    return __half22float2(h);
}

// ---------------------------------------------------------------------------
// prep_w: Bt[n][k] = fp16(W[k][n]) via coalesced smem transpose.
// grid 32: blockIdx = mat*16 + kt; each block does a 64k x 64n tile.
// ---------------------------------------------------------------------------
__global__ __launch_bounds__(256) void prep_w(const float* __restrict__ Wk,
                                              const float* __restrict__ Wv)
{
    __shared__ float tile[64][65];
    const int tid = threadIdx.x;
    const int mat = blockIdx.x >> 4;      // 0 -> Wk (n 0..63), 1 -> Wv (n 64..127)
    const int kt  = blockIdx.x & 15;
    const float* W = mat ? Wv : Wk;

    // Coalesced load: rows k = kt*64..+63, cols n = 0..63.
#pragma unroll
    for (int l = 0; l < 16; ++l) {
        int i = tid + l * 256;            // 0..4095
        int kk = i >> 6;
        int n  = i & 63;
        tile[kk][n] = W[(size_t)(kt * 64 + kk) * E_ + n];
    }
    __syncthreads();

    // Transposed write: row n' = mat*64+n, k-contiguous fp16 (32B per thread).
    const int n  = tid >> 2;              // 0..63
    const int k0 = (tid & 3) * 16;        // 0,16,32,48
    __half tmp[16];
#pragma unroll
    for (int k = 0; k < 16; ++k)
        tmp[k] = __float2half_rn(tile[k0 + k][n]);
    uint4* dst = reinterpret_cast<uint4*>(
        &g_Wh[(size_t)(mat * 64 + n) * H_ + kt * 64 + k0]);
    dst[0] = reinterpret_cast<uint4*>(tmp)[0];
    dst[1] = reinterpret_cast<uint4*>(tmp)[1];
}

// ---------------------------------------------------------------------------
// proj_mma: C[16384,128] = A @ Bt^T, single-pass fp16, double-buffered.
// 2 x 32KB buffers (AH, WH 16KB each, SW128 rows of 128B).
// ---------------------------------------------------------------------------
#define OFF_AH 0
#define OFF_WH 16384
#define PBUF   32768
#define PROJ_SMEM (2 * PBUF)

__device__ __forceinline__ void proj_cp_w(uint32_t sb, uint32_t bufoff,
                                          int kt, int tid)
{
#pragma unroll
    for (int l = 0; l < 4; ++l) {      // 1024 16B-chunks: full 128 n-rows
        int idx = tid + l * 256;
        int row = idx >> 3;            // n 0..127
        int s8  = (idx & 7) << 3;      // k-offset 0..56
        uint32_t so = SW128((uint32_t)(row * 128 + s8 * 2));
        CP16(sb + bufoff + OFF_WH + so, &g_Wh[row * H_ + kt * 64 + s8]);
    }
}

__device__ __forceinline__ void proj_load_a(const float* __restrict__ A,
                                            int M0, int kt, int tid, float4* ar)
{
#pragma unroll
    for (int l = 0; l < 8; ++l) {
        int idx = tid + l * 256;
        int row = idx >> 4;
        int c4  = (idx & 15) << 2;
        ar[l] = *reinterpret_cast<const float4*>(
            A + (size_t)(M0 + row) * H_ + kt * 64 + c4);
    }
}

__device__ __forceinline__ void proj_store_a(char* sm, uint32_t bufoff,
                                             int tid, const float4* ar)
{
#pragma unroll
    for (int l = 0; l < 8; ++l) {
        int idx = tid + l * 256;
        int row = idx >> 4;
        int c4  = (idx & 15) << 2;
        float4 a = ar[l];
        uint32_t so = SW128((uint32_t)(row * 128 + c4 * 2));
        *reinterpret_cast<uint2*>(sm + bufoff + OFF_AH + so) =
            make_uint2(pack2h(a.x, a.y), pack2h(a.z, a.w));
    }
}

__global__ __launch_bounds__(256) void proj_mma(const float* __restrict__ A)
{
    extern __shared__ char sm[];
    const uint32_t sb = smem_u32(sm);
    const int tid = threadIdx.x;
    const int wid = tid >> 5;
    const int lane = tid & 31;
    const int M0 = blockIdx.x * 128;

    const int wm0 = (wid & 3) * 32;
    const int wn0 = (wid >> 2) * 64;   // 0 -> keys, 64 -> vals

    float acc[2][8][4];
#pragma unroll
    for (int mi = 0; mi < 2; ++mi)
#pragma unroll
        for (int ni = 0; ni < 8; ++ni)
#pragma unroll
            for (int q = 0; q < 4; ++q) acc[mi][ni][q] = 0.f;

    const int lrow = lane & 15;
    const int lchk = lane >> 4;

    float4 areg[8];

    // ---- prologue ----
    proj_cp_w(sb, 0, 0, tid);
    CP_COMMIT;
    proj_load_a(A, M0, 0, tid, areg);
    proj_store_a(sm, 0, tid, areg);
    proj_cp_w(sb, PBUF, 1, tid);
    CP_COMMIT;
    proj_load_a(A, M0, 1, tid, areg);
    CP_WAIT(1);          // W(0) landed
    __syncthreads();

    for (int kt = 0; kt < 16; ++kt) {
        const uint32_t bo = (kt & 1) ? PBUF : 0;

#pragma unroll
        for (int ks = 0; ks < 4; ++ks) {
            uint32_t ah[2][4];
#pragma unroll
            for (int mi = 0; mi < 2; ++mi) {
                uint32_t off = SW128((uint32_t)(
                    (wm0 + mi * 16 + lrow) * 128 + (ks * 2 + lchk) * 16));
                LDSM_X4(ah[mi][0], ah[mi][1], ah[mi][2], ah[mi][3],
                        sb + bo + OFF_AH + off);
            }
            uint32_t bh[4][4];
#pragma unroll
            for (int g = 0; g < 4; ++g) {
                uint32_t off = SW128((uint32_t)(
                    (wn0 + g * 16 + lrow) * 128 + (ks * 2 + lchk) * 16));
                LDSM_X4(bh[g][0], bh[g][1], bh[g][2], bh[g][3],
                        sb + bo + OFF_WH + off);
            }
#pragma unroll
            for (int mi = 0; mi < 2; ++mi) {
#pragma unroll
                for (int ni = 0; ni < 8; ++ni) {
                    const int g = ni >> 1;
                    const int s = ni & 1;
                    float* d = acc[mi][ni];
                    MMA_F16(d[0], d[1], d[2], d[3],
                            ah[mi][0], ah[mi][1], ah[mi][2], ah[mi][3],
                            bh[g][s], bh[g][s + 2]);
                }
            }
        }

        if (kt < 15)
            proj_store_a(sm, (kt & 1) ? 0 : PBUF, tid, areg);
        __syncthreads();

        if (kt < 14) {
            proj_cp_w(sb, bo, kt + 2, tid);
            CP_COMMIT;
            proj_load_a(A, M0, kt + 2, tid, areg);
            CP_WAIT(1);
        } else {
            CP_WAIT(0);
        }
        __syncthreads();
    }

    // ---- epilogue: fp16 K or V ----
    __half* outm = (wn0 == 0) ? g_kh : g_vh;
    const int colb = (lane & 3) * 2;
    const int rowb = M0 + wm0 + (lane >> 2);
#pragma unroll
    for (int mi = 0; mi < 2; ++mi) {
#pragma unroll
        for (int ni = 0; ni < 8; ++ni) {
            const int col = ni * 8 + colb;
#pragma unroll
            for (int hq = 0; hq < 2; ++hq) {
                const int r = rowb + mi * 16 + hq * 8;
                *reinterpret_cast<uint32_t*>(&outm[(size_t)r * E_ + col]) =
                    pack2h(acc[mi][ni][hq * 2 + 0], acc[mi][ni][hq * 2 + 1]);
            }
        }
    }
}

// ---------------------------------------------------------------------------
// attn_partial: S = Kh.Vh ; O = Ph.Vh^T. K fragments hoisted (j-invariant).
// 3-stage V ring -> ONE __syncthreads per j-tile: the prefetch (issued after
// the top-of-iter barrier) writes buf (jt+2)%3 == (jt-1)%3, which every warp
// finished reading before arriving at that barrier.
// smem: KH (8KB) + 3 x VH (8KB) -> 32KB.
// ---------------------------------------------------------------------------
#define AT_KH 0
#define AT_V0 8192
#define ATTN_SMEM_BYTES 32768

__device__ __forceinline__ void attn_cp_tile(uint32_t sb, uint32_t off,
                                             const __half* __restrict__ src,
                                             size_t gbase, int tid)
{
#pragma unroll
    for (int l = 0; l < 4; ++l) {
        int idx = tid + l * 128;       // 0..511 16B-chunks (64 rows x 128B)
        int row = idx >> 3;
        int e8  = (idx & 7) << 3;
        uint32_t so = SW128((uint32_t)(row * 128 + e8 * 2));
        CP16(sb + off + so, src + gbase + (size_t)row * E_ + e8);
    }
}

__global__ __launch_bounds__(128) void attn_partial()
{
    extern __shared__ char sm[];
    const uint32_t sb = smem_u32(sm);
    const int tid = threadIdx.x;
    const int wid = tid >> 5;
    const int lane = tid & 31;

    const int b = blockIdx.x / BLK_PER_B;
    int ent = blockIdx.x - b * BLK_PER_B;
    int t = 0, acc0 = 0;
    for (int tt = 0; tt < NT; ++tt) {
        int nc = (NT - tt + CHUNK - 1) / CHUNK;
        if (ent < acc0 + nc) { t = tt; break; }
        acc0 += nc;
    }
    const int chunk = ent - acc0;
    const int j0 = t + chunk * CHUNK;
    const int j1 = min(NT, j0 + CHUNK);

    const int wm0 = wid * 16;
    const int lrow = lane & 15;
    const int lchk = lane >> 4;

    // ---- prologue: K (g0), V(j0) (g1), V(j0+1) (g2 if it exists) ----
    attn_cp_tile(sb, AT_KH, g_kh, ((size_t)b * N_ + t * 64) * E_, tid);
    CP_COMMIT;
    attn_cp_tile(sb, AT_V0, g_vh, ((size_t)b * N_ + j0 * 64) * E_, tid);
    CP_COMMIT;
    const bool have2 = (j0 + 1 < j1);
    if (have2) {
        attn_cp_tile(sb, AT_V0 + 8192, g_vh,
                     ((size_t)b * N_ + (j0 + 1) * 64) * E_, tid);
        CP_COMMIT;
    }

    // ---- hoist K fragments: K (oldest group) complete after these waits ----
    if (have2) CP_WAIT(2); else CP_WAIT(1);
    __syncthreads();
    uint32_t kfr[4][4];
#pragma unroll
    for (int ks = 0; ks < 4; ++ks) {
        uint32_t offa = SW128((uint32_t)(
            (wm0 + lrow) * 128 + (ks * 2 + lchk) * 16));
        LDSM_X4(kfr[ks][0], kfr[ks][1], kfr[ks][2], kfr[ks][3], sb + AT_KH + offa);
    }

    float m_i[2], l_i[2], accO[8][4];
#pragma unroll
    for (int h = 0; h < 2; ++h) { m_i[h] = -INFINITY; l_i[h] = 0.f; }
#pragma unroll
    for (int ne = 0; ne < 8; ++ne)
#pragma unroll
        for (int q = 0; q < 4; ++q) accO[ne][q] = 0.f;

    int vslot = 0;
    for (int jt = j0; jt < j1; ++jt) {
        // V(jt) complete: the only possibly-pending newer group is V(jt+1).
        if (jt + 1 < j1) CP_WAIT(1); else CP_WAIT(0);
        __syncthreads();   // single barrier per iter (see header comment)

        if (jt + 2 < j1) {
            int ps = vslot + 2; if (ps >= 3) ps -= 3;
            attn_cp_tile(sb, AT_V0 + ps * 8192, g_vh,
                         ((size_t)b * N_ + (jt + 2) * 64) * E_, tid);
            CP_COMMIT;
        }
        const uint32_t vb = AT_V0 + vslot * 8192;

        // ---- S-gemm: S = Kh.Vh (K frags in registers) ----
        float Sa[8][4];
#pragma unroll
        for (int ni = 0; ni < 8; ++ni)
#pragma unroll
            for (int q = 0; q < 4; ++q) Sa[ni][q] = 0.f;

#pragma unroll
        for (int ks = 0; ks < 4; ++ks) {
            uint32_t bh[4][4];
#pragma unroll
            for (int g = 0; g < 4; ++g) {
                uint32_t offb = SW128((uint32_t)(
                    (g * 16 + lrow) * 128 + (ks * 2 + lchk) * 16));
                LDSM_X4(bh[g][0], bh[g][1], bh[g][2], bh[g][3], sb + vb + offb);
            }
#pragma unroll
            for (int ni = 0; ni < 8; ++ni) {
                const int g = ni >> 1;
                const int s = ni & 1;
                float* d = Sa[ni];
                MMA_F16(d[0], d[1], d[2], d[3],
                        kfr[ks][0], kfr[ks][1], kfr[ks][2], kfr[ks][3],
                        bh[g][s], bh[g][s + 2]);
            }
        }

        // ---- scale + mask ----
        const float sc = 0.125f;
        if (jt == t) {
#pragma unroll
            for (int ni = 0; ni < 8; ++ni)
#pragma unroll
                for (int q = 0; q < 4; ++q) {
                    int i_loc = wm0 + (lane >> 2) + ((q >> 1) << 3);
                    int j_loc = ni * 8 + (lane & 3) * 2 + (q & 1);
                    Sa[ni][q] = (j_loc >= i_loc) ? Sa[ni][q] * sc : -1e30f;
                }
        } else {
#pragma unroll
            for (int ni = 0; ni < 8; ++ni)
#pragma unroll
                for (int q = 0; q < 4; ++q) Sa[ni][q] *= sc;
        }

        // ---- online softmax ----
#pragma unroll
        for (int h = 0; h < 2; ++h) {
            float tmax = -INFINITY;
#pragma unroll
            for (int ni = 0; ni < 8; ++ni)
                tmax = fmaxf(tmax, fmaxf(Sa[ni][h * 2], Sa[ni][h * 2 + 1]));
            tmax = fmaxf(tmax, __shfl_xor_sync(0xffffffffu, tmax, 1));
            tmax = fmaxf(tmax, __shfl_xor_sync(0xffffffffu, tmax, 2));
            float mnew = fmaxf(m_i[h], tmax);
            float alpha = __expf(m_i[h] - mnew);
            float ps = 0.f;
#pragma unroll
            for (int ni = 0; ni < 8; ++ni) {
                float p0 = __expf(Sa[ni][h * 2] - mnew);
                float p1 = __expf(Sa[ni][h * 2 + 1] - mnew);
                Sa[ni][h * 2] = p0;
                Sa[ni][h * 2 + 1] = p1;
                ps += p0 + p1;
            }
            ps += __shfl_xor_sync(0xffffffffu, ps, 1);
            ps += __shfl_xor_sync(0xffffffffu, ps, 2);
            l_i[h] = l_i[h] * alpha + ps;
            m_i[h] = mnew;
#pragma unroll
            for (int ne = 0; ne < 8; ++ne) {
                accO[ne][h * 2] *= alpha;
                accO[ne][h * 2 + 1] *= alpha;
            }
        }

        // ---- O-gemm: accO += Ph @ Vh (trans fragments on same V tile) ----
#pragma unroll
        for (int kc = 0; kc < 4; ++kc) {
            const int n0 = 2 * kc, n1 = 2 * kc + 1;
            uint32_t pah[4];
            pah[0] = pack2h(Sa[n0][0], Sa[n0][1]);
            pah[1] = pack2h(Sa[n0][2], Sa[n0][3]);
            pah[2] = pack2h(Sa[n1][0], Sa[n1][1]);
            pah[3] = pack2h(Sa[n1][2], Sa[n1][3]);
            uint32_t tbh[4][4];
#pragma unroll
            for (int g = 0; g < 4; ++g) {
                uint32_t offt = SW128((uint32_t)(
                    (kc * 16 + lrow) * 128 + g * 32 + lchk * 16));
                LDSM_X4_T(tbh[g][0], tbh[g][1], tbh[g][2], tbh[g][3],
                          sb + vb + offt);
            }
#pragma unroll
            for (int ne = 0; ne < 8; ++ne) {
                const int g = ne >> 1;
                const int s = ne & 1;
                float* d = accO[ne];
                MMA_F16(d[0], d[1], d[2], d[3], pah[0], pah[1], pah[2], pah[3],
                        tbh[g][2 * s], tbh[g][2 * s + 1]);
            }
        }

        vslot = (vslot + 1 == 3) ? 0 : vslot + 1;
    }

    // ---- write unnormalized partials (fp16) ----
    const size_t base = ((size_t)b * NT + t) * MAXC + chunk;
    __half* pO = g_pOh + base * 4096;
    const int r0 = wm0 + (lane >> 2);
    if ((lane & 3) == 0) {
        g_pm[base * 64 + r0]     = m_i[0];
        g_pm[base * 64 + r0 + 8] = m_i[1];
        g_pl[base * 64 + r0]     = l_i[0];
        g_pl[base * 64 + r0 + 8] = l_i[1];
    }
#pragma unroll
    for (int ne = 0; ne < 8; ++ne) {
        const int e = ne * 8 + (lane & 3) * 2;
        *reinterpret_cast<uint32_t*>(&pO[(size_t)r0 * 64 + e]) =
            pack2h(accO[ne][0], accO[ne][1]);
        *reinterpret_cast<uint32_t*>(&pO[(size_t)(r0 + 8) * 64 + e]) =
            pack2h(accO[ne][2], accO[ne][3]);
    }
}

// ---------------------------------------------------------------------------
// Combine: merge the <=4 chunks of each (b, row-tile). 1024 blocks
// (quarter-e per block) for latency hiding; fp16 partials, uint2 loads.
// ---------------------------------------------------------------------------
__global__ __launch_bounds__(256) void combine_kernel(float* __restrict__ out)
{
    const int quarter = blockIdx.x & 3;
    const int bt = blockIdx.x >> 2;
    const int t = bt >> 3;
    const int b = bt & 7;
    const int nc = (NT - t + CHUNK - 1) / CHUNK;
    const int tid = threadIdx.x;
    const int r  = tid >> 2;                     // 0..63
    const int e0 = quarter * 16 + (tid & 3) * 4; // 4 e per thread

    const size_t base = ((size_t)b * NT + t) * MAXC;

    float pm[MAXC], pl[MAXC];
#pragma unroll
    for (int c = 0; c < MAXC; ++c) {
        if (c < nc) {
            pm[c] = g_pm[(base + c) * 64 + r];
            pl[c] = g_pl[(base + c) * 64 + r];
        } else { pm[c] = -INFINITY; pl[c] = 0.f; }
    }
    uint2 raw[MAXC];
#pragma unroll
    for (int c = 0; c < MAXC; ++c) {
        if (c < nc)
            raw[c] = *reinterpret_cast<const uint2*>(
                g_pOh + (base + c) * 4096 + (size_t)r * 64 + e0);
    }

    float m = -INFINITY;
#pragma unroll
    for (int c = 0; c < MAXC; ++c) m = fmaxf(m, pm[c]);

    float w[MAXC], lsum = 0.f;
#pragma unroll
    for (int c = 0; c < MAXC; ++c) {
        float wc = __expf(pm[c] - m);
        w[c] = wc;
        lsum += wc * pl[c];
    }
    const float inv = 1.f / lsum;

    float o[4];
#pragma unroll
    for (int k = 0; k < 4; ++k) o[k] = 0.f;
#pragma unroll
    for (int c = 0; c < MAXC; ++c) {
        if (c < nc) {
            float wc = w[c];
            float2 p0 = unpack2h(raw[c].x);
            float2 p1 = unpack2h(raw[c].y);
            o[0] = fmaf(wc, p0.x, o[0]);
            o[1] = fmaf(wc, p0.y, o[1]);
            o[2] = fmaf(wc, p1.x, o[2]);
            o[3] = fmaf(wc, p1.y, o[3]);
        }
    }

    float* dst = out + ((size_t)b * N_ + t * 64 + r) * E_ + e0;
    *reinterpret_cast<float4*>(dst) =
        make_float4(o[0] * inv, o[1] * inv, o[2] * inv, o[3] * inv);
}

// ---------------------------------------------------------------------------
extern "C" void kernel_launch(void* const* d_in, const int* in_sizes, int n_in,
                              void* d_out, int out_size)
{
    (void)in_sizes; (void)n_in; (void)out_size;
    const float* input = (const float*)d_in[0];
    const float* Wk    = (const float*)d_in[1];
    // d_in[2] is q — dead in the reference, intentionally unused.
    const float* Wv    = (const float*)d_in[3];
    float* out = (float*)d_out;

    cudaFuncSetAttribute(proj_mma,
                         cudaFuncAttributeMaxDynamicSharedMemorySize, PROJ_SMEM);
    cudaFuncSetAttribute(attn_partial,
                         cudaFuncAttributeMaxDynamicSharedMemorySize, ATTN_SMEM_BYTES);

    prep_w<<<32, 256>>>(Wk, Wv);
    proj_mma<<<128, 256, PROJ_SMEM>>>(input);
    attn_partial<<<B_ * BLK_PER_B, 128, ATTN_SMEM_BYTES>>>();
    combine_kernel<<<B_ * NT * 4, 256>>>(out);
}

// round 16
// speedup vs baseline: 7.2677x; 1.0035x over previous
#include <cuda_runtime.h>
#include <cuda_fp16.h>
#include <math.h>
#include <stdint.h>

#define B_ 8
#define N_ 2048
#define H_ 1024
#define E_ 64
#define NT 32            // number of 64-row tiles per batch
#define CHUNK 8          // j-tiles (64 cols each) per partial block
#define MAXC 4           // max chunks per row-tile = ceil(32/8)
#define BLK_PER_B 80     // sum_t ceil((32-t)/8)
// Softmax scale folded into K: 1/sqrt(64) * log2(e). Scores come out of the
// S-gemm already in the exp2 domain.
#define KSCL 0.1803368801111244f

// Scratch (no allocation allowed in kernel_launch).
__device__ __half g_pOh[B_ * NT * MAXC * 64 * 64];   // unnormalized partial O (fp16)
__device__ float g_pm[B_ * NT * MAXC * 64];          // row max (log2e-scaled domain)
__device__ float g_pl[B_ * NT * MAXC * 64];
// K (pre-scaled by KSCL) and V stored fp16.
__device__ __half g_kh[B_ * N_ * E_];
__device__ __half g_vh[B_ * N_ * E_];
// Pre-transposed fp16 weight matrix Bt[n][k] = fp16([Wk|Wv][k][n]).
__device__ __half g_Wh[128 * 1024];

// ---------------------------------------------------------------------------
// Helpers (base-ISA: ldmatrix + mma.sync + cp.async — plain sm_100 target)
// ---------------------------------------------------------------------------
__device__ __forceinline__ uint32_t smem_u32(const void* p) {
    uint32_t a;
    asm("{ .reg .u64 t; cvta.to.shared.u64 t, %1; cvt.u32.u64 %0, t; }"
        : "=r"(a) : "l"(p));
    return a;
}

#define SW128(o) ((o) ^ ((((uint32_t)(o)) >> 3) & 0x70))

#define LDSM_X4(r0, r1, r2, r3, addr) \
    asm volatile("ldmatrix.sync.aligned.m8n8.x4.shared.b16 {%0,%1,%2,%3}, [%4];" \
                 : "=r"(r0), "=r"(r1), "=r"(r2), "=r"(r3) : "r"(addr))

#define LDSM_X4_T(r0, r1, r2, r3, addr) \
    asm volatile("ldmatrix.sync.aligned.m8n8.x4.trans.shared.b16 {%0,%1,%2,%3}, [%4];" \
                 : "=r"(r0), "=r"(r1), "=r"(r2), "=r"(r3) : "r"(addr))

#define MMA_F16(d0, d1, d2, d3, a0, a1, a2, a3, b0, b1) \
    asm volatile("mma.sync.aligned.m16n8k16.row.col.f32.f16.f16.f32 " \
                 "{%0,%1,%2,%3}, {%4,%5,%6,%7}, {%8,%9}, {%0,%1,%2,%3};" \
                 : "+f"(d0), "+f"(d1), "+f"(d2), "+f"(d3) \
                 : "r"(a0), "r"(a1), "r"(a2), "r"(a3), "r"(b0), "r"(b1))

#define CP16(dst, src) \
    asm volatile("cp.async.cg.shared.global [%0], [%1], 16;" \
                 :: "r"(dst), "l"(src) : "memory")
#define CP_COMMIT asm volatile("cp.async.commit_group;" ::: "memory")
#define CP_WAIT(n) asm volatile("cp.async.wait_group %0;" :: "n"(n) : "memory")

__device__ __forceinline__ uint32_t pack2h(float a, float b) {
    __half2 h = __floats2half2_rn(a, b);
    return *reinterpret_cast<uint32_t*>(&h);
}
__device__ __forceinline__ float2 unpack2h(uint32_t u) {
    __half2 h = *reinterpret_cast<__half2*>(&u);
    return __half22float2(h);
}

// ---------------------------------------------------------------------------
// prep_w: Bt[n][k] = fp16(W[k][n]) via coalesced smem transpose.
// ---------------------------------------------------------------------------
__global__ __launch_bounds__(256) void prep_w(const float* __restrict__ Wk,
                                              const float* __restrict__ Wv)
{
    __shared__ float tile[64][65];
    const int tid = threadIdx.x;
    const int mat = blockIdx.x >> 4;
    const int kt  = blockIdx.x & 15;
    const float* W = mat ? Wv : Wk;

#pragma unroll
    for (int l = 0; l < 16; ++l) {
        int i = tid + l * 256;
        int kk = i >> 6;
        int n  = i & 63;
        tile[kk][n] = W[(size_t)(kt * 64 + kk) * E_ + n];
    }
    __syncthreads();

    const int n  = tid >> 2;
    const int k0 = (tid & 3) * 16;
    __half tmp[16];
#pragma unroll
    for (int k = 0; k < 16; ++k)
        tmp[k] = __float2half_rn(tile[k0 + k][n]);
    uint4* dst = reinterpret_cast<uint4*>(
        &g_Wh[(size_t)(mat * 64 + n) * H_ + kt * 64 + k0]);
    dst[0] = reinterpret_cast<uint4*>(tmp)[0];
    dst[1] = reinterpret_cast<uint4*>(tmp)[1];
}

// ---------------------------------------------------------------------------
// proj_mma: C[16384,128] = A @ Bt^T, single-pass fp16, double-buffered.
// Keys epilogue pre-scales by KSCL (softmax scale folded in).
// ---------------------------------------------------------------------------
#define OFF_AH 0
#define OFF_WH 16384
#define PBUF   32768
#define PROJ_SMEM (2 * PBUF)

__device__ __forceinline__ void proj_cp_w(uint32_t sb, uint32_t bufoff,
                                          int kt, int tid)
{
#pragma unroll
    for (int l = 0; l < 4; ++l) {
        int idx = tid + l * 256;
        int row = idx >> 3;
        int s8  = (idx & 7) << 3;
        uint32_t so = SW128((uint32_t)(row * 128 + s8 * 2));
        CP16(sb + bufoff + OFF_WH + so, &g_Wh[row * H_ + kt * 64 + s8]);
    }
}

__device__ __forceinline__ void proj_load_a(const float* __restrict__ A,
                                            int M0, int kt, int tid, float4* ar)
{
#pragma unroll
    for (int l = 0; l < 8; ++l) {
        int idx = tid + l * 256;
        int row = idx >> 4;
        int c4  = (idx & 15) << 2;
        ar[l] = *reinterpret_cast<const float4*>(
            A + (size_t)(M0 + row) * H_ + kt * 64 + c4);
    }
}

__device__ __forceinline__ void proj_store_a(char* sm, uint32_t bufoff,
                                             int tid, const float4* ar)
{
#pragma unroll
    for (int l = 0; l < 8; ++l) {
        int idx = tid + l * 256;
        int row = idx >> 4;
        int c4  = (idx & 15) << 2;
        float4 a = ar[l];
        uint32_t so = SW128((uint32_t)(row * 128 + c4 * 2));
        *reinterpret_cast<uint2*>(sm + bufoff + OFF_AH + so) =
            make_uint2(pack2h(a.x, a.y), pack2h(a.z, a.w));
    }
}

__global__ __launch_bounds__(256) void proj_mma(const float* __restrict__ A)
{
    extern __shared__ char sm[];
    const uint32_t sb = smem_u32(sm);
    const int tid = threadIdx.x;
    const int wid = tid >> 5;
    const int lane = tid & 31;
    const int M0 = blockIdx.x * 128;

    const int wm0 = (wid & 3) * 32;
    const int wn0 = (wid >> 2) * 64;   // 0 -> keys, 64 -> vals

    float acc[2][8][4];
#pragma unroll
    for (int mi = 0; mi < 2; ++mi)
#pragma unroll
        for (int ni = 0; ni < 8; ++ni)
#pragma unroll
            for (int q = 0; q < 4; ++q) acc[mi][ni][q] = 0.f;

    const int lrow = lane & 15;
    const int lchk = lane >> 4;

    float4 areg[8];

    // ---- prologue ----
    proj_cp_w(sb, 0, 0, tid);
    CP_COMMIT;
    proj_load_a(A, M0, 0, tid, areg);
    proj_store_a(sm, 0, tid, areg);
    proj_cp_w(sb, PBUF, 1, tid);
    CP_COMMIT;
    proj_load_a(A, M0, 1, tid, areg);
    CP_WAIT(1);          // W(0) landed
    __syncthreads();

    for (int kt = 0; kt < 16; ++kt) {
        const uint32_t bo = (kt & 1) ? PBUF : 0;

#pragma unroll
        for (int ks = 0; ks < 4; ++ks) {
            uint32_t ah[2][4];
#pragma unroll
            for (int mi = 0; mi < 2; ++mi) {
                uint32_t off = SW128((uint32_t)(
                    (wm0 + mi * 16 + lrow) * 128 + (ks * 2 + lchk) * 16));
                LDSM_X4(ah[mi][0], ah[mi][1], ah[mi][2], ah[mi][3],
                        sb + bo + OFF_AH + off);
            }
            uint32_t bh[4][4];
#pragma unroll
            for (int g = 0; g < 4; ++g) {
                uint32_t off = SW128((uint32_t)(
                    (wn0 + g * 16 + lrow) * 128 + (ks * 2 + lchk) * 16));
                LDSM_X4(bh[g][0], bh[g][1], bh[g][2], bh[g][3],
                        sb + bo + OFF_WH + off);
            }
#pragma unroll
            for (int mi = 0; mi < 2; ++mi) {
#pragma unroll
                for (int ni = 0; ni < 8; ++ni) {
                    const int g = ni >> 1;
                    const int s = ni & 1;
                    float* d = acc[mi][ni];
                    MMA_F16(d[0], d[1], d[2], d[3],
                            ah[mi][0], ah[mi][1], ah[mi][2], ah[mi][3],
                            bh[g][s], bh[g][s + 2]);
                }
            }
        }

        if (kt < 15)
            proj_store_a(sm, (kt & 1) ? 0 : PBUF, tid, areg);
        __syncthreads();

        if (kt < 14) {
            proj_cp_w(sb, bo, kt + 2, tid);
            CP_COMMIT;
            proj_load_a(A, M0, kt + 2, tid, areg);
            CP_WAIT(1);
        } else {
            CP_WAIT(0);
        }
        __syncthreads();
    }

    // ---- epilogue: keys scaled by KSCL; vals plain fp16 ----
    __half* outm = (wn0 == 0) ? g_kh : g_vh;
    const float scl = (wn0 == 0) ? KSCL : 1.0f;
    const int colb = (lane & 3) * 2;
    const int rowb = M0 + wm0 + (lane >> 2);
#pragma unroll
    for (int mi = 0; mi < 2; ++mi) {
#pragma unroll
        for (int ni = 0; ni < 8; ++ni) {
            const int col = ni * 8 + colb;
#pragma unroll
            for (int hq = 0; hq < 2; ++hq) {
                const int r = rowb + mi * 16 + hq * 8;
                *reinterpret_cast<uint32_t*>(&outm[(size_t)r * E_ + col]) =
                    pack2h(acc[mi][ni][hq * 2 + 0] * scl,
                           acc[mi][ni][hq * 2 + 1] * scl);
            }
        }
    }
}

// ---------------------------------------------------------------------------
// attn_partial: S = Kscaled.Vh (already exp2-domain) ; O = Ph.Vh^T.
// K fragments hoisted; 3-stage V ring, one barrier per j-tile.
// No per-tile scale step; softmax via exp2f.
// smem: KH (8KB) + 3 x VH (8KB) -> 32KB.
// ---------------------------------------------------------------------------
#define AT_KH 0
#define AT_V0 8192
#define ATTN_SMEM_BYTES 32768

__device__ __forceinline__ void attn_cp_tile(uint32_t sb, uint32_t off,
                                             const __half* __restrict__ src,
                                             size_t gbase, int tid)
{
#pragma unroll
    for (int l = 0; l < 4; ++l) {
        int idx = tid + l * 128;
        int row = idx >> 3;
        int e8  = (idx & 7) << 3;
        uint32_t so = SW128((uint32_t)(row * 128 + e8 * 2));
        CP16(sb + off + so, src + gbase + (size_t)row * E_ + e8);
    }
}

__global__ __launch_bounds__(128) void attn_partial()
{
    extern __shared__ char sm[];
    const uint32_t sb = smem_u32(sm);
    const int tid = threadIdx.x;
    const int wid = tid >> 5;
    const int lane = tid & 31;

    const int b = blockIdx.x / BLK_PER_B;
    int ent = blockIdx.x - b * BLK_PER_B;
    int t = 0, acc0 = 0;
    for (int tt = 0; tt < NT; ++tt) {
        int nc = (NT - tt + CHUNK - 1) / CHUNK;
        if (ent < acc0 + nc) { t = tt; break; }
        acc0 += nc;
    }
    const int chunk = ent - acc0;
    const int j0 = t + chunk * CHUNK;
    const int j1 = min(NT, j0 + CHUNK);

    const int wm0 = wid * 16;
    const int lrow = lane & 15;
    const int lchk = lane >> 4;

    // ---- prologue: K (g0), V(j0) (g1), V(j0+1) (g2 if it exists) ----
    attn_cp_tile(sb, AT_KH, g_kh, ((size_t)b * N_ + t * 64) * E_, tid);
    CP_COMMIT;
    attn_cp_tile(sb, AT_V0, g_vh, ((size_t)b * N_ + j0 * 64) * E_, tid);
    CP_COMMIT;
    const bool have2 = (j0 + 1 < j1);
    if (have2) {
        attn_cp_tile(sb, AT_V0 + 8192, g_vh,
                     ((size_t)b * N_ + (j0 + 1) * 64) * E_, tid);
        CP_COMMIT;
    }

    // ---- hoist K fragments ----
    if (have2) CP_WAIT(2); else CP_WAIT(1);
    __syncthreads();
    uint32_t kfr[4][4];
#pragma unroll
    for (int ks = 0; ks < 4; ++ks) {
        uint32_t offa = SW128((uint32_t)(
            (wm0 + lrow) * 128 + (ks * 2 + lchk) * 16));
        LDSM_X4(kfr[ks][0], kfr[ks][1], kfr[ks][2], kfr[ks][3], sb + AT_KH + offa);
    }

    float m_i[2], l_i[2], accO[8][4];
#pragma unroll
    for (int h = 0; h < 2; ++h) { m_i[h] = -INFINITY; l_i[h] = 0.f; }
#pragma unroll
    for (int ne = 0; ne < 8; ++ne)
#pragma unroll
        for (int q = 0; q < 4; ++q) accO[ne][q] = 0.f;

    int vslot = 0;
    for (int jt = j0; jt < j1; ++jt) {
        if (jt + 1 < j1) CP_WAIT(1); else CP_WAIT(0);
        __syncthreads();

        if (jt + 2 < j1) {
            int ps = vslot + 2; if (ps >= 3) ps -= 3;
            attn_cp_tile(sb, AT_V0 + ps * 8192, g_vh,
                         ((size_t)b * N_ + (jt + 2) * 64) * E_, tid);
            CP_COMMIT;
        }
        const uint32_t vb = AT_V0 + vslot * 8192;

        // ---- S-gemm (scores emerge pre-scaled, exp2 domain) ----
        float Sa[8][4];
#pragma unroll
        for (int ni = 0; ni < 8; ++ni)
#pragma unroll
            for (int q = 0; q < 4; ++q) Sa[ni][q] = 0.f;

#pragma unroll
        for (int ks = 0; ks < 4; ++ks) {
            uint32_t bh[4][4];
#pragma unroll
            for (int g = 0; g < 4; ++g) {
                uint32_t offb = SW128((uint32_t)(
                    (g * 16 + lrow) * 128 + (ks * 2 + lchk) * 16));
                LDSM_X4(bh[g][0], bh[g][1], bh[g][2], bh[g][3], sb + vb + offb);
            }
#pragma unroll
            for (int ni = 0; ni < 8; ++ni) {
                const int g = ni >> 1;
                const int s = ni & 1;
                float* d = Sa[ni];
                MMA_F16(d[0], d[1], d[2], d[3],
                        kfr[ks][0], kfr[ks][1], kfr[ks][2], kfr[ks][3],
                        bh[g][s], bh[g][s + 2]);
            }
        }

        // ---- mask (diagonal tile only; no scale step anywhere) ----
        if (jt == t) {
#pragma unroll
            for (int ni = 0; ni < 8; ++ni)
#pragma unroll
                for (int q = 0; q < 4; ++q) {
                    int i_loc = wm0 + (lane >> 2) + ((q >> 1) << 3);
                    int j_loc = ni * 8 + (lane & 3) * 2 + (q & 1);
                    if (j_loc < i_loc) Sa[ni][q] = -1e30f;
                }
        }

        // ---- online softmax (exp2 domain) ----
#pragma unroll
        for (int h = 0; h < 2; ++h) {
            float tmax = -INFINITY;
#pragma unroll
            for (int ni = 0; ni < 8; ++ni)
                tmax = fmaxf(tmax, fmaxf(Sa[ni][h * 2], Sa[ni][h * 2 + 1]));
            tmax = fmaxf(tmax, __shfl_xor_sync(0xffffffffu, tmax, 1));
            tmax = fmaxf(tmax, __shfl_xor_sync(0xffffffffu, tmax, 2));
            float mnew = fmaxf(m_i[h], tmax);
            float alpha = exp2f(m_i[h] - mnew);
            float ps = 0.f;
#pragma unroll
            for (int ni = 0; ni < 8; ++ni) {
                float p0 = exp2f(Sa[ni][h * 2] - mnew);
                float p1 = exp2f(Sa[ni][h * 2 + 1] - mnew);
                Sa[ni][h * 2] = p0;
                Sa[ni][h * 2 + 1] = p1;
                ps += p0 + p1;
            }
            ps += __shfl_xor_sync(0xffffffffu, ps, 1);
            ps += __shfl_xor_sync(0xffffffffu, ps, 2);
            l_i[h] = l_i[h] * alpha + ps;
            m_i[h] = mnew;
#pragma unroll
            for (int ne = 0; ne < 8; ++ne) {
                accO[ne][h * 2] *= alpha;
                accO[ne][h * 2 + 1] *= alpha;
            }
        }

        // ---- O-gemm ----
#pragma unroll
        for (int kc = 0; kc < 4; ++kc) {
            const int n0 = 2 * kc, n1 = 2 * kc + 1;
            uint32_t pah[4];
            pah[0] = pack2h(Sa[n0][0], Sa[n0][1]);
            pah[1] = pack2h(Sa[n0][2], Sa[n0][3]);
            pah[2] = pack2h(Sa[n1][0], Sa[n1][1]);
            pah[3] = pack2h(Sa[n1][2], Sa[n1][3]);
            uint32_t tbh[4][4];
#pragma unroll
            for (int g = 0; g < 4; ++g) {
                uint32_t offt = SW128((uint32_t)(
                    (kc * 16 + lrow) * 128 + g * 32 + lchk * 16));
                LDSM_X4_T(tbh[g][0], tbh[g][1], tbh[g][2], tbh[g][3],
                          sb + vb + offt);
            }
#pragma unroll
            for (int ne = 0; ne < 8; ++ne) {
                const int g = ne >> 1;
                const int s = ne & 1;
                float* d = accO[ne];
                MMA_F16(d[0], d[1], d[2], d[3], pah[0], pah[1], pah[2], pah[3],
                        tbh[g][2 * s], tbh[g][2 * s + 1]);
            }
        }

        vslot = (vslot + 1 == 3) ? 0 : vslot + 1;
    }

    // ---- write unnormalized partials (fp16) ----
    const size_t base = ((size_t)b * NT + t) * MAXC + chunk;
    __half* pO = g_pOh + base * 4096;
    const int r0 = wm0 + (lane >> 2);
    if ((lane & 3) == 0) {
        g_pm[base * 64 + r0]     = m_i[0];
        g_pm[base * 64 + r0 + 8] = m_i[1];
        g_pl[base * 64 + r0]     = l_i[0];
        g_pl[base * 64 + r0 + 8] = l_i[1];
    }
#pragma unroll
    for (int ne = 0; ne < 8; ++ne) {
        const int e = ne * 8 + (lane & 3) * 2;
        *reinterpret_cast<uint32_t*>(&pO[(size_t)r0 * 64 + e]) =
            pack2h(accO[ne][0], accO[ne][1]);
        *reinterpret_cast<uint32_t*>(&pO[(size_t)(r0 + 8) * 64 + e]) =
            pack2h(accO[ne][2], accO[ne][3]);
    }
}

// ---------------------------------------------------------------------------
// Combine (R14-measured-best config: 512 blocks, uint4 batched loads), exp2
// domain for the merge weights.
// ---------------------------------------------------------------------------
__global__ __launch_bounds__(256) void combine_kernel(float* __restrict__ out)
{
    const int half = blockIdx.x & 1;
    const int bt = blockIdx.x >> 1;
    const int t = bt >> 3;
    const int b = bt & 7;
    const int nc = (NT - t + CHUNK - 1) / CHUNK;
    const int tid = threadIdx.x;
    const int r  = tid >> 2;
    const int e0 = half * 32 + (tid & 3) * 8;

    const size_t base = ((size_t)b * NT + t) * MAXC;

    float pm[MAXC], pl[MAXC];
#pragma unroll
    for (int c = 0; c < MAXC; ++c) {
        if (c < nc) {
            pm[c] = g_pm[(base + c) * 64 + r];
            pl[c] = g_pl[(base + c) * 64 + r];
        } else { pm[c] = -INFINITY; pl[c] = 0.f; }
    }
    uint4 raw[MAXC];
#pragma unroll
    for (int c = 0; c < MAXC; ++c) {
        if (c < nc)
            raw[c] = *reinterpret_cast<const uint4*>(
                g_pOh + (base + c) * 4096 + (size_t)r * 64 + e0);
    }

    float m = -INFINITY;
#pragma unroll
    for (int c = 0; c < MAXC; ++c) m = fmaxf(m, pm[c]);

    float w[MAXC], lsum = 0.f;
#pragma unroll
    for (int c = 0; c < MAXC; ++c) {
        float wc = exp2f(pm[c] - m);
        w[c] = wc;
        lsum += wc * pl[c];
    }
    const float inv = 1.f / lsum;

    float o[8];
#pragma unroll
    for (int k = 0; k < 8; ++k) o[k] = 0.f;
#pragma unroll
    for (int c = 0; c < MAXC; ++c) {
        if (c < nc) {
            float wc = w[c];
            float2 p0 = unpack2h(raw[c].x);
            float2 p1 = unpack2h(raw[c].y);
            float2 p2 = unpack2h(raw[c].z);
            float2 p3 = unpack2h(raw[c].w);
            o[0] = fmaf(wc, p0.x, o[0]);
            o[1] = fmaf(wc, p0.y, o[1]);
            o[2] = fmaf(wc, p1.x, o[2]);
            o[3] = fmaf(wc, p1.y, o[3]);
            o[4] = fmaf(wc, p2.x, o[4]);
            o[5] = fmaf(wc, p2.y, o[5]);
            o[6] = fmaf(wc, p3.x, o[6]);
            o[7] = fmaf(wc, p3.y, o[7]);
        }
    }

    float* dst = out + ((size_t)b * N_ + t * 64 + r) * E_ + e0;
    *reinterpret_cast<float4*>(dst) =
        make_float4(o[0] * inv, o[1] * inv, o[2] * inv, o[3] * inv);
    *reinterpret_cast<float4*>(dst + 4) =
        make_float4(o[4] * inv, o[5] * inv, o[6] * inv, o[7] * inv);
}

// ---------------------------------------------------------------------------
extern "C" void kernel_launch(void* const* d_in, const int* in_sizes, int n_in,
                              void* d_out, int out_size)
{
    (void)in_sizes; (void)n_in; (void)out_size;
    const float* input = (const float*)d_in[0];
    const float* Wk    = (const float*)d_in[1];
    // d_in[2] is q — dead in the reference, intentionally unused.
    const float* Wv    = (const float*)d_in[3];
    float* out = (float*)d_out;

    cudaFuncSetAttribute(proj_mma,
                         cudaFuncAttributeMaxDynamicSharedMemorySize, PROJ_SMEM);
    cudaFuncSetAttribute(attn_partial,
                         cudaFuncAttributeMaxDynamicSharedMemorySize, ATTN_SMEM_BYTES);

    prep_w<<<32, 256>>>(Wk, Wv);
    proj_mma<<<128, 256, PROJ_SMEM>>>(input);
    attn_partial<<<B_ * BLK_PER_B, 128, ATTN_SMEM_BYTES>>>();
    combine_kernel<<<B_ * NT * 2, 256>>>(out);
}